// round 3
// baseline (speedup 1.0000x reference)
#include <cuda_runtime.h>
#include <math.h>

#define BB   16
#define CC   512
#define HWW  1024
#define NCAPS 8
#define CAPC 32
#define OC   256
#define TAPS 81

// ---------------- scratch (static device globals; no runtime alloc) ----------
__device__ float g_wt[CC * CC];                 // transposed conv_w  [c][o]
__device__ float g_x[BB * CC * HWW];            // residual 1x1 conv output
__device__ float g_cap[(size_t)BB * OC * HWW];  // 9x9 conv output (67MB)
__device__ float g_cap4[BB * NCAPS * HWW];
__device__ int   g_idx[BB * NCAPS];
__device__ float g_norm[BB * HWW];
__device__ float g_smean[CC * NCAPS];
__device__ float g_cm[BB * NCAPS * HWW];
__device__ float g_mm[BB * NCAPS * 2];
__device__ float g_cmmean[BB * HWW];
__device__ float g_proto[NCAPS * CC];
__device__ float g_pm[CC];

// ---------------- K0: transpose conv_w ---------------------------------------
__global__ void k0_tr(const float* __restrict__ w) {
    int i = blockIdx.x * 256 + threadIdx.x;     // 262144 total
    int o = i >> 9, c = i & 511;
    g_wt[c * CC + o] = w[i];
}

// ---------------- K1: x = x5 @ W^T + b + x5  (per-pixel 512x512 GEMM) --------
__global__ __launch_bounds__(256) void k1_gemm(const float* __restrict__ x5,
                                               const float* __restrict__ bias) {
    __shared__ float As[16][64];   // [k][o]
    __shared__ float Bs[16][64];   // [k][hw]
    int b  = blockIdx.z;
    int bo = blockIdx.y * 64;
    int bh = blockIdx.x * 64;
    int tid = threadIdx.x;
    int ty = tid >> 4, tx = tid & 15;
    float acc[4][4] = {};
    for (int k0 = 0; k0 < CC; k0 += 16) {
        for (int e = tid; e < 1024; e += 256) {
            int k_l = e >> 6, o_l = e & 63;
            As[k_l][o_l] = g_wt[(k0 + k_l) * CC + bo + o_l];
        }
        for (int e = tid; e < 1024; e += 256) {
            int k_l = e >> 6, h_l = e & 63;
            Bs[k_l][h_l] = x5[((size_t)(b * CC + k0 + k_l)) * HWW + bh + h_l];
        }
        __syncthreads();
#pragma unroll
        for (int k = 0; k < 16; k++) {
            float4 a  = *(const float4*)&As[k][ty * 4];
            float4 bb = *(const float4*)&Bs[k][tx * 4];
            float av[4] = {a.x, a.y, a.z, a.w};
            float bv[4] = {bb.x, bb.y, bb.z, bb.w};
#pragma unroll
            for (int i = 0; i < 4; i++)
#pragma unroll
                for (int j = 0; j < 4; j++) acc[i][j] += av[i] * bv[j];
        }
        __syncthreads();
    }
#pragma unroll
    for (int i = 0; i < 4; i++) {
        int o = bo + ty * 4 + i;
        float bi = bias[o];
#pragma unroll
        for (int j = 0; j < 4; j++) {
            int hw = bh + tx * 4 + j;
            size_t off = ((size_t)(b * CC + o)) * HWW + hw;
            g_x[off] = acc[i][j] + bi + x5[off];
        }
    }
}

// ---------------- K2: 9x9 conv (pad 4), the hot kernel ------------------------
// block: (b, 64 ocs, 8 output rows x 32 cols); thread: 8 oc x 8 rows, col=lane
__global__ __launch_bounds__(256, 2) void k2_conv(const float* __restrict__ cw,
                                                  const float* __restrict__ cb) {
    __shared__ float sx[16 * 40];      // one cin: 16 rows (8 + halo) x 40 cols
    __shared__ float sw_[64 * TAPS];   // 64 ocs x 81 taps for current cin
    int b    = blockIdx.z;
    int ocb  = blockIdx.y * 64;
    int h0   = blockIdx.x * 8;
    int tid  = threadIdx.x;
    int warp = tid >> 5, lane = tid & 31;
    float acc[8][8] = {};
    const float* xb = g_x + (size_t)b * CC * HWW;

    for (int ci = 0; ci < CC; ++ci) {
        __syncthreads();
        for (int e = tid; e < 640; e += 256) {
            int r = e / 40, col = e % 40;
            int gr = h0 - 4 + r, gc = col - 4;
            float v = 0.f;
            if ((unsigned)gr < 32u && (unsigned)gc < 32u)
                v = xb[ci * HWW + gr * 32 + gc];
            sx[e] = v;
        }
        for (int e = tid; e < 64 * TAPS; e += 256) {
            int o = e / TAPS, t = e % TAPS;
            sw_[e] = cw[((size_t)(ocb + o) * CC + ci) * TAPS + t];
        }
        __syncthreads();
#pragma unroll 1
        for (int dy = 0; dy < 9; ++dy) {
#pragma unroll
            for (int dx = 0; dx < 9; ++dx) {
                float xv[8];
#pragma unroll
                for (int r = 0; r < 8; r++) xv[r] = sx[(r + dy) * 40 + lane + dx];
#pragma unroll
                for (int o = 0; o < 8; o++) {
                    float wv = sw_[(warp * 8 + o) * TAPS + dy * 9 + dx];
#pragma unroll
                    for (int r = 0; r < 8; r++) acc[o][r] += wv * xv[r];
                }
            }
        }
    }
#pragma unroll
    for (int o = 0; o < 8; o++) {
        int oc = ocb + warp * 8 + o;
        float bi = cb[oc];
#pragma unroll
        for (int r = 0; r < 8; r++)
            g_cap[((size_t)(b * OC + oc)) * HWW + (h0 + r) * 32 + lane] = acc[o][r] + bi;
    }
}

// ---------------- K3: per-pixel channel L2 norm of x --------------------------
__global__ void k3_norm() {
    int i = blockIdx.x * 256 + threadIdx.x;    // 16384
    int b = i >> 10, hw = i & 1023;
    const float* p = g_x + (size_t)b * CC * HWW + hw;
    float s = 0.f;
    for (int c = 0; c < CC; c++) { float v = p[c * HWW]; s += v * v; }
    g_norm[i] = sqrtf(s);
}

// ---------------- K4: squash + max over CAP_C --------------------------------
__global__ void k4_sqmax() {
    int i = blockIdx.x * 256 + threadIdx.x;
    int b = i >> 10, hw = i & 1023;
    const float* cp = g_cap + (size_t)b * OC * HWW + hw;
    float m[8];
#pragma unroll
    for (int k = 0; k < 8; k++) m[k] = -INFINITY;
    for (int c = 0; c < CAPC; c++) {
        float v[8]; float sq = 0.f;
#pragma unroll
        for (int k = 0; k < 8; k++) { v[k] = cp[(size_t)(k * CAPC + c) * HWW]; sq += v[k] * v[k]; }
        float s = sq / ((1.f + sq) * sqrtf(sq + 1e-8f));
#pragma unroll
        for (int k = 0; k < 8; k++) m[k] = fmaxf(m[k], v[k] * s);
    }
#pragma unroll
    for (int k = 0; k < 8; k++) g_cap4[(b * 8 + k) * HWW + hw] = m[k];
}

// ---------------- K5: spatial argmax (== softmax-equality mask) --------------
__global__ void k5_argmax() {
    int bk = blockIdx.x;
    __shared__ float sv[256];
    __shared__ int   si[256];
    int tid = threadIdx.x;
    float best = -INFINITY; int bi = 0;
    for (int hw = tid; hw < HWW; hw += 256) {
        float v = g_cap4[bk * HWW + hw];
        if (v > best) { best = v; bi = hw; }
    }
    sv[tid] = best; si[tid] = bi;
    __syncthreads();
    for (int s = 128; s > 0; s >>= 1) {
        if (tid < s) {
            if (sv[tid + s] > sv[tid] ||
                (sv[tid + s] == sv[tid] && si[tid + s] < si[tid])) {
                sv[tid] = sv[tid + s]; si[tid] = si[tid + s];
            }
        }
        __syncthreads();
    }
    if (tid == 0) g_idx[bk] = si[0];
}

// ---------------- K6: s_mean[c][k] = mean_b norm0[b,c,argmax] -----------------
__global__ void k6_smean() {
    int i = blockIdx.x * 256 + threadIdx.x;   // 4096
    int c = i >> 3, k = i & 7;
    float s = 0.f;
    for (int b = 0; b < BB; b++) {
        int hw = g_idx[b * 8 + k];
        float n = fmaxf(g_norm[b * HWW + hw], 1e-12f);
        s += g_x[((size_t)(b * CC + c)) * HWW + hw] / n;
    }
    g_smean[c * 8 + k] = s * (1.f / 16.f);
}

// ---------------- K7: cm[b,k,hw] = norm0 . s_mean ----------------------------
__global__ __launch_bounds__(256) void k7_cm() {
    __shared__ float ss[CC * 8];    // 16KB
    for (int e = threadIdx.x; e < CC * 8; e += 256) ss[e] = g_smean[e];
    __syncthreads();
    int i = blockIdx.x * 256 + threadIdx.x;
    int b = i >> 10, hw = i & 1023;
    const float* xp = g_x + (size_t)b * CC * HWW + hw;
    float acc[8] = {};
    for (int c = 0; c < CC; c++) {
        float xv = xp[c * HWW];
#pragma unroll
        for (int k = 0; k < 8; k++) acc[k] += xv * ss[c * 8 + k];
    }
    float inv = 1.f / fmaxf(g_norm[i], 1e-12f);
#pragma unroll
    for (int k = 0; k < 8; k++) g_cm[(b * 8 + k) * HWW + hw] = acc[k] * inv;
}

// ---------------- K8: per (b,k) min/max over hw ------------------------------
__global__ void k8_minmax() {
    int bk = blockIdx.x;
    __shared__ float smn[256], smx[256];
    int tid = threadIdx.x;
    float mn = INFINITY, mx = -INFINITY;
    for (int hw = tid; hw < HWW; hw += 256) {
        float v = g_cm[bk * HWW + hw];
        mn = fminf(mn, v); mx = fmaxf(mx, v);
    }
    smn[tid] = mn; smx[tid] = mx;
    __syncthreads();
    for (int s = 128; s > 0; s >>= 1) {
        if (tid < s) {
            smn[tid] = fminf(smn[tid], smn[tid + s]);
            smx[tid] = fmaxf(smx[tid], smx[tid + s]);
        }
        __syncthreads();
    }
    if (tid == 0) { g_mm[bk * 2] = smn[0]; g_mm[bk * 2 + 1] = smx[0]; }
}

// ---------------- K9: normalize cm in-place + cm_mean over k -----------------
__global__ void k9_cmnorm() {
    int i = blockIdx.x * 256 + threadIdx.x;
    int b = i >> 10, hw = i & 1023;
    float s = 0.f;
#pragma unroll
    for (int k = 0; k < 8; k++) {
        int bk = b * 8 + k;
        float mn = g_mm[bk * 2], mx = g_mm[bk * 2 + 1];
        float v = (g_cm[bk * HWW + hw] - mn) / (mx - mn + 1e-12f);
        g_cm[bk * HWW + hw] = v;
        s += v;
    }
    g_cmmean[i] = s * 0.125f;
}

// ---------------- K10: proto[k][c] = sum_{b,hw} x*cm / (B*HW) ----------------
__global__ void k10_proto() {
    int c = blockIdx.x;
    float acc[8] = {};
    for (int i = threadIdx.x; i < BB * HWW; i += 256) {
        int b = i >> 10, hw = i & 1023;
        float xv = g_x[((size_t)(b * CC + c)) * HWW + hw];
#pragma unroll
        for (int k = 0; k < 8; k++) acc[k] += xv * g_cm[(b * 8 + k) * HWW + hw];
    }
    __shared__ float red[256];
    for (int k = 0; k < 8; k++) {
        red[threadIdx.x] = acc[k];
        __syncthreads();
        for (int s = 128; s > 0; s >>= 1) {
            if (threadIdx.x < s) red[threadIdx.x] += red[threadIdx.x + s];
            __syncthreads();
        }
        if (threadIdx.x == 0) g_proto[k * CC + c] = red[0] * (1.f / (BB * HWW));
        __syncthreads();
    }
}

// ---------------- K11: proto_mean + out_pro ----------------------------------
__global__ void k11_pm(float* __restrict__ out) {
    int c = threadIdx.x;   // 512 threads
    float s = 0.f;
#pragma unroll
    for (int k = 0; k < 8; k++) s += g_proto[k * CC + c];
    s *= 0.125f;
    g_pm[c] = s;
    __shared__ float red[512];
    red[c] = s * s;
    __syncthreads();
    for (int st = 256; st > 0; st >>= 1) {
        if (c < st) red[c] += red[c + st];
        __syncthreads();
    }
    float nrm = fmaxf(sqrtf(red[0]), 1e-12f);
    out[c] = s / nrm;
}

// ---------------- K12: out_map = l2norm(x*(pm + cm_mean)) --------------------
__global__ __launch_bounds__(256) void k12_out(float* __restrict__ out) {
    __shared__ float spm[CC];
    for (int e = threadIdx.x; e < CC; e += 256) spm[e] = g_pm[e];
    __syncthreads();
    int i = blockIdx.x * 256 + threadIdx.x;
    int b = i >> 10, hw = i & 1023;
    float cmm = g_cmmean[i];
    const float* xp = g_x + (size_t)b * CC * HWW + hw;
    float ss2 = 0.f;
    for (int c = 0; c < CC; c++) {
        float v = xp[c * HWW] * (spm[c] + cmm);
        ss2 += v * v;
    }
    float inv = 1.f / fmaxf(sqrtf(ss2), 1e-12f);
    float* op = out + CC + (size_t)b * CC * HWW + hw;
    for (int c = 0; c < CC; c++)
        op[c * HWW] = xp[c * HWW] * (spm[c] + cmm) * inv;
}

// ---------------- launcher ----------------------------------------------------
extern "C" void kernel_launch(void* const* d_in, const int* in_sizes, int n_in,
                              void* d_out, int out_size) {
    const float* x5     = (const float*)d_in[0];
    const float* conv_w = (const float*)d_in[1];
    const float* conv_b = (const float*)d_in[2];
    const float* caps_w = (const float*)d_in[3];
    const float* caps_b = (const float*)d_in[4];
    float* out = (float*)d_out;
    (void)in_sizes; (void)n_in; (void)out_size;

    k0_tr   <<<1024, 256>>>(conv_w);
    k1_gemm <<<dim3(16, 8, 16), 256>>>(x5, conv_b);
    k2_conv <<<dim3(4, 4, 16), 256>>>(caps_w, caps_b);
    k3_norm <<<64, 256>>>();
    k4_sqmax<<<64, 256>>>();
    k5_argmax<<<128, 256>>>();
    k6_smean<<<16, 256>>>();
    k7_cm   <<<64, 256>>>();
    k8_minmax<<<128, 256>>>();
    k9_cmnorm<<<64, 256>>>();
    k10_proto<<<512, 256>>>();
    k11_pm  <<<1, 512>>>(out);
    k12_out <<<64, 256>>>(out);
}

// round 5
// speedup vs baseline: 2.5965x; 2.5965x over previous
#include <cuda_runtime.h>
#include <cuda_bf16.h>
#include <math.h>
#include <stdint.h>

#define BB   16
#define CC   512
#define HWW  1024
#define NCAPS 8
#define CAPC 32
#define OC   256
#define TAPS 81

// ================= helpers =================
__device__ __forceinline__ uint32_t smem_u32(const void* p) {
    uint32_t a;
    asm("{ .reg .u64 t; cvta.to.shared.u64 t, %1; cvt.u32.u64 %0, t; }" : "=r"(a) : "l"(p));
    return a;
}
#define CP_ASYNC16(dst, src) \
    asm volatile("cp.async.cg.shared.global [%0], [%1], 16;" :: "r"(dst), "l"(src) : "memory")
#define CP_COMMIT() asm volatile("cp.async.commit_group;" ::: "memory")
#define CP_WAIT1()  asm volatile("cp.async.wait_group 1;" ::: "memory")

__device__ __forceinline__ void ldsm_x4(uint32_t* r, uint32_t addr) {
    asm volatile("ldmatrix.sync.aligned.m8n8.x4.shared.b16 {%0,%1,%2,%3}, [%4];"
                 : "=r"(r[0]), "=r"(r[1]), "=r"(r[2]), "=r"(r[3]) : "r"(addr));
}
__device__ __forceinline__ void ldsm_x2(uint32_t* r, uint32_t addr) {
    asm volatile("ldmatrix.sync.aligned.m8n8.x2.shared.b16 {%0,%1}, [%2];"
                 : "=r"(r[0]), "=r"(r[1]) : "r"(addr));
}
__device__ __forceinline__ void mma_bf16(float* c, const uint32_t* a, const uint32_t* b) {
    asm volatile("mma.sync.aligned.m16n8k16.row.col.f32.bf16.bf16.f32 "
                 "{%0,%1,%2,%3}, {%4,%5,%6,%7}, {%8,%9}, {%0,%1,%2,%3};"
                 : "+f"(c[0]), "+f"(c[1]), "+f"(c[2]), "+f"(c[3])
                 : "r"(a[0]), "r"(a[1]), "r"(a[2]), "r"(a[3]), "r"(b[0]), "r"(b[1]));
}
// swizzled smem offset for (row, 16B-chunk kc) on 64B rows: conflict-free ldmatrix
__device__ __forceinline__ uint32_t swz(int row, int kc) {
    return (uint32_t)(row * 64 + (((kc) + (row >> 1)) & 3) * 16);
}

// ================= scratch =================
__device__ __align__(128) float g_wt[CC * CC];
__device__ __align__(128) float g_x[BB * CC * HWW];
__device__ __align__(128) float g_cap[(size_t)BB * OC * HWW];
__device__ float g_cap4[BB * NCAPS * HWW];
__device__ int   g_idx[BB * NCAPS];
__device__ float g_norm[BB * HWW];
__device__ float g_smean[CC * NCAPS];
__device__ float g_cm[BB * NCAPS * HWW];
__device__ float g_mm[BB * NCAPS * 2];
__device__ float g_cmmean[BB * HWW];
__device__ float g_proto[NCAPS * CC];
__device__ float g_pm[CC];
// split-bf16 operands
__device__ __align__(128) __nv_bfloat16 g_w_hi[TAPS * OC * CC];     // [tap][oc][ci]
__device__ __align__(128) __nv_bfloat16 g_w_lo[TAPS * OC * CC];
__device__ __align__(128) __nv_bfloat16 g_xp_hi[BB * 40 * 40 * CC]; // [b][ph][pw][ci]
__device__ __align__(128) __nv_bfloat16 g_xp_lo[BB * 40 * 40 * CC];

// ================= K0: transpose conv_w =================
__global__ void k0_tr(const float* __restrict__ w) {
    int i = blockIdx.x * 256 + threadIdx.x;
    int o = i >> 9, c = i & 511;
    g_wt[c * CC + o] = w[i];
}

// ================= K1: x = x5 @ W^T + b + x5 =================
__global__ __launch_bounds__(256) void k1_gemm(const float* __restrict__ x5,
                                               const float* __restrict__ bias) {
    __shared__ float As[16][64];
    __shared__ float Bs[16][64];
    int b  = blockIdx.z;
    int bo = blockIdx.y * 64;
    int bh = blockIdx.x * 64;
    int tid = threadIdx.x;
    int ty = tid >> 4, tx = tid & 15;
    float acc[4][4] = {};
    for (int k0 = 0; k0 < CC; k0 += 16) {
        for (int e = tid; e < 1024; e += 256) {
            int k_l = e >> 6, o_l = e & 63;
            As[k_l][o_l] = g_wt[(k0 + k_l) * CC + bo + o_l];
        }
        for (int e = tid; e < 1024; e += 256) {
            int k_l = e >> 6, h_l = e & 63;
            Bs[k_l][h_l] = x5[((size_t)(b * CC + k0 + k_l)) * HWW + bh + h_l];
        }
        __syncthreads();
#pragma unroll
        for (int k = 0; k < 16; k++) {
            float4 a  = *(const float4*)&As[k][ty * 4];
            float4 bb = *(const float4*)&Bs[k][tx * 4];
            float av[4] = {a.x, a.y, a.z, a.w};
            float bv[4] = {bb.x, bb.y, bb.z, bb.w};
#pragma unroll
            for (int i = 0; i < 4; i++)
#pragma unroll
                for (int j = 0; j < 4; j++) acc[i][j] += av[i] * bv[j];
        }
        __syncthreads();
    }
#pragma unroll
    for (int i = 0; i < 4; i++) {
        int o = bo + ty * 4 + i;
        float bi = bias[o];
#pragma unroll
        for (int j = 0; j < 4; j++) {
            int hw = bh + tx * 4 + j;
            size_t off = ((size_t)(b * CC + o)) * HWW + hw;
            g_x[off] = acc[i][j] + bi + x5[off];
        }
    }
}

// ================= KPW: prepack weights to bf16 hi/lo [tap][oc][ci] =========
__global__ void kp_w(const float* __restrict__ cw) {
    int i = blockIdx.x * 256 + threadIdx.x;
    int c = i & 511, o = (i >> 9) & 255, t = i >> 17;
    float v = cw[((size_t)o * CC + c) * TAPS + t];
    __nv_bfloat16 h = __float2bfloat16(v);
    g_w_hi[i] = h;
    g_w_lo[i] = __float2bfloat16(v - __bfloat162float(h));
}

// ================= KPZ: zero padded x planes =================================
__global__ void kp_xz() {
    int i = blockIdx.x * 256 + threadIdx.x;
    uint4 z = {0, 0, 0, 0};
    ((uint4*)g_xp_hi)[i] = z;
    ((uint4*)g_xp_lo)[i] = z;
}

// ================= KPX: transpose g_x -> padded pixel-major bf16 hi/lo ======
__global__ __launch_bounds__(256) void kp_x() {
    __shared__ float tile[32][33];
    int b = blockIdx.y, h = blockIdx.x;
    int tid = threadIdx.x;
    for (int c0 = 0; c0 < CC; c0 += 32) {
#pragma unroll
        for (int s = 0; s < 4; s++) {
            int cl = (tid >> 5) + s * 8, w = tid & 31;
            tile[cl][w] = g_x[((size_t)(b * CC + c0 + cl)) * HWW + h * 32 + w];
        }
        __syncthreads();
#pragma unroll
        for (int s = 0; s < 4; s++) {
            int wl = (tid >> 5) + s * 8, ci = tid & 31;
            float v = tile[ci][wl];
            size_t dst = ((size_t)((b * 40 + h + 4) * 40 + wl + 4)) * CC + c0 + ci;
            __nv_bfloat16 hh = __float2bfloat16(v);
            g_xp_hi[dst] = hh;
            g_xp_lo[dst] = __float2bfloat16(v - __bfloat162float(hh));
        }
        __syncthreads();
    }
}

// ================= K2: mma.sync bf16 conv (split-bf16, 3-term) ==============
// grid (4 N-tiles, 2 M-tiles, 16 b), 256 thr; stage 48KB x2 dyn smem
#define OFF_AH 0
#define OFF_AL 8192
#define OFF_BH 16384
#define OFF_BL 32768
#define STG    49152
#define NITER  1296
__global__ __launch_bounds__(256, 1) void k2_mma(const float* __restrict__ cb) {
    extern __shared__ char smem[];
    uint32_t sb = smem_u32(smem);
    int tid = threadIdx.x, wid = tid >> 5, lane = tid & 31;
    int pix0 = blockIdx.x * 256;
    int bh8  = blockIdx.x * 8;
    int ocb  = blockIdx.y * 128;
    int b    = blockIdx.z;
    int mbase = (wid >> 2) * 64;   // warp row within 128
    int nbase = (wid & 3) * 64;    // warp col within 256

    float acc[4][8][4];
#pragma unroll
    for (int mt = 0; mt < 4; mt++)
#pragma unroll
        for (int nt = 0; nt < 8; nt++)
#pragma unroll
            for (int j = 0; j < 4; j++) acc[mt][nt][j] = 0.f;

    // ---- loader lambda-ish (macro-free explicit) ----
    // issues 12 cp.async for iteration `it` into stage `s`
    auto issue = [&](int it, int s) {
        int tap = it >> 4, q = it & 15;
        int dy = tap / 9, dx = tap - dy * 9;
        uint32_t stg = sb + (uint32_t)s * STG;
#pragma unroll
        for (int p = 0; p < 2; p++) {       // A: 512 chunks/plane
            int c = tid + p * 256;
            int r = c >> 2, kc = c & 3;
            uint32_t so = swz(r, kc);
            size_t gi = ((size_t)(tap * OC + ocb + r)) * CC + q * 32 + kc * 8;
            CP_ASYNC16(stg + OFF_AH + so, (const void*)(g_w_hi + gi));
            CP_ASYNC16(stg + OFF_AL + so, (const void*)(g_w_lo + gi));
        }
#pragma unroll
        for (int p = 0; p < 4; p++) {       // B: 1024 chunks/plane
            int c = tid + p * 256;
            int n = c >> 2, kc = c & 3;
            uint32_t so = swz(n, kc);
            int prow = (b * 40 + bh8 + (n >> 5) + dy) * 40 + (n & 31) + dx;
            size_t gi = (size_t)prow * CC + q * 32 + kc * 8;
            CP_ASYNC16(stg + OFF_BH + so, (const void*)(g_xp_hi + gi));
            CP_ASYNC16(stg + OFF_BL + so, (const void*)(g_xp_lo + gi));
        }
    };

    issue(0, 0);
    CP_COMMIT();

    for (int it = 0; it < NITER; it++) {
        int s = it & 1;
        if (it + 1 < NITER) issue(it + 1, s ^ 1);
        CP_COMMIT();
        CP_WAIT1();
        __syncthreads();
        uint32_t stg = sb + (uint32_t)s * STG;
#pragma unroll
        for (int kb = 0; kb < 2; kb++) {
            uint32_t ah[4][4], al[4][4];
#pragma unroll
            for (int mt = 0; mt < 4; mt++) {
                int arow = mbase + mt * 16 + (lane & 15);
                int kcs = kb * 2 + (lane >> 4);
                uint32_t so = swz(arow, kcs);
                ldsm_x4(ah[mt], stg + OFF_AH + so);
                ldsm_x4(al[mt], stg + OFF_AL + so);
            }
#pragma unroll
            for (int nt = 0; nt < 8; nt++) {
                int l = lane & 15;
                int brow = nbase + nt * 8 + (l & 7);
                int kcs = kb * 2 + (l >> 3);
                uint32_t so = swz(brow, kcs);
                uint32_t bh[2], bl[2];
                ldsm_x2(bh, stg + OFF_BH + so);
                ldsm_x2(bl, stg + OFF_BL + so);
#pragma unroll
                for (int mt = 0; mt < 4; mt++) {
                    mma_bf16(acc[mt][nt], ah[mt], bh);
                    mma_bf16(acc[mt][nt], ah[mt], bl);
                    mma_bf16(acc[mt][nt], al[mt], bh);
                }
            }
        }
        __syncthreads();
    }

    // ---- epilogue: add bias, store ----
#pragma unroll
    for (int mt = 0; mt < 4; mt++) {
        int m0 = ocb + mbase + mt * 16 + (lane >> 2);
        float bi0 = cb[m0], bi1 = cb[m0 + 8];
        float* d0 = g_cap + ((size_t)(b * OC + m0)) * HWW + pix0;
        float* d1 = g_cap + ((size_t)(b * OC + m0 + 8)) * HWW + pix0;
#pragma unroll
        for (int nt = 0; nt < 8; nt++) {
            int n = nbase + nt * 8 + (lane & 3) * 2;
            d0[n]     = acc[mt][nt][0] + bi0;
            d0[n + 1] = acc[mt][nt][1] + bi0;
            d1[n]     = acc[mt][nt][2] + bi1;
            d1[n + 1] = acc[mt][nt][3] + bi1;
        }
    }
}

// ================= K3..K12 reductions =======================================
__global__ void k3_norm() {
    int i = blockIdx.x * 256 + threadIdx.x;
    int b = i >> 10, hw = i & 1023;
    const float* p = g_x + (size_t)b * CC * HWW + hw;
    float s = 0.f;
    for (int c = 0; c < CC; c++) { float v = p[c * HWW]; s += v * v; }
    g_norm[i] = sqrtf(s);
}

__global__ void k4_sqmax() {
    int i = blockIdx.x * 256 + threadIdx.x;
    int b = i >> 10, hw = i & 1023;
    const float* cp = g_cap + (size_t)b * OC * HWW + hw;
    float m[8];
#pragma unroll
    for (int k = 0; k < 8; k++) m[k] = -INFINITY;
    for (int c = 0; c < CAPC; c++) {
        float v[8]; float sq = 0.f;
#pragma unroll
        for (int k = 0; k < 8; k++) { v[k] = cp[(size_t)(k * CAPC + c) * HWW]; sq += v[k] * v[k]; }
        float s = sq / ((1.f + sq) * sqrtf(sq + 1e-8f));
#pragma unroll
        for (int k = 0; k < 8; k++) m[k] = fmaxf(m[k], v[k] * s);
    }
#pragma unroll
    for (int k = 0; k < 8; k++) g_cap4[(b * 8 + k) * HWW + hw] = m[k];
}

__global__ void k5_argmax() {
    int bk = blockIdx.x;
    __shared__ float sv[256];
    __shared__ int   si[256];
    int tid = threadIdx.x;
    float best = -INFINITY; int bi = 0;
    for (int hw = tid; hw < HWW; hw += 256) {
        float v = g_cap4[bk * HWW + hw];
        if (v > best) { best = v; bi = hw; }
    }
    sv[tid] = best; si[tid] = bi;
    __syncthreads();
    for (int s = 128; s > 0; s >>= 1) {
        if (tid < s) {
            if (sv[tid + s] > sv[tid] ||
                (sv[tid + s] == sv[tid] && si[tid + s] < si[tid])) {
                sv[tid] = sv[tid + s]; si[tid] = si[tid + s];
            }
        }
        __syncthreads();
    }
    if (tid == 0) g_idx[bk] = si[0];
}

__global__ void k6_smean() {
    int i = blockIdx.x * 256 + threadIdx.x;
    int c = i >> 3, k = i & 7;
    float s = 0.f;
    for (int b = 0; b < BB; b++) {
        int hw = g_idx[b * 8 + k];
        float n = fmaxf(g_norm[b * HWW + hw], 1e-12f);
        s += g_x[((size_t)(b * CC + c)) * HWW + hw] / n;
    }
    g_smean[c * 8 + k] = s * (1.f / 16.f);
}

__global__ __launch_bounds__(256) void k7_cm() {
    __shared__ float ss[CC * 8];
    for (int e = threadIdx.x; e < CC * 8; e += 256) ss[e] = g_smean[e];
    __syncthreads();
    int i = blockIdx.x * 256 + threadIdx.x;
    int b = i >> 10, hw = i & 1023;
    const float* xp = g_x + (size_t)b * CC * HWW + hw;
    float acc[8] = {};
    for (int c = 0; c < CC; c++) {
        float xv = xp[c * HWW];
#pragma unroll
        for (int k = 0; k < 8; k++) acc[k] += xv * ss[c * 8 + k];
    }
    float inv = 1.f / fmaxf(g_norm[i], 1e-12f);
#pragma unroll
    for (int k = 0; k < 8; k++) g_cm[(b * 8 + k) * HWW + hw] = acc[k] * inv;
}

__global__ void k8_minmax() {
    int bk = blockIdx.x;
    __shared__ float smn[256], smx[256];
    int tid = threadIdx.x;
    float mn = INFINITY, mx = -INFINITY;
    for (int hw = tid; hw < HWW; hw += 256) {
        float v = g_cm[bk * HWW + hw];
        mn = fminf(mn, v); mx = fmaxf(mx, v);
    }
    smn[tid] = mn; smx[tid] = mx;
    __syncthreads();
    for (int s = 128; s > 0; s >>= 1) {
        if (tid < s) {
            smn[tid] = fminf(smn[tid], smn[tid + s]);
            smx[tid] = fmaxf(smx[tid], smx[tid + s]);
        }
        __syncthreads();
    }
    if (tid == 0) { g_mm[bk * 2] = smn[0]; g_mm[bk * 2 + 1] = smx[0]; }
}

__global__ void k9_cmnorm() {
    int i = blockIdx.x * 256 + threadIdx.x;
    int b = i >> 10, hw = i & 1023;
    float s = 0.f;
#pragma unroll
    for (int k = 0; k < 8; k++) {
        int bk = b * 8 + k;
        float mn = g_mm[bk * 2], mx = g_mm[bk * 2 + 1];
        float v = (g_cm[bk * HWW + hw] - mn) / (mx - mn + 1e-12f);
        g_cm[bk * HWW + hw] = v;
        s += v;
    }
    g_cmmean[i] = s * 0.125f;
}

__global__ void k10_proto() {
    int c = blockIdx.x;
    float acc[8] = {};
    for (int i = threadIdx.x; i < BB * HWW; i += 256) {
        int b = i >> 10, hw = i & 1023;
        float xv = g_x[((size_t)(b * CC + c)) * HWW + hw];
#pragma unroll
        for (int k = 0; k < 8; k++) acc[k] += xv * g_cm[(b * 8 + k) * HWW + hw];
    }
    __shared__ float red[256];
    for (int k = 0; k < 8; k++) {
        red[threadIdx.x] = acc[k];
        __syncthreads();
        for (int s = 128; s > 0; s >>= 1) {
            if (threadIdx.x < s) red[threadIdx.x] += red[threadIdx.x + s];
            __syncthreads();
        }
        if (threadIdx.x == 0) g_proto[k * CC + c] = red[0] * (1.f / (BB * HWW));
        __syncthreads();
    }
}

__global__ void k11_pm(float* __restrict__ out) {
    int c = threadIdx.x;
    float s = 0.f;
#pragma unroll
    for (int k = 0; k < 8; k++) s += g_proto[k * CC + c];
    s *= 0.125f;
    g_pm[c] = s;
    __shared__ float red[512];
    red[c] = s * s;
    __syncthreads();
    for (int st = 256; st > 0; st >>= 1) {
        if (c < st) red[c] += red[c + st];
        __syncthreads();
    }
    float nrm = fmaxf(sqrtf(red[0]), 1e-12f);
    out[c] = s / nrm;
}

__global__ __launch_bounds__(256) void k12_out(float* __restrict__ out) {
    __shared__ float spm[CC];
    for (int e = threadIdx.x; e < CC; e += 256) spm[e] = g_pm[e];
    __syncthreads();
    int i = blockIdx.x * 256 + threadIdx.x;
    int b = i >> 10, hw = i & 1023;
    float cmm = g_cmmean[i];
    const float* xp = g_x + (size_t)b * CC * HWW + hw;
    float ss2 = 0.f;
    for (int c = 0; c < CC; c++) {
        float v = xp[c * HWW] * (spm[c] + cmm);
        ss2 += v * v;
    }
    float inv = 1.f / fmaxf(sqrtf(ss2), 1e-12f);
    float* op = out + CC + (size_t)b * CC * HWW + hw;
    for (int c = 0; c < CC; c++)
        op[c * HWW] = xp[c * HWW] * (spm[c] + cmm) * inv;
}

// ================= launcher ==================================================
extern "C" void kernel_launch(void* const* d_in, const int* in_sizes, int n_in,
                              void* d_out, int out_size) {
    const float* x5     = (const float*)d_in[0];
    const float* conv_w = (const float*)d_in[1];
    const float* conv_b = (const float*)d_in[2];
    const float* caps_w = (const float*)d_in[3];
    const float* caps_b = (const float*)d_in[4];
    float* out = (float*)d_out;
    (void)in_sizes; (void)n_in; (void)out_size;

    cudaFuncSetAttribute(k2_mma, cudaFuncAttributeMaxDynamicSharedMemorySize, 98304);

    k0_tr   <<<1024, 256>>>(conv_w);
    kp_w    <<<41472, 256>>>(caps_w);
    kp_xz   <<<6400, 256>>>();
    k1_gemm <<<dim3(16, 8, 16), 256>>>(x5, conv_b);
    kp_x    <<<dim3(32, 16), 256>>>();
    k2_mma  <<<dim3(4, 2, 16), 256, 98304>>>(caps_b);
    k3_norm <<<64, 256>>>();
    k4_sqmax<<<64, 256>>>();
    k5_argmax<<<128, 256>>>();
    k6_smean<<<16, 256>>>();
    k7_cm   <<<64, 256>>>();
    k8_minmax<<<128, 256>>>();
    k9_cmnorm<<<64, 256>>>();
    k10_proto<<<512, 256>>>();
    k11_pm  <<<1, 512>>>(out);
    k12_out <<<64, 256>>>(out);
}

// round 6
// speedup vs baseline: 2.9961x; 1.1539x over previous
#include <cuda_runtime.h>
#include <cuda_bf16.h>
#include <math.h>
#include <stdint.h>

#define BB   16
#define CC   512
#define HWW  1024
#define NCAPS 8
#define CAPC 32
#define OC   256
#define TAPS 81

// ================= helpers =================
__device__ __forceinline__ uint32_t smem_u32(const void* p) {
    uint32_t a;
    asm("{ .reg .u64 t; cvta.to.shared.u64 t, %1; cvt.u32.u64 %0, t; }" : "=r"(a) : "l"(p));
    return a;
}
#define CP_ASYNC16(dst, src) \
    asm volatile("cp.async.cg.shared.global [%0], [%1], 16;" :: "r"(dst), "l"(src) : "memory")
#define CP_COMMIT() asm volatile("cp.async.commit_group;" ::: "memory")
#define CP_WAIT0()  asm volatile("cp.async.wait_group 0;" ::: "memory")
#define CP_WAIT1()  asm volatile("cp.async.wait_group 1;" ::: "memory")

__device__ __forceinline__ void ldsm_x4(uint32_t* r, uint32_t addr) {
    asm volatile("ldmatrix.sync.aligned.m8n8.x4.shared.b16 {%0,%1,%2,%3}, [%4];"
                 : "=r"(r[0]), "=r"(r[1]), "=r"(r[2]), "=r"(r[3]) : "r"(addr));
}
__device__ __forceinline__ void mma_bf16(float* c, const uint32_t* a, const uint32_t* b) {
    asm volatile("mma.sync.aligned.m16n8k16.row.col.f32.bf16.bf16.f32 "
                 "{%0,%1,%2,%3}, {%4,%5,%6,%7}, {%8,%9}, {%0,%1,%2,%3};"
                 : "+f"(c[0]), "+f"(c[1]), "+f"(c[2]), "+f"(c[3])
                 : "r"(a[0]), "r"(a[1]), "r"(a[2]), "r"(a[3]), "r"(b[0]), "r"(b[1]));
}
// SW128-style swizzle on 64B logical rows (2 rows per 128B line): conflict-free
__device__ __forceinline__ uint32_t swz64(uint32_t o) { return o ^ ((o >> 3) & 0x70); }

// ================= scratch =================
__device__ __align__(128) float g_wt[CC * CC];
__device__ __align__(128) float g_x[BB * CC * HWW];
__device__ __align__(128) float g_cap[(size_t)BB * OC * HWW];
__device__ float g_cap4[BB * NCAPS * HWW];
__device__ int   g_idx[BB * NCAPS];
__device__ float g_norm[BB * HWW];
__device__ float g_smean[CC * NCAPS];
__device__ float g_cm[BB * NCAPS * HWW];
__device__ float g_mm[BB * NCAPS * 2];
__device__ float g_cmmean[BB * HWW];
__device__ float g_proto[NCAPS * CC];
__device__ float g_pm[CC];
__device__ __align__(128) __nv_bfloat16 g_w_hi[TAPS * OC * CC];     // [tap][oc][ci]
__device__ __align__(128) __nv_bfloat16 g_w_lo[TAPS * OC * CC];
__device__ __align__(128) __nv_bfloat16 g_xp_hi[BB * 40 * 40 * CC]; // [b][ph][pw][ci]
__device__ __align__(128) __nv_bfloat16 g_xp_lo[BB * 40 * 40 * CC];

// ================= K0: transpose conv_w =================
__global__ void k0_tr(const float* __restrict__ w) {
    int i = blockIdx.x * 256 + threadIdx.x;
    int o = i >> 9, c = i & 511;
    g_wt[c * CC + o] = w[i];
}

// ================= K1: x = x5 @ W^T + b + x5 =================
__global__ __launch_bounds__(256) void k1_gemm(const float* __restrict__ x5,
                                               const float* __restrict__ bias) {
    __shared__ float As[16][64];
    __shared__ float Bs[16][64];
    int b  = blockIdx.z;
    int bo = blockIdx.y * 64;
    int bh = blockIdx.x * 64;
    int tid = threadIdx.x;
    int ty = tid >> 4, tx = tid & 15;
    float acc[4][4] = {};
    for (int k0 = 0; k0 < CC; k0 += 16) {
        for (int e = tid; e < 1024; e += 256) {
            int k_l = e >> 6, o_l = e & 63;
            As[k_l][o_l] = g_wt[(k0 + k_l) * CC + bo + o_l];
        }
        for (int e = tid; e < 1024; e += 256) {
            int k_l = e >> 6, h_l = e & 63;
            Bs[k_l][h_l] = x5[((size_t)(b * CC + k0 + k_l)) * HWW + bh + h_l];
        }
        __syncthreads();
#pragma unroll
        for (int k = 0; k < 16; k++) {
            float4 a  = *(const float4*)&As[k][ty * 4];
            float4 bb = *(const float4*)&Bs[k][tx * 4];
            float av[4] = {a.x, a.y, a.z, a.w};
            float bv[4] = {bb.x, bb.y, bb.z, bb.w};
#pragma unroll
            for (int i = 0; i < 4; i++)
#pragma unroll
                for (int j = 0; j < 4; j++) acc[i][j] += av[i] * bv[j];
        }
        __syncthreads();
    }
#pragma unroll
    for (int i = 0; i < 4; i++) {
        int o = bo + ty * 4 + i;
        float bi = bias[o];
#pragma unroll
        for (int j = 0; j < 4; j++) {
            int hw = bh + tx * 4 + j;
            size_t off = ((size_t)(b * CC + o)) * HWW + hw;
            g_x[off] = acc[i][j] + bi + x5[off];
        }
    }
}

// ================= KPW: tiled transpose of caps_w -> bf16 hi/lo [tap][oc][ci]
__global__ __launch_bounds__(256) void kp_w(const float* __restrict__ cw) {
    __shared__ float tile[64 * 81];
    int o  = blockIdx.x >> 3;
    int c0 = (blockIdx.x & 7) * 64;
    int tid = threadIdx.x;
    for (int e = tid; e < 64 * 81; e += 256) {
        int c_l = e / 81, t = e - c_l * 81;
        tile[e] = cw[((size_t)o * CC + c0 + c_l) * TAPS + t];
    }
    __syncthreads();
    for (int e = tid; e < 81 * 64; e += 256) {
        int t = e >> 6, c_l = e & 63;
        float v = tile[c_l * 81 + t];
        __nv_bfloat16 h = __float2bfloat16(v);
        size_t di = ((size_t)(t * OC + o)) * CC + c0 + c_l;
        g_w_hi[di] = h;
        g_w_lo[di] = __float2bfloat16(v - __bfloat162float(h));
    }
}

// ================= KPZ: zero padded x planes =================================
__global__ void kp_xz() {
    int i = blockIdx.x * 256 + threadIdx.x;
    uint4 z = {0, 0, 0, 0};
    ((uint4*)g_xp_hi)[i] = z;
    ((uint4*)g_xp_lo)[i] = z;
}

// ================= KPX: transpose g_x -> padded pixel-major bf16 hi/lo ======
__global__ __launch_bounds__(256) void kp_x() {
    __shared__ float tile[32][33];
    int b = blockIdx.y, h = blockIdx.x;
    int tid = threadIdx.x;
    for (int c0 = 0; c0 < CC; c0 += 32) {
#pragma unroll
        for (int s = 0; s < 4; s++) {
            int cl = (tid >> 5) + s * 8, w = tid & 31;
            tile[cl][w] = g_x[((size_t)(b * CC + c0 + cl)) * HWW + h * 32 + w];
        }
        __syncthreads();
#pragma unroll
        for (int s = 0; s < 4; s++) {
            int wl = (tid >> 5) + s * 8, ci = tid & 31;
            float v = tile[ci][wl];
            size_t dst = ((size_t)((b * 40 + h + 4) * 40 + wl + 4)) * CC + c0 + ci;
            __nv_bfloat16 hh = __float2bfloat16(v);
            g_xp_hi[dst] = hh;
            g_xp_lo[dst] = __float2bfloat16(v - __bfloat162float(hh));
        }
        __syncthreads();
    }
}

// ================= K2: mma.sync conv, slab-resident B + 3-stage A ===========
// smem: B slab hi(40960) + lo(40960) + A stages 3 x (hi 8K + lo 8K) = 131072
#define SLAB_H 0u
#define SLAB_L 40960u
#define A_BASE 81920u
#define K2_SMEM 131072
__global__ __launch_bounds__(256, 1) void k2_mma(const float* __restrict__ cb) {
    extern __shared__ char smem[];
    uint32_t sb = smem_u32(smem);
    int tid = threadIdx.x, wid = tid >> 5, lane = tid & 31;
    int bh8  = blockIdx.x * 8;
    int pix0 = blockIdx.x * 256;
    int ocb  = blockIdx.y * 128;
    int b    = blockIdx.z;
    int mbase = (wid >> 2) * 64;
    int nbase = (wid & 3) * 64;

    float acc[4][8][4];
#pragma unroll
    for (int mt = 0; mt < 4; mt++)
#pragma unroll
        for (int nt = 0; nt < 8; nt++)
#pragma unroll
            for (int j = 0; j < 4; j++) acc[mt][nt][j] = 0.f;

    for (int q = 0; q < 16; q++) {
        __syncthreads();   // all warps done reading slab + A stages of prev q
        // ---- load B slab: 640 pixels x 64B, hi+lo ----
        for (int e = tid; e < 2560; e += 256) {
            int p = e >> 2, kc = e & 3;
            int pr = p / 40, pc = p - pr * 40;
            size_t gsrc = ((size_t)((b * 40 + bh8 + pr) * 40 + pc)) * CC + q * 32 + kc * 8;
            uint32_t so = swz64((uint32_t)(p * 64 + kc * 16));
            CP_ASYNC16(sb + SLAB_H + so, (const void*)(g_xp_hi + gsrc));
            CP_ASYNC16(sb + SLAB_L + so, (const void*)(g_xp_lo + gsrc));
        }
        CP_COMMIT();
        // ---- prime A stages 0,1 (taps 0,1) ----
#pragma unroll
        for (int t0 = 0; t0 < 2; t0++) {
#pragma unroll
            for (int p = 0; p < 4; p++) {
                int e = tid + p * 256;
                int plane = e >> 9, r = (e >> 2) & 127, kc = e & 3;
                size_t gsrc = ((size_t)(t0 * OC + ocb + r)) * CC + q * 32 + kc * 8;
                uint32_t so = swz64((uint32_t)(r * 64 + kc * 16));
                const __nv_bfloat16* src = (plane ? g_w_lo : g_w_hi) + gsrc;
                CP_ASYNC16(sb + A_BASE + (uint32_t)t0 * 16384u + (uint32_t)plane * 8192u + so,
                           (const void*)src);
            }
            CP_COMMIT();
        }
        CP_WAIT0();
        __syncthreads();

        for (int tap = 0; tap < TAPS; tap++) {
            int st = tap - (tap / 3) * 3;
            int dy = tap / 9, dx = tap - dy * 9;
            CP_WAIT1();
            __syncthreads();
            // issue A for tap+2 into stage (tap+2)%3
            if (tap + 2 < TAPS) {
                int tnx = tap + 2;
                int stn = tnx - (tnx / 3) * 3;
#pragma unroll
                for (int p = 0; p < 4; p++) {
                    int e = tid + p * 256;
                    int plane = e >> 9, r = (e >> 2) & 127, kc = e & 3;
                    size_t gsrc = ((size_t)(tnx * OC + ocb + r)) * CC + q * 32 + kc * 8;
                    uint32_t so = swz64((uint32_t)(r * 64 + kc * 16));
                    const __nv_bfloat16* src = (plane ? g_w_lo : g_w_hi) + gsrc;
                    CP_ASYNC16(sb + A_BASE + (uint32_t)stn * 16384u + (uint32_t)plane * 8192u + so,
                               (const void*)src);
                }
            }
            CP_COMMIT();
            // ---- compute tap ----
            uint32_t abase = sb + A_BASE + (uint32_t)st * 16384u;
#pragma unroll
            for (int kb = 0; kb < 2; kb++) {
                uint32_t ah[4][4], al[4][4];
#pragma unroll
                for (int mt = 0; mt < 4; mt++) {
                    int arow = mbase + mt * 16 + (lane & 15);
                    int kcs = kb * 2 + (lane >> 4);
                    uint32_t so = swz64((uint32_t)(arow * 64 + kcs * 16));
                    ldsm_x4(ah[mt], abase + so);
                    ldsm_x4(al[mt], abase + 8192u + so);
                }
#pragma unroll
                for (int ntp = 0; ntp < 4; ntp++) {
                    int m = lane >> 3;
                    int n_ = nbase + ntp * 16 + ((m & 2) << 2) + (lane & 7);
                    int hl = n_ >> 5, w = n_ & 31;
                    int kcs = kb * 2 + (m & 1);
                    int p = (hl + dy) * 40 + (w + dx);
                    uint32_t so = swz64((uint32_t)(p * 64 + kcs * 16));
                    uint32_t bh[4], bl[4];
                    ldsm_x4(bh, sb + SLAB_H + so);
                    ldsm_x4(bl, sb + SLAB_L + so);
#pragma unroll
                    for (int mt = 0; mt < 4; mt++) {
                        mma_bf16(acc[mt][2 * ntp],     ah[mt], bh);
                        mma_bf16(acc[mt][2 * ntp],     ah[mt], bl);
                        mma_bf16(acc[mt][2 * ntp],     al[mt], bh);
                        mma_bf16(acc[mt][2 * ntp + 1], ah[mt], bh + 2);
                        mma_bf16(acc[mt][2 * ntp + 1], ah[mt], bl + 2);
                        mma_bf16(acc[mt][2 * ntp + 1], al[mt], bh + 2);
                    }
                }
            }
        }
    }

    // ---- epilogue ----
#pragma unroll
    for (int mt = 0; mt < 4; mt++) {
        int m0 = ocb + mbase + mt * 16 + (lane >> 2);
        float bi0 = cb[m0], bi1 = cb[m0 + 8];
        float* d0 = g_cap + ((size_t)(b * OC + m0)) * HWW + pix0;
        float* d1 = g_cap + ((size_t)(b * OC + m0 + 8)) * HWW + pix0;
#pragma unroll
        for (int nt = 0; nt < 8; nt++) {
            int n = nbase + nt * 8 + (lane & 3) * 2;
            d0[n]     = acc[mt][nt][0] + bi0;
            d0[n + 1] = acc[mt][nt][1] + bi0;
            d1[n]     = acc[mt][nt][2] + bi1;
            d1[n + 1] = acc[mt][nt][3] + bi1;
        }
    }
}

// ================= K3..K12 reductions =======================================
__global__ void k3_norm() {
    int i = blockIdx.x * 256 + threadIdx.x;
    int b = i >> 10, hw = i & 1023;
    const float* p = g_x + (size_t)b * CC * HWW + hw;
    float s = 0.f;
    for (int c = 0; c < CC; c++) { float v = p[c * HWW]; s += v * v; }
    g_norm[i] = sqrtf(s);
}

__global__ void k4_sqmax() {
    int i = blockIdx.x * 256 + threadIdx.x;
    int b = i >> 10, hw = i & 1023;
    const float* cp = g_cap + (size_t)b * OC * HWW + hw;
    float m[8];
#pragma unroll
    for (int k = 0; k < 8; k++) m[k] = -INFINITY;
    for (int c = 0; c < CAPC; c++) {
        float v[8]; float sq = 0.f;
#pragma unroll
        for (int k = 0; k < 8; k++) { v[k] = cp[(size_t)(k * CAPC + c) * HWW]; sq += v[k] * v[k]; }
        float s = sq / ((1.f + sq) * sqrtf(sq + 1e-8f));
#pragma unroll
        for (int k = 0; k < 8; k++) m[k] = fmaxf(m[k], v[k] * s);
    }
#pragma unroll
    for (int k = 0; k < 8; k++) g_cap4[(b * 8 + k) * HWW + hw] = m[k];
}

__global__ void k5_argmax() {
    int bk = blockIdx.x;
    __shared__ float sv[256];
    __shared__ int   si[256];
    int tid = threadIdx.x;
    float best = -INFINITY; int bi = 0;
    for (int hw = tid; hw < HWW; hw += 256) {
        float v = g_cap4[bk * HWW + hw];
        if (v > best) { best = v; bi = hw; }
    }
    sv[tid] = best; si[tid] = bi;
    __syncthreads();
    for (int s = 128; s > 0; s >>= 1) {
        if (tid < s) {
            if (sv[tid + s] > sv[tid] ||
                (sv[tid + s] == sv[tid] && si[tid + s] < si[tid])) {
                sv[tid] = sv[tid + s]; si[tid] = si[tid + s];
            }
        }
        __syncthreads();
    }
    if (tid == 0) g_idx[bk] = si[0];
}

__global__ void k6_smean() {
    int i = blockIdx.x * 256 + threadIdx.x;
    int c = i >> 3, k = i & 7;
    float s = 0.f;
    for (int b = 0; b < BB; b++) {
        int hw = g_idx[b * 8 + k];
        float n = fmaxf(g_norm[b * HWW + hw], 1e-12f);
        s += g_x[((size_t)(b * CC + c)) * HWW + hw] / n;
    }
    g_smean[c * 8 + k] = s * (1.f / 16.f);
}

__global__ __launch_bounds__(256) void k7_cm() {
    __shared__ float ss[CC * 8];
    for (int e = threadIdx.x; e < CC * 8; e += 256) ss[e] = g_smean[e];
    __syncthreads();
    int i = blockIdx.x * 256 + threadIdx.x;
    int b = i >> 10, hw = i & 1023;
    const float* xp = g_x + (size_t)b * CC * HWW + hw;
    float acc[8] = {};
    for (int c = 0; c < CC; c++) {
        float xv = xp[c * HWW];
#pragma unroll
        for (int k = 0; k < 8; k++) acc[k] += xv * ss[c * 8 + k];
    }
    float inv = 1.f / fmaxf(g_norm[i], 1e-12f);
#pragma unroll
    for (int k = 0; k < 8; k++) g_cm[(b * 8 + k) * HWW + hw] = acc[k] * inv;
}

__global__ void k8_minmax() {
    int bk = blockIdx.x;
    __shared__ float smn[256], smx[256];
    int tid = threadIdx.x;
    float mn = INFINITY, mx = -INFINITY;
    for (int hw = tid; hw < HWW; hw += 256) {
        float v = g_cm[bk * HWW + hw];
        mn = fminf(mn, v); mx = fmaxf(mx, v);
    }
    smn[tid] = mn; smx[tid] = mx;
    __syncthreads();
    for (int s = 128; s > 0; s >>= 1) {
        if (tid < s) {
            smn[tid] = fminf(smn[tid], smn[tid + s]);
            smx[tid] = fmaxf(smx[tid], smx[tid + s]);
        }
        __syncthreads();
    }
    if (tid == 0) { g_mm[bk * 2] = smn[0]; g_mm[bk * 2 + 1] = smx[0]; }
}

__global__ void k9_cmnorm() {
    int i = blockIdx.x * 256 + threadIdx.x;
    int b = i >> 10, hw = i & 1023;
    float s = 0.f;
#pragma unroll
    for (int k = 0; k < 8; k++) {
        int bk = b * 8 + k;
        float mn = g_mm[bk * 2], mx = g_mm[bk * 2 + 1];
        float v = (g_cm[bk * HWW + hw] - mn) / (mx - mn + 1e-12f);
        g_cm[bk * HWW + hw] = v;
        s += v;
    }
    g_cmmean[i] = s * 0.125f;
}

__global__ void k10_proto() {
    int c = blockIdx.x;
    float acc[8] = {};
    for (int i = threadIdx.x; i < BB * HWW; i += 256) {
        int b = i >> 10, hw = i & 1023;
        float xv = g_x[((size_t)(b * CC + c)) * HWW + hw];
#pragma unroll
        for (int k = 0; k < 8; k++) acc[k] += xv * g_cm[(b * 8 + k) * HWW + hw];
    }
    __shared__ float red[256];
    for (int k = 0; k < 8; k++) {
        red[threadIdx.x] = acc[k];
        __syncthreads();
        for (int s = 128; s > 0; s >>= 1) {
            if (threadIdx.x < s) red[threadIdx.x] += red[threadIdx.x + s];
            __syncthreads();
        }
        if (threadIdx.x == 0) g_proto[k * CC + c] = red[0] * (1.f / (BB * HWW));
        __syncthreads();
    }
}

__global__ void k11_pm(float* __restrict__ out) {
    int c = threadIdx.x;
    float s = 0.f;
#pragma unroll
    for (int k = 0; k < 8; k++) s += g_proto[k * CC + c];
    s *= 0.125f;
    g_pm[c] = s;
    __shared__ float red[512];
    red[c] = s * s;
    __syncthreads();
    for (int st = 256; st > 0; st >>= 1) {
        if (c < st) red[c] += red[c + st];
        __syncthreads();
    }
    float nrm = fmaxf(sqrtf(red[0]), 1e-12f);
    out[c] = s / nrm;
}

__global__ __launch_bounds__(256) void k12_out(float* __restrict__ out) {
    __shared__ float spm[CC];
    for (int e = threadIdx.x; e < CC; e += 256) spm[e] = g_pm[e];
    __syncthreads();
    int i = blockIdx.x * 256 + threadIdx.x;
    int b = i >> 10, hw = i & 1023;
    float cmm = g_cmmean[i];
    const float* xp = g_x + (size_t)b * CC * HWW + hw;
    float ss2 = 0.f;
    for (int c = 0; c < CC; c++) {
        float v = xp[c * HWW] * (spm[c] + cmm);
        ss2 += v * v;
    }
    float inv = 1.f / fmaxf(sqrtf(ss2), 1e-12f);
    float* op = out + CC + (size_t)b * CC * HWW + hw;
    for (int c = 0; c < CC; c++)
        op[c * HWW] = xp[c * HWW] * (spm[c] + cmm) * inv;
}

// ================= launcher ==================================================
extern "C" void kernel_launch(void* const* d_in, const int* in_sizes, int n_in,
                              void* d_out, int out_size) {
    const float* x5     = (const float*)d_in[0];
    const float* conv_w = (const float*)d_in[1];
    const float* conv_b = (const float*)d_in[2];
    const float* caps_w = (const float*)d_in[3];
    const float* caps_b = (const float*)d_in[4];
    float* out = (float*)d_out;
    (void)in_sizes; (void)n_in; (void)out_size;

    cudaFuncSetAttribute(k2_mma, cudaFuncAttributeMaxDynamicSharedMemorySize, K2_SMEM);

    k0_tr   <<<1024, 256>>>(conv_w);
    kp_w    <<<2048, 256>>>(caps_w);
    kp_xz   <<<6400, 256>>>();
    k1_gemm <<<dim3(16, 8, 16), 256>>>(x5, conv_b);
    kp_x    <<<dim3(32, 16), 256>>>();
    k2_mma  <<<dim3(4, 2, 16), 256, K2_SMEM>>>(caps_b);
    k3_norm <<<64, 256>>>();
    k4_sqmax<<<64, 256>>>();
    k5_argmax<<<128, 256>>>();
    k6_smean<<<16, 256>>>();
    k7_cm   <<<64, 256>>>();
    k8_minmax<<<128, 256>>>();
    k9_cmnorm<<<64, 256>>>();
    k10_proto<<<512, 256>>>();
    k11_pm  <<<1, 512>>>(out);
    k12_out <<<64, 256>>>(out);
}

// round 7
// speedup vs baseline: 4.7434x; 1.5832x over previous
#include <cuda_runtime.h>
#include <cuda_bf16.h>
#include <math.h>
#include <stdint.h>

#define BB   16
#define CC   512
#define HWW  1024
#define NCAPS 8
#define CAPC 32
#define OC   256
#define TAPS 81
#define SLOTS 64
#define TOPK  8

// ================= helpers =================
__device__ __forceinline__ uint32_t smem_u32(const void* p) {
    uint32_t a;
    asm("{ .reg .u64 t; cvta.to.shared.u64 t, %1; cvt.u32.u64 %0, t; }" : "=r"(a) : "l"(p));
    return a;
}
#define CP_ASYNC16(dst, src) \
    asm volatile("cp.async.cg.shared.global [%0], [%1], 16;" :: "r"(dst), "l"(src) : "memory")
#define CP_COMMIT() asm volatile("cp.async.commit_group;" ::: "memory")
#define CP_WAIT0()  asm volatile("cp.async.wait_group 0;" ::: "memory")
#define CP_WAIT1()  asm volatile("cp.async.wait_group 1;" ::: "memory")

__device__ __forceinline__ void ldsm_x4(uint32_t* r, uint32_t addr) {
    asm volatile("ldmatrix.sync.aligned.m8n8.x4.shared.b16 {%0,%1,%2,%3}, [%4];"
                 : "=r"(r[0]), "=r"(r[1]), "=r"(r[2]), "=r"(r[3]) : "r"(addr));
}
__device__ __forceinline__ void mma_bf16(float* c, const uint32_t* a, const uint32_t* b) {
    asm volatile("mma.sync.aligned.m16n8k16.row.col.f32.bf16.bf16.f32 "
                 "{%0,%1,%2,%3}, {%4,%5,%6,%7}, {%8,%9}, {%0,%1,%2,%3};"
                 : "+f"(c[0]), "+f"(c[1]), "+f"(c[2]), "+f"(c[3])
                 : "r"(a[0]), "r"(a[1]), "r"(a[2]), "r"(a[3]), "r"(b[0]), "r"(b[1]));
}
__device__ __forceinline__ uint32_t swz64(uint32_t o) { return o ^ ((o >> 3) & 0x70); }

// ================= scratch =================
__device__ __align__(128) float g_wt[CC * CC];
__device__ __align__(128) float g_x[BB * CC * HWW];
__device__ __align__(128) float g_cap[(size_t)BB * OC * HWW];
__device__ float g_cap4[BB * NCAPS * HWW];
__device__ int   g_idx[BB * NCAPS];
__device__ int   g_slots[BB * SLOTS];
__device__ float g_rpart[4 * BB * OC * SLOTS];   // split-K rescore partials
__device__ float g_norm[BB * HWW];
__device__ float g_smean[CC * NCAPS];
__device__ float g_cm[BB * NCAPS * HWW];
__device__ float g_mm[BB * NCAPS * 2];
__device__ float g_cmmean[BB * HWW];
__device__ float g_proto[NCAPS * CC];
__device__ float g_pm[CC];
__device__ __align__(128) __nv_bfloat16 g_w_hi[TAPS * OC * CC];
__device__ __align__(128) __nv_bfloat16 g_w_lo[TAPS * OC * CC];
__device__ __align__(128) __nv_bfloat16 g_xp_hi[BB * 40 * 40 * CC];
__device__ __align__(128) __nv_bfloat16 g_xp_lo[BB * 40 * 40 * CC];

// ================= K0: transpose conv_w =================
__global__ void k0_tr(const float* __restrict__ w) {
    int i = blockIdx.x * 256 + threadIdx.x;
    int o = i >> 9, c = i & 511;
    g_wt[c * CC + o] = w[i];
}

// ================= K1: x = x5 @ W^T + b + x5 =================
__global__ __launch_bounds__(256) void k1_gemm(const float* __restrict__ x5,
                                               const float* __restrict__ bias) {
    __shared__ float As[16][64];
    __shared__ float Bs[16][64];
    int b  = blockIdx.z;
    int bo = blockIdx.y * 64;
    int bh = blockIdx.x * 64;
    int tid = threadIdx.x;
    int ty = tid >> 4, tx = tid & 15;
    float acc[4][4] = {};
    for (int k0 = 0; k0 < CC; k0 += 16) {
        for (int e = tid; e < 1024; e += 256) {
            int k_l = e >> 6, o_l = e & 63;
            As[k_l][o_l] = g_wt[(k0 + k_l) * CC + bo + o_l];
        }
        for (int e = tid; e < 1024; e += 256) {
            int k_l = e >> 6, h_l = e & 63;
            Bs[k_l][h_l] = x5[((size_t)(b * CC + k0 + k_l)) * HWW + bh + h_l];
        }
        __syncthreads();
#pragma unroll
        for (int k = 0; k < 16; k++) {
            float4 a  = *(const float4*)&As[k][ty * 4];
            float4 bb = *(const float4*)&Bs[k][tx * 4];
            float av[4] = {a.x, a.y, a.z, a.w};
            float bv[4] = {bb.x, bb.y, bb.z, bb.w};
#pragma unroll
            for (int i = 0; i < 4; i++)
#pragma unroll
                for (int j = 0; j < 4; j++) acc[i][j] += av[i] * bv[j];
        }
        __syncthreads();
    }
#pragma unroll
    for (int i = 0; i < 4; i++) {
        int o = bo + ty * 4 + i;
        float bi = bias[o];
#pragma unroll
        for (int j = 0; j < 4; j++) {
            int hw = bh + tx * 4 + j;
            size_t off = ((size_t)(b * CC + o)) * HWW + hw;
            g_x[off] = acc[i][j] + bi + x5[off];
        }
    }
}

// ================= KPW: transpose caps_w -> bf16 hi/lo [tap][oc][ci] ========
__global__ __launch_bounds__(256) void kp_w(const float* __restrict__ cw) {
    __shared__ float tile[64 * 81];
    int o  = blockIdx.x >> 3;
    int c0 = (blockIdx.x & 7) * 64;
    int tid = threadIdx.x;
    for (int e = tid; e < 64 * 81; e += 256) {
        int c_l = e / 81, t = e - c_l * 81;
        tile[e] = cw[((size_t)o * CC + c0 + c_l) * TAPS + t];
    }
    __syncthreads();
    for (int e = tid; e < 81 * 64; e += 256) {
        int t = e >> 6, c_l = e & 63;
        float v = tile[c_l * 81 + t];
        __nv_bfloat16 h = __float2bfloat16(v);
        size_t di = ((size_t)(t * OC + o)) * CC + c0 + c_l;
        g_w_hi[di] = h;
        g_w_lo[di] = __float2bfloat16(v - __bfloat162float(h));
    }
}

// ================= KPZ: zero padded x planes =================================
__global__ void kp_xz() {
    int i = blockIdx.x * 256 + threadIdx.x;
    uint4 z = {0, 0, 0, 0};
    ((uint4*)g_xp_hi)[i] = z;
    ((uint4*)g_xp_lo)[i] = z;
}

// ================= KPX: transpose g_x -> padded pixel-major bf16 hi/lo ======
__global__ __launch_bounds__(256) void kp_x() {
    __shared__ float tile[32][33];
    int b = blockIdx.y, h = blockIdx.x;
    int tid = threadIdx.x;
    for (int c0 = 0; c0 < CC; c0 += 32) {
#pragma unroll
        for (int s = 0; s < 4; s++) {
            int cl = (tid >> 5) + s * 8, w = tid & 31;
            tile[cl][w] = g_x[((size_t)(b * CC + c0 + cl)) * HWW + h * 32 + w];
        }
        __syncthreads();
#pragma unroll
        for (int s = 0; s < 4; s++) {
            int wl = (tid >> 5) + s * 8, ci = tid & 31;
            float v = tile[ci][wl];
            size_t dst = ((size_t)((b * 40 + h + 4) * 40 + wl + 4)) * CC + c0 + ci;
            __nv_bfloat16 hh = __float2bfloat16(v);
            g_xp_hi[dst] = hh;
            g_xp_lo[dst] = __float2bfloat16(v - __bfloat162float(hh));
        }
        __syncthreads();
    }
}

// ================= K2a: 1-term bf16 conv (approx, ranking only) =============
#define SLAB_H 0u
#define A_BASE 40960u
#define K2A_SMEM 65536
__global__ __launch_bounds__(256, 1) void k2a_mma(const float* __restrict__ cb) {
    extern __shared__ char smem[];
    uint32_t sb = smem_u32(smem);
    int tid = threadIdx.x, wid = tid >> 5, lane = tid & 31;
    int bh8  = blockIdx.x * 8;
    int pix0 = blockIdx.x * 256;
    int ocb  = blockIdx.y * 128;
    int b    = blockIdx.z;
    int mbase = (wid >> 2) * 64;
    int nbase = (wid & 3) * 64;

    float acc[4][8][4];
#pragma unroll
    for (int mt = 0; mt < 4; mt++)
#pragma unroll
        for (int nt = 0; nt < 8; nt++)
#pragma unroll
            for (int j = 0; j < 4; j++) acc[mt][nt][j] = 0.f;

    for (int q = 0; q < 16; q++) {
        __syncthreads();
        // B slab (hi only): 640 pixels x 64B
        for (int e = tid; e < 2560; e += 256) {
            int p = e >> 2, kc = e & 3;
            int pr = p / 40, pc = p - pr * 40;
            size_t gsrc = ((size_t)((b * 40 + bh8 + pr) * 40 + pc)) * CC + q * 32 + kc * 8;
            CP_ASYNC16(sb + SLAB_H + swz64((uint32_t)(p * 64 + kc * 16)),
                       (const void*)(g_xp_hi + gsrc));
        }
        CP_COMMIT();
        // prime A stages 0,1 (hi only)
#pragma unroll
        for (int t0 = 0; t0 < 2; t0++) {
#pragma unroll
            for (int p = 0; p < 2; p++) {
                int e = tid + p * 256;
                int r = e >> 2, kc = e & 3;
                size_t gsrc = ((size_t)(t0 * OC + ocb + r)) * CC + q * 32 + kc * 8;
                CP_ASYNC16(sb + A_BASE + (uint32_t)t0 * 8192u + swz64((uint32_t)(r * 64 + kc * 16)),
                           (const void*)(g_w_hi + gsrc));
            }
            CP_COMMIT();
        }
        CP_WAIT0();
        __syncthreads();

        for (int tap = 0; tap < TAPS; tap++) {
            int st = tap - (tap / 3) * 3;
            int dy = tap / 9, dx = tap - dy * 9;
            CP_WAIT1();
            __syncthreads();
            if (tap + 2 < TAPS) {
                int tnx = tap + 2;
                int stn = tnx - (tnx / 3) * 3;
#pragma unroll
                for (int p = 0; p < 2; p++) {
                    int e = tid + p * 256;
                    int r = e >> 2, kc = e & 3;
                    size_t gsrc = ((size_t)(tnx * OC + ocb + r)) * CC + q * 32 + kc * 8;
                    CP_ASYNC16(sb + A_BASE + (uint32_t)stn * 8192u + swz64((uint32_t)(r * 64 + kc * 16)),
                               (const void*)(g_w_hi + gsrc));
                }
            }
            CP_COMMIT();
            uint32_t abase = sb + A_BASE + (uint32_t)st * 8192u;
#pragma unroll
            for (int kb = 0; kb < 2; kb++) {
                uint32_t ah[4][4];
#pragma unroll
                for (int mt = 0; mt < 4; mt++) {
                    int arow = mbase + mt * 16 + (lane & 15);
                    int kcs = kb * 2 + (lane >> 4);
                    ldsm_x4(ah[mt], abase + swz64((uint32_t)(arow * 64 + kcs * 16)));
                }
#pragma unroll
                for (int ntp = 0; ntp < 4; ntp++) {
                    int m = lane >> 3;
                    int n_ = nbase + ntp * 16 + ((m & 2) << 2) + (lane & 7);
                    int hl = n_ >> 5, w = n_ & 31;
                    int kcs = kb * 2 + (m & 1);
                    int p = (hl + dy) * 40 + (w + dx);
                    uint32_t bh[4];
                    ldsm_x4(bh, sb + SLAB_H + swz64((uint32_t)(p * 64 + kcs * 16)));
#pragma unroll
                    for (int mt = 0; mt < 4; mt++) {
                        mma_bf16(acc[mt][2 * ntp],     ah[mt], bh);
                        mma_bf16(acc[mt][2 * ntp + 1], ah[mt], bh + 2);
                    }
                }
            }
        }
    }
#pragma unroll
    for (int mt = 0; mt < 4; mt++) {
        int m0 = ocb + mbase + mt * 16 + (lane >> 2);
        float bi0 = cb[m0], bi1 = cb[m0 + 8];
        float* d0 = g_cap + ((size_t)(b * OC + m0)) * HWW + pix0;
        float* d1 = g_cap + ((size_t)(b * OC + m0 + 8)) * HWW + pix0;
#pragma unroll
        for (int nt = 0; nt < 8; nt++) {
            int n = nbase + nt * 8 + (lane & 3) * 2;
            d0[n]     = acc[mt][nt][0] + bi0;
            d0[n + 1] = acc[mt][nt][1] + bi0;
            d1[n]     = acc[mt][nt][2] + bi1;
            d1[n + 1] = acc[mt][nt][3] + bi1;
        }
    }
}

// ================= K4: squash + max over CAP_C (approx values) ==============
__global__ void k4_sqmax() {
    int i = blockIdx.x * 256 + threadIdx.x;
    int b = i >> 10, hw = i & 1023;
    const float* cp = g_cap + (size_t)b * OC * HWW + hw;
    float m[8];
#pragma unroll
    for (int k = 0; k < 8; k++) m[k] = -INFINITY;
    for (int c = 0; c < CAPC; c++) {
        float v[8]; float sq = 0.f;
#pragma unroll
        for (int k = 0; k < 8; k++) { v[k] = cp[(size_t)(k * CAPC + c) * HWW]; sq += v[k] * v[k]; }
        float s = sq / ((1.f + sq) * sqrtf(sq + 1e-8f));
#pragma unroll
        for (int k = 0; k < 8; k++) m[k] = fmaxf(m[k], v[k] * s);
    }
#pragma unroll
    for (int k = 0; k < 8; k++) g_cap4[(b * 8 + k) * HWW + hw] = m[k];
}

// ================= K5: top-8 candidate pixels per (b,k) =====================
__global__ void k5_top8() {
    int bk = blockIdx.x;       // 128 blocks
    int b = bk >> 3, k = bk & 7;
    __shared__ float val[1024];
    __shared__ float sv[256];
    __shared__ int   si[256];
    int tid = threadIdx.x;
    for (int hw = tid; hw < HWW; hw += 256) val[hw] = g_cap4[bk * HWW + hw];
    __syncthreads();
    for (int j = 0; j < TOPK; j++) {
        float best = -INFINITY; int bi = 0x7fffffff;
        for (int hw = tid; hw < HWW; hw += 256) {
            float v = val[hw];
            if (v > best || (v == best && hw < bi)) { best = v; bi = hw; }
        }
        sv[tid] = best; si[tid] = bi;
        __syncthreads();
        for (int s = 128; s > 0; s >>= 1) {
            if (tid < s) {
                if (sv[tid + s] > sv[tid] ||
                    (sv[tid + s] == sv[tid] && si[tid + s] < si[tid])) {
                    sv[tid] = sv[tid + s]; si[tid] = si[tid + s];
                }
            }
            __syncthreads();
        }
        if (tid == 0) {
            g_slots[b * SLOTS + k * TOPK + j] = si[0];
            val[si[0]] = -INFINITY;
        }
        __syncthreads();
    }
}

// ================= K2b: 3-term exact rescore at candidate pixels ============
// grid (qs=4, mtile=2, b=16); stage = A hi/lo 16K + B hi/lo 8K = 24576
#define RB_STG 24576u
#define K2B_SMEM 49664
__global__ __launch_bounds__(256, 1) void k2b_rescore() {
    extern __shared__ char smem[];
    uint32_t sb = smem_u32(smem);
    int* s_slots = (int*)(smem + 49152);
    int tid = threadIdx.x, wid = tid >> 5, lane = tid & 31;
    int qs  = blockIdx.x;
    int ocb = blockIdx.y * 128;
    int b   = blockIdx.z;
    int mbase = (wid >> 1) * 32;
    int nbase = (wid & 1) * 32;

    if (tid < SLOTS) s_slots[tid] = g_slots[b * SLOTS + tid];
    __syncthreads();

    float acc[2][4][4];
#pragma unroll
    for (int mt = 0; mt < 2; mt++)
#pragma unroll
        for (int nt = 0; nt < 4; nt++)
#pragma unroll
            for (int j = 0; j < 4; j++) acc[mt][nt][j] = 0.f;

    auto issue = [&](int it, int s) {
        int q = qs * 4 + it / 81;
        int tap = it - (it / 81) * 81;
        int dy = tap / 9, dx = tap - dy * 9;
        uint32_t stg = sb + (uint32_t)s * RB_STG;
#pragma unroll
        for (int p = 0; p < 4; p++) {   // A: 1024 chunks (hi+lo)
            int e = tid + p * 256;
            int plane = e >> 9, r = (e >> 2) & 127, kc = e & 3;
            size_t gsrc = ((size_t)(tap * OC + ocb + r)) * CC + q * 32 + kc * 8;
            const __nv_bfloat16* src = (plane ? g_w_lo : g_w_hi) + gsrc;
            CP_ASYNC16(stg + (uint32_t)plane * 8192u + swz64((uint32_t)(r * 64 + kc * 16)),
                       (const void*)src);
        }
#pragma unroll
        for (int p = 0; p < 2; p++) {   // B: 512 chunks (hi+lo), gathered rows
            int e = tid + p * 256;
            int plane = (e >> 8) & 1, row = (e >> 2) & 63, kc = e & 3;
            int pix = s_slots[row];
            int y = pix >> 5, x = pix & 31;
            size_t gsrc = ((size_t)((b * 40 + y + dy) * 40 + (x + dx))) * CC + q * 32 + kc * 8;
            const __nv_bfloat16* src = (plane ? g_xp_lo : g_xp_hi) + gsrc;
            CP_ASYNC16(stg + 16384u + (uint32_t)plane * 4096u + swz64((uint32_t)(row * 64 + kc * 16)),
                       (const void*)src);
        }
    };

    issue(0, 0);
    CP_COMMIT();
    const int NIT = 4 * TAPS;
    for (int it = 0; it < NIT; it++) {
        int s = it & 1;
        if (it + 1 < NIT) issue(it + 1, s ^ 1);
        CP_COMMIT();
        CP_WAIT1();
        __syncthreads();
        uint32_t stg = sb + (uint32_t)s * RB_STG;
#pragma unroll
        for (int kb = 0; kb < 2; kb++) {
            uint32_t ah[2][4], al[2][4];
#pragma unroll
            for (int mt = 0; mt < 2; mt++) {
                int arow = mbase + mt * 16 + (lane & 15);
                int kcs = kb * 2 + (lane >> 4);
                uint32_t so = swz64((uint32_t)(arow * 64 + kcs * 16));
                ldsm_x4(ah[mt], stg + so);
                ldsm_x4(al[mt], stg + 8192u + so);
            }
#pragma unroll
            for (int ntp = 0; ntp < 2; ntp++) {
                int m = lane >> 3;
                int row = nbase + ntp * 16 + ((m & 2) << 2) + (lane & 7);
                int kcs = kb * 2 + (m & 1);
                uint32_t so = swz64((uint32_t)(row * 64 + kcs * 16));
                uint32_t bh[4], bl[4];
                ldsm_x4(bh, stg + 16384u + so);
                ldsm_x4(bl, stg + 16384u + 4096u + so);
#pragma unroll
                for (int mt = 0; mt < 2; mt++) {
                    mma_bf16(acc[mt][2 * ntp],     ah[mt], bh);
                    mma_bf16(acc[mt][2 * ntp],     ah[mt], bl);
                    mma_bf16(acc[mt][2 * ntp],     al[mt], bh);
                    mma_bf16(acc[mt][2 * ntp + 1], ah[mt], bh + 2);
                    mma_bf16(acc[mt][2 * ntp + 1], ah[mt], bl + 2);
                    mma_bf16(acc[mt][2 * ntp + 1], al[mt], bh + 2);
                }
            }
        }
        __syncthreads();
    }
    // partial store (no bias here)
#pragma unroll
    for (int mt = 0; mt < 2; mt++) {
        int m0 = ocb + mbase + mt * 16 + (lane >> 2);
        float* d0 = g_rpart + ((size_t)((qs * BB + b) * OC + m0)) * SLOTS;
        float* d1 = d0 + 8 * SLOTS;
#pragma unroll
        for (int nt = 0; nt < 4; nt++) {
            int n = nbase + nt * 8 + (lane & 3) * 2;
            d0[n]     = acc[mt][nt][0];
            d0[n + 1] = acc[mt][nt][1];
            d1[n]     = acc[mt][nt][2];
            d1[n + 1] = acc[mt][nt][3];
        }
    }
}

// ================= K2c: combine + exact squash + final argmax ===============
#define K2C_SMEM (OC * SLOTS * 4 + NCAPS * SLOTS * 4 + SLOTS * 4)
__global__ __launch_bounds__(256) void k2c_pick(const float* __restrict__ cb) {
    extern __shared__ char smem[];
    float* v     = (float*)smem;                       // [256][64]
    float* sval  = (float*)(smem + OC * SLOTS * 4);    // [8][64]
    int*   sl    = (int*)(smem + OC * SLOTS * 4 + NCAPS * SLOTS * 4);
    int b = blockIdx.x, tid = threadIdx.x;
    if (tid < SLOTS) sl[tid] = g_slots[b * SLOTS + tid];
    for (int idx = tid; idx < OC * SLOTS; idx += 256) {
        int oc = idx >> 6;
        float s = cb[oc];
#pragma unroll
        for (int qs = 0; qs < 4; qs++)
            s += g_rpart[((size_t)((qs * BB + b) * OC)) * SLOTS + idx];
        v[idx] = s;
    }
    __syncthreads();
    if (tid < SLOTS) {
        float mk[8];
#pragma unroll
        for (int k = 0; k < 8; k++) mk[k] = -INFINITY;
        for (int c = 0; c < CAPC; c++) {
            float vv[8]; float sq = 0.f;
#pragma unroll
            for (int k = 0; k < 8; k++) {
                vv[k] = v[(k * CAPC + c) * SLOTS + tid];
                sq += vv[k] * vv[k];
            }
            float sf = sq / ((1.f + sq) * sqrtf(sq + 1e-8f));
#pragma unroll
            for (int k = 0; k < 8; k++) mk[k] = fmaxf(mk[k], vv[k] * sf);
        }
#pragma unroll
        for (int k = 0; k < 8; k++) sval[k * SLOTS + tid] = mk[k];
    }
    __syncthreads();
    if (tid < NCAPS) {
        float best = -INFINITY; int bp = 0x7fffffff;
        for (int s = 0; s < SLOTS; s++) {
            float vv = sval[tid * SLOTS + s];
            int px = sl[s];
            if (vv > best || (vv == best && px < bp)) { best = vv; bp = px; }
        }
        g_idx[b * NCAPS + tid] = bp;
    }
}

// ================= K3, K6..K12 (exact path, unchanged) ======================
__global__ void k3_norm() {
    int i = blockIdx.x * 256 + threadIdx.x;
    int b = i >> 10, hw = i & 1023;
    const float* p = g_x + (size_t)b * CC * HWW + hw;
    float s = 0.f;
    for (int c = 0; c < CC; c++) { float v = p[c * HWW]; s += v * v; }
    g_norm[i] = sqrtf(s);
}

__global__ void k6_smean() {
    int i = blockIdx.x * 256 + threadIdx.x;
    int c = i >> 3, k = i & 7;
    float s = 0.f;
    for (int b = 0; b < BB; b++) {
        int hw = g_idx[b * 8 + k];
        float n = fmaxf(g_norm[b * HWW + hw], 1e-12f);
        s += g_x[((size_t)(b * CC + c)) * HWW + hw] / n;
    }
    g_smean[c * 8 + k] = s * (1.f / 16.f);
}

__global__ __launch_bounds__(256) void k7_cm() {
    __shared__ float ss[CC * 8];
    for (int e = threadIdx.x; e < CC * 8; e += 256) ss[e] = g_smean[e];
    __syncthreads();
    int i = blockIdx.x * 256 + threadIdx.x;
    int b = i >> 10, hw = i & 1023;
    const float* xp = g_x + (size_t)b * CC * HWW + hw;
    float acc[8] = {};
    for (int c = 0; c < CC; c++) {
        float xv = xp[c * HWW];
#pragma unroll
        for (int k = 0; k < 8; k++) acc[k] += xv * ss[c * 8 + k];
    }
    float inv = 1.f / fmaxf(g_norm[i], 1e-12f);
#pragma unroll
    for (int k = 0; k < 8; k++) g_cm[(b * 8 + k) * HWW + hw] = acc[k] * inv;
}

__global__ void k8_minmax() {
    int bk = blockIdx.x;
    __shared__ float smn[256], smx[256];
    int tid = threadIdx.x;
    float mn = INFINITY, mx = -INFINITY;
    for (int hw = tid; hw < HWW; hw += 256) {
        float v = g_cm[bk * HWW + hw];
        mn = fminf(mn, v); mx = fmaxf(mx, v);
    }
    smn[tid] = mn; smx[tid] = mx;
    __syncthreads();
    for (int s = 128; s > 0; s >>= 1) {
        if (tid < s) {
            smn[tid] = fminf(smn[tid], smn[tid + s]);
            smx[tid] = fmaxf(smx[tid], smx[tid + s]);
        }
        __syncthreads();
    }
    if (tid == 0) { g_mm[bk * 2] = smn[0]; g_mm[bk * 2 + 1] = smx[0]; }
}

__global__ void k9_cmnorm() {
    int i = blockIdx.x * 256 + threadIdx.x;
    int b = i >> 10, hw = i & 1023;
    float s = 0.f;
#pragma unroll
    for (int k = 0; k < 8; k++) {
        int bk = b * 8 + k;
        float mn = g_mm[bk * 2], mx = g_mm[bk * 2 + 1];
        float v = (g_cm[bk * HWW + hw] - mn) / (mx - mn + 1e-12f);
        g_cm[bk * HWW + hw] = v;
        s += v;
    }
    g_cmmean[i] = s * 0.125f;
}

__global__ void k10_proto() {
    int c = blockIdx.x;
    float acc[8] = {};
    for (int i = threadIdx.x; i < BB * HWW; i += 256) {
        int b = i >> 10, hw = i & 1023;
        float xv = g_x[((size_t)(b * CC + c)) * HWW + hw];
#pragma unroll
        for (int k = 0; k < 8; k++) acc[k] += xv * g_cm[(b * 8 + k) * HWW + hw];
    }
    __shared__ float red[256];
    for (int k = 0; k < 8; k++) {
        red[threadIdx.x] = acc[k];
        __syncthreads();
        for (int s = 128; s > 0; s >>= 1) {
            if (threadIdx.x < s) red[threadIdx.x] += red[threadIdx.x + s];
            __syncthreads();
        }
        if (threadIdx.x == 0) g_proto[k * CC + c] = red[0] * (1.f / (BB * HWW));
        __syncthreads();
    }
}

__global__ void k11_pm(float* __restrict__ out) {
    int c = threadIdx.x;
    float s = 0.f;
#pragma unroll
    for (int k = 0; k < 8; k++) s += g_proto[k * CC + c];
    s *= 0.125f;
    g_pm[c] = s;
    __shared__ float red[512];
    red[c] = s * s;
    __syncthreads();
    for (int st = 256; st > 0; st >>= 1) {
        if (c < st) red[c] += red[c + st];
        __syncthreads();
    }
    float nrm = fmaxf(sqrtf(red[0]), 1e-12f);
    out[c] = s / nrm;
}

__global__ __launch_bounds__(256) void k12_out(float* __restrict__ out) {
    __shared__ float spm[CC];
    for (int e = threadIdx.x; e < CC; e += 256) spm[e] = g_pm[e];
    __syncthreads();
    int i = blockIdx.x * 256 + threadIdx.x;
    int b = i >> 10, hw = i & 1023;
    float cmm = g_cmmean[i];
    const float* xp = g_x + (size_t)b * CC * HWW + hw;
    float ss2 = 0.f;
    for (int c = 0; c < CC; c++) {
        float v = xp[c * HWW] * (spm[c] + cmm);
        ss2 += v * v;
    }
    float inv = 1.f / fmaxf(sqrtf(ss2), 1e-12f);
    float* op = out + CC + (size_t)b * CC * HWW + hw;
    for (int c = 0; c < CC; c++)
        op[c * HWW] = xp[c * HWW] * (spm[c] + cmm) * inv;
}

// ================= launcher ==================================================
extern "C" void kernel_launch(void* const* d_in, const int* in_sizes, int n_in,
                              void* d_out, int out_size) {
    const float* x5     = (const float*)d_in[0];
    const float* conv_w = (const float*)d_in[1];
    const float* conv_b = (const float*)d_in[2];
    const float* caps_w = (const float*)d_in[3];
    const float* caps_b = (const float*)d_in[4];
    float* out = (float*)d_out;
    (void)in_sizes; (void)n_in; (void)out_size;

    cudaFuncSetAttribute(k2a_mma,     cudaFuncAttributeMaxDynamicSharedMemorySize, K2A_SMEM);
    cudaFuncSetAttribute(k2b_rescore, cudaFuncAttributeMaxDynamicSharedMemorySize, K2B_SMEM);
    cudaFuncSetAttribute(k2c_pick,    cudaFuncAttributeMaxDynamicSharedMemorySize, K2C_SMEM);

    k0_tr   <<<1024, 256>>>(conv_w);
    kp_w    <<<2048, 256>>>(caps_w);
    kp_xz   <<<6400, 256>>>();
    k1_gemm <<<dim3(16, 8, 16), 256>>>(x5, conv_b);
    kp_x    <<<dim3(32, 16), 256>>>();
    k2a_mma <<<dim3(4, 2, 16), 256, K2A_SMEM>>>(caps_b);
    k3_norm <<<64, 256>>>();
    k4_sqmax<<<64, 256>>>();
    k5_top8 <<<128, 256>>>();
    k2b_rescore<<<dim3(4, 2, 16), 256, K2B_SMEM>>>();
    k2c_pick<<<16, 256, K2C_SMEM>>>(caps_b);
    k6_smean<<<16, 256>>>();
    k7_cm   <<<64, 256>>>();
    k8_minmax<<<128, 256>>>();
    k9_cmnorm<<<64, 256>>>();
    k10_proto<<<512, 256>>>();
    k11_pm  <<<1, 512>>>(out);
    k12_out <<<64, 256>>>(out);
}

// round 9
// speedup vs baseline: 5.6646x; 1.1942x over previous
#include <cuda_runtime.h>
#include <cuda_bf16.h>
#include <math.h>
#include <stdint.h>

#define BB   16
#define CC   512
#define HWW  1024
#define NCAPS 8
#define CAPC 32
#define OC   256
#define TAPS 81
#define SLOTS 64
#define TOPK  8

// ================= helpers =================
__device__ __forceinline__ uint32_t smem_u32(const void* p) {
    uint32_t a;
    asm("{ .reg .u64 t; cvta.to.shared.u64 t, %1; cvt.u32.u64 %0, t; }" : "=r"(a) : "l"(p));
    return a;
}
#define CP_ASYNC16(dst, src) \
    asm volatile("cp.async.cg.shared.global [%0], [%1], 16;" :: "r"(dst), "l"(src) : "memory")
#define CP_COMMIT() asm volatile("cp.async.commit_group;" ::: "memory")
#define CP_WAIT0()  asm volatile("cp.async.wait_group 0;" ::: "memory")
#define CP_WAIT1()  asm volatile("cp.async.wait_group 1;" ::: "memory")

__device__ __forceinline__ void ldsm_x4(uint32_t* r, uint32_t addr) {
    asm volatile("ldmatrix.sync.aligned.m8n8.x4.shared.b16 {%0,%1,%2,%3}, [%4];"
                 : "=r"(r[0]), "=r"(r[1]), "=r"(r[2]), "=r"(r[3]) : "r"(addr));
}
__device__ __forceinline__ void mma_bf16(float* c, const uint32_t* a, const uint32_t* b) {
    asm volatile("mma.sync.aligned.m16n8k16.row.col.f32.bf16.bf16.f32 "
                 "{%0,%1,%2,%3}, {%4,%5,%6,%7}, {%8,%9}, {%0,%1,%2,%3};"
                 : "+f"(c[0]), "+f"(c[1]), "+f"(c[2]), "+f"(c[3])
                 : "r"(a[0]), "r"(a[1]), "r"(a[2]), "r"(a[3]), "r"(b[0]), "r"(b[1]));
}
__device__ __forceinline__ uint32_t swz64(uint32_t o) { return o ^ ((o >> 3) & 0x70); }

// ================= scratch =================
__device__ __align__(128) float g_x[BB * CC * HWW];
__device__ __align__(128) float g_cap[(size_t)BB * OC * HWW];
__device__ float g_cap4[BB * NCAPS * HWW];
__device__ int   g_idx[BB * NCAPS];
__device__ int   g_slots[BB * SLOTS];
__device__ float g_rpart[4 * BB * OC * SLOTS];
__device__ float g_norm[BB * HWW];
__device__ float g_smean[CC * NCAPS];
__device__ float g_cm[BB * NCAPS * HWW];
__device__ float g_mm[BB * NCAPS * 2];
__device__ float g_cmmean[BB * HWW];
__device__ float g_proto[NCAPS * CC];
__device__ float g_pm[CC];
__device__ __align__(128) __nv_bfloat16 g_w_hi[TAPS * OC * CC];
__device__ __align__(128) __nv_bfloat16 g_w_lo[TAPS * OC * CC];
__device__ __align__(128) __nv_bfloat16 g_xp_hi[BB * 40 * 40 * CC];
__device__ __align__(128) __nv_bfloat16 g_xp_lo[BB * 40 * 40 * CC];
// k1 operands
__device__ __align__(128) __nv_bfloat16 g_cw_hi[CC * CC];           // [o][c]
__device__ __align__(128) __nv_bfloat16 g_cw_lo[CC * CC];
__device__ __align__(128) __nv_bfloat16 g_x5t_hi[BB * HWW * CC];    // [b][hw][c]
__device__ __align__(128) __nv_bfloat16 g_x5t_lo[BB * HWW * CC];

// ================= KP_W1: split conv_w into bf16 hi/lo ======================
__global__ void kp_w1(const float* __restrict__ w) {
    int i = blockIdx.x * 256 + threadIdx.x;   // 262144
    float v = w[i];
    __nv_bfloat16 h = __float2bfloat16(v);
    g_cw_hi[i] = h;
    g_cw_lo[i] = __float2bfloat16(v - __bfloat162float(h));
}

// ================= KP5: transpose x5 -> pixel-major bf16 hi/lo ==============
__global__ __launch_bounds__(256) void kp5(const float* __restrict__ x5) {
    __shared__ float tile[32][33];
    int b = blockIdx.y, h = blockIdx.x;
    int tid = threadIdx.x;
    for (int c0 = 0; c0 < CC; c0 += 32) {
#pragma unroll
        for (int s = 0; s < 4; s++) {
            int cl = (tid >> 5) + s * 8, w = tid & 31;
            tile[cl][w] = x5[((size_t)(b * CC + c0 + cl)) * HWW + h * 32 + w];
        }
        __syncthreads();
#pragma unroll
        for (int s = 0; s < 4; s++) {
            int wl = (tid >> 5) + s * 8, ci = tid & 31;
            float v = tile[ci][wl];
            size_t dst = ((size_t)(b * HWW + h * 32 + wl)) * CC + c0 + ci;
            __nv_bfloat16 hh = __float2bfloat16(v);
            g_x5t_hi[dst] = hh;
            g_x5t_lo[dst] = __float2bfloat16(v - __bfloat162float(hh));
        }
        __syncthreads();
    }
}

// ================= K1: split-bf16 mma: x = W@x5 + b + x5 ====================
// grid (4 pixtiles, 4 octiles, 16 b); stage = A hi/lo 16K + B hi/lo 32K
#define K1_STG 49152u
#define K1_SMEM 98304
__global__ __launch_bounds__(256, 1) void k1_mma(const float* __restrict__ x5,
                                                 const float* __restrict__ bias) {
    extern __shared__ char smem[];
    uint32_t sb = smem_u32(smem);
    int tid = threadIdx.x, wid = tid >> 5, lane = tid & 31;
    int pix0 = blockIdx.x * 256;
    int ocb  = blockIdx.y * 128;
    int b    = blockIdx.z;
    int mbase = (wid >> 2) * 64;
    int nbase = (wid & 3) * 64;

    float acc[4][8][4];
#pragma unroll
    for (int mt = 0; mt < 4; mt++)
#pragma unroll
        for (int nt = 0; nt < 8; nt++)
#pragma unroll
            for (int j = 0; j < 4; j++) acc[mt][nt][j] = 0.f;

    auto issue = [&](int kch, int s) {
        uint32_t stg = sb + (uint32_t)s * K1_STG;
#pragma unroll
        for (int p = 0; p < 4; p++) {   // A: 1024 chunks (hi+lo)
            int e = tid + p * 256;
            int plane = e >> 9, r = (e >> 2) & 127, kc = e & 3;
            size_t gsrc = (size_t)(ocb + r) * CC + kch * 32 + kc * 8;
            const __nv_bfloat16* src = (plane ? g_cw_lo : g_cw_hi) + gsrc;
            CP_ASYNC16(stg + (uint32_t)plane * 8192u + swz64((uint32_t)(r * 64 + kc * 16)),
                       (const void*)src);
        }
#pragma unroll
        for (int p = 0; p < 8; p++) {   // B: 2048 chunks (hi+lo)
            int e = tid + p * 256;
            int plane = e >> 10, row = (e >> 2) & 255, kc = e & 3;
            size_t gsrc = ((size_t)(b * HWW + pix0 + row)) * CC + kch * 32 + kc * 8;
            const __nv_bfloat16* src = (plane ? g_x5t_lo : g_x5t_hi) + gsrc;
            CP_ASYNC16(stg + 16384u + (uint32_t)plane * 16384u + swz64((uint32_t)(row * 64 + kc * 16)),
                       (const void*)src);
        }
    };

    issue(0, 0);
    CP_COMMIT();
    for (int kch = 0; kch < 16; kch++) {
        int s = kch & 1;
        if (kch + 1 < 16) issue(kch + 1, s ^ 1);
        CP_COMMIT();
        CP_WAIT1();
        __syncthreads();
        uint32_t stg = sb + (uint32_t)s * K1_STG;
#pragma unroll
        for (int kb = 0; kb < 2; kb++) {
            uint32_t ah[4][4], al[4][4];
#pragma unroll
            for (int mt = 0; mt < 4; mt++) {
                int arow = mbase + mt * 16 + (lane & 15);
                int kcs = kb * 2 + (lane >> 4);
                uint32_t so = swz64((uint32_t)(arow * 64 + kcs * 16));
                ldsm_x4(ah[mt], stg + so);
                ldsm_x4(al[mt], stg + 8192u + so);
            }
#pragma unroll
            for (int ntp = 0; ntp < 4; ntp++) {
                int m = lane >> 3;
                int row = nbase + ntp * 16 + ((m & 2) << 2) + (lane & 7);
                int kcs = kb * 2 + (m & 1);
                uint32_t so = swz64((uint32_t)(row * 64 + kcs * 16));
                uint32_t bh[4], bl[4];
                ldsm_x4(bh, stg + 16384u + so);
                ldsm_x4(bl, stg + 32768u + so);
#pragma unroll
                for (int mt = 0; mt < 4; mt++) {
                    mma_bf16(acc[mt][2 * ntp],     ah[mt], bh);
                    mma_bf16(acc[mt][2 * ntp],     ah[mt], bl);
                    mma_bf16(acc[mt][2 * ntp],     al[mt], bh);
                    mma_bf16(acc[mt][2 * ntp + 1], ah[mt], bh + 2);
                    mma_bf16(acc[mt][2 * ntp + 1], ah[mt], bl + 2);
                    mma_bf16(acc[mt][2 * ntp + 1], al[mt], bh + 2);
                }
            }
        }
        __syncthreads();
    }
    // epilogue: + bias + x5 residual
#pragma unroll
    for (int mt = 0; mt < 4; mt++) {
        int m0 = ocb + mbase + mt * 16 + (lane >> 2);
        float bi0 = bias[m0], bi1 = bias[m0 + 8];
        size_t base0 = ((size_t)(b * CC + m0)) * HWW + pix0;
        size_t base1 = ((size_t)(b * CC + m0 + 8)) * HWW + pix0;
#pragma unroll
        for (int nt = 0; nt < 8; nt++) {
            int n = nbase + nt * 8 + (lane & 3) * 2;
            g_x[base0 + n]     = acc[mt][nt][0] + bi0 + x5[base0 + n];
            g_x[base0 + n + 1] = acc[mt][nt][1] + bi0 + x5[base0 + n + 1];
            g_x[base1 + n]     = acc[mt][nt][2] + bi1 + x5[base1 + n];
            g_x[base1 + n + 1] = acc[mt][nt][3] + bi1 + x5[base1 + n + 1];
        }
    }
}

// ================= KPW: transpose caps_w -> bf16 hi/lo [tap][oc][ci] ========
__global__ __launch_bounds__(256) void kp_w(const float* __restrict__ cw) {
    __shared__ float tile[64 * 81];
    int o  = blockIdx.x >> 3;
    int c0 = (blockIdx.x & 7) * 64;
    int tid = threadIdx.x;
    for (int e = tid; e < 64 * 81; e += 256) {
        int c_l = e / 81, t = e - c_l * 81;
        tile[e] = cw[((size_t)o * CC + c0 + c_l) * TAPS + t];
    }
    __syncthreads();
    for (int e = tid; e < 81 * 64; e += 256) {
        int t = e >> 6, c_l = e & 63;
        float v = tile[c_l * 81 + t];
        __nv_bfloat16 h = __float2bfloat16(v);
        size_t di = ((size_t)(t * OC + o)) * CC + c0 + c_l;
        g_w_hi[di] = h;
        g_w_lo[di] = __float2bfloat16(v - __bfloat162float(h));
    }
}

// ================= KPZ: zero padded x planes =================================
__global__ void kp_xz() {
    int i = blockIdx.x * 256 + threadIdx.x;
    uint4 z = {0, 0, 0, 0};
    ((uint4*)g_xp_hi)[i] = z;
    ((uint4*)g_xp_lo)[i] = z;
}

// ================= KPX: transpose g_x -> padded pixel-major bf16 hi/lo ======
__global__ __launch_bounds__(256) void kp_x() {
    __shared__ float tile[32][33];
    int b = blockIdx.y, h = blockIdx.x;
    int tid = threadIdx.x;
    for (int c0 = 0; c0 < CC; c0 += 32) {
#pragma unroll
        for (int s = 0; s < 4; s++) {
            int cl = (tid >> 5) + s * 8, w = tid & 31;
            tile[cl][w] = g_x[((size_t)(b * CC + c0 + cl)) * HWW + h * 32 + w];
        }
        __syncthreads();
#pragma unroll
        for (int s = 0; s < 4; s++) {
            int wl = (tid >> 5) + s * 8, ci = tid & 31;
            float v = tile[ci][wl];
            size_t dst = ((size_t)((b * 40 + h + 4) * 40 + wl + 4)) * CC + c0 + ci;
            __nv_bfloat16 hh = __float2bfloat16(v);
            g_xp_hi[dst] = hh;
            g_xp_lo[dst] = __float2bfloat16(v - __bfloat162float(hh));
        }
        __syncthreads();
    }
}

// ================= K2a: 1-term bf16 conv (approx, ranking only) =============
#define SLAB_H 0u
#define A_BASE 40960u
#define K2A_SMEM 65536
__global__ __launch_bounds__(256, 1) void k2a_mma(const float* __restrict__ cb) {
    extern __shared__ char smem[];
    uint32_t sb = smem_u32(smem);
    int tid = threadIdx.x, wid = tid >> 5, lane = tid & 31;
    int bh8  = blockIdx.x * 8;
    int pix0 = blockIdx.x * 256;
    int ocb  = blockIdx.y * 128;
    int b    = blockIdx.z;
    int mbase = (wid >> 2) * 64;
    int nbase = (wid & 3) * 64;

    float acc[4][8][4];
#pragma unroll
    for (int mt = 0; mt < 4; mt++)
#pragma unroll
        for (int nt = 0; nt < 8; nt++)
#pragma unroll
            for (int j = 0; j < 4; j++) acc[mt][nt][j] = 0.f;

    for (int q = 0; q < 16; q++) {
        __syncthreads();
        for (int e = tid; e < 2560; e += 256) {
            int p = e >> 2, kc = e & 3;
            int pr = p / 40, pc = p - pr * 40;
            size_t gsrc = ((size_t)((b * 40 + bh8 + pr) * 40 + pc)) * CC + q * 32 + kc * 8;
            CP_ASYNC16(sb + SLAB_H + swz64((uint32_t)(p * 64 + kc * 16)),
                       (const void*)(g_xp_hi + gsrc));
        }
        CP_COMMIT();
#pragma unroll
        for (int t0 = 0; t0 < 2; t0++) {
#pragma unroll
            for (int p = 0; p < 2; p++) {
                int e = tid + p * 256;
                int r = e >> 2, kc = e & 3;
                size_t gsrc = ((size_t)(t0 * OC + ocb + r)) * CC + q * 32 + kc * 8;
                CP_ASYNC16(sb + A_BASE + (uint32_t)t0 * 8192u + swz64((uint32_t)(r * 64 + kc * 16)),
                           (const void*)(g_w_hi + gsrc));
            }
            CP_COMMIT();
        }
        CP_WAIT0();
        __syncthreads();

        for (int tap = 0; tap < TAPS; tap++) {
            int st = tap - (tap / 3) * 3;
            int dy = tap / 9, dx = tap - dy * 9;
            CP_WAIT1();
            __syncthreads();
            if (tap + 2 < TAPS) {
                int tnx = tap + 2;
                int stn = tnx - (tnx / 3) * 3;
#pragma unroll
                for (int p = 0; p < 2; p++) {
                    int e = tid + p * 256;
                    int r = e >> 2, kc = e & 3;
                    size_t gsrc = ((size_t)(tnx * OC + ocb + r)) * CC + q * 32 + kc * 8;
                    CP_ASYNC16(sb + A_BASE + (uint32_t)stn * 8192u + swz64((uint32_t)(r * 64 + kc * 16)),
                               (const void*)(g_w_hi + gsrc));
                }
            }
            CP_COMMIT();
            uint32_t abase = sb + A_BASE + (uint32_t)st * 8192u;
#pragma unroll
            for (int kb = 0; kb < 2; kb++) {
                uint32_t ah[4][4];
#pragma unroll
                for (int mt = 0; mt < 4; mt++) {
                    int arow = mbase + mt * 16 + (lane & 15);
                    int kcs = kb * 2 + (lane >> 4);
                    ldsm_x4(ah[mt], abase + swz64((uint32_t)(arow * 64 + kcs * 16)));
                }
#pragma unroll
                for (int ntp = 0; ntp < 4; ntp++) {
                    int m = lane >> 3;
                    int n_ = nbase + ntp * 16 + ((m & 2) << 2) + (lane & 7);
                    int hl = n_ >> 5, w = n_ & 31;
                    int kcs = kb * 2 + (m & 1);
                    int p = (hl + dy) * 40 + (w + dx);
                    uint32_t bh[4];
                    ldsm_x4(bh, sb + SLAB_H + swz64((uint32_t)(p * 64 + kcs * 16)));
#pragma unroll
                    for (int mt = 0; mt < 4; mt++) {
                        mma_bf16(acc[mt][2 * ntp],     ah[mt], bh);
                        mma_bf16(acc[mt][2 * ntp + 1], ah[mt], bh + 2);
                    }
                }
            }
        }
    }
#pragma unroll
    for (int mt = 0; mt < 4; mt++) {
        int m0 = ocb + mbase + mt * 16 + (lane >> 2);
        float bi0 = cb[m0], bi1 = cb[m0 + 8];
        float* d0 = g_cap + ((size_t)(b * OC + m0)) * HWW + pix0;
        float* d1 = g_cap + ((size_t)(b * OC + m0 + 8)) * HWW + pix0;
#pragma unroll
        for (int nt = 0; nt < 8; nt++) {
            int n = nbase + nt * 8 + (lane & 3) * 2;
            d0[n]     = acc[mt][nt][0] + bi0;
            d0[n + 1] = acc[mt][nt][1] + bi0;
            d1[n]     = acc[mt][nt][2] + bi1;
            d1[n + 1] = acc[mt][nt][3] + bi1;
        }
    }
}

// ================= K4: squash + max over CAP_C (approx values) ==============
__global__ void k4_sqmax() {
    int i = blockIdx.x * 256 + threadIdx.x;
    int b = i >> 10, hw = i & 1023;
    const float* cp = g_cap + (size_t)b * OC * HWW + hw;
    float m[8];
#pragma unroll
    for (int k = 0; k < 8; k++) m[k] = -INFINITY;
    for (int c = 0; c < CAPC; c++) {
        float v[8]; float sq = 0.f;
#pragma unroll
        for (int k = 0; k < 8; k++) { v[k] = cp[(size_t)(k * CAPC + c) * HWW]; sq += v[k] * v[k]; }
        float s = sq / ((1.f + sq) * sqrtf(sq + 1e-8f));
#pragma unroll
        for (int k = 0; k < 8; k++) m[k] = fmaxf(m[k], v[k] * s);
    }
#pragma unroll
    for (int k = 0; k < 8; k++) g_cap4[(b * 8 + k) * HWW + hw] = m[k];
}

// ================= K5: top-8 candidate pixels per (b,k) =====================
__global__ void k5_top8() {
    int bk = blockIdx.x;
    int b = bk >> 3, k = bk & 7;
    __shared__ float val[1024];
    __shared__ float sv[256];
    __shared__ int   si[256];
    int tid = threadIdx.x;
    for (int hw = tid; hw < HWW; hw += 256) val[hw] = g_cap4[bk * HWW + hw];
    __syncthreads();
    for (int j = 0; j < TOPK; j++) {
        float best = -INFINITY; int bi = 0x7fffffff;
        for (int hw = tid; hw < HWW; hw += 256) {
            float v = val[hw];
            if (v > best || (v == best && hw < bi)) { best = v; bi = hw; }
        }
        sv[tid] = best; si[tid] = bi;
        __syncthreads();
        for (int s = 128; s > 0; s >>= 1) {
            if (tid < s) {
                if (sv[tid + s] > sv[tid] ||
                    (sv[tid + s] == sv[tid] && si[tid + s] < si[tid])) {
                    sv[tid] = sv[tid + s]; si[tid] = si[tid + s];
                }
            }
            __syncthreads();
        }
        if (tid == 0) {
            g_slots[b * SLOTS + k * TOPK + j] = si[0];
            val[si[0]] = -INFINITY;
        }
        __syncthreads();
    }
}

// ================= K2b: 3-term exact rescore at candidate pixels ============
#define RB_STG 24576u
#define K2B_SMEM 49664
__global__ __launch_bounds__(256, 1) void k2b_rescore() {
    extern __shared__ char smem[];
    uint32_t sb = smem_u32(smem);
    int* s_slots = (int*)(smem + 49152);
    int tid = threadIdx.x, wid = tid >> 5, lane = tid & 31;
    int qs  = blockIdx.x;
    int ocb = blockIdx.y * 128;
    int b   = blockIdx.z;
    int mbase = (wid >> 1) * 32;
    int nbase = (wid & 1) * 32;

    if (tid < SLOTS) s_slots[tid] = g_slots[b * SLOTS + tid];
    __syncthreads();

    float acc[2][4][4];
#pragma unroll
    for (int mt = 0; mt < 2; mt++)
#pragma unroll
        for (int nt = 0; nt < 4; nt++)
#pragma unroll
            for (int j = 0; j < 4; j++) acc[mt][nt][j] = 0.f;

    auto issue = [&](int it, int s) {
        int q = qs * 4 + it / 81;
        int tap = it - (it / 81) * 81;
        int dy = tap / 9, dx = tap - dy * 9;
        uint32_t stg = sb + (uint32_t)s * RB_STG;
#pragma unroll
        for (int p = 0; p < 4; p++) {
            int e = tid + p * 256;
            int plane = e >> 9, r = (e >> 2) & 127, kc = e & 3;
            size_t gsrc = ((size_t)(tap * OC + ocb + r)) * CC + q * 32 + kc * 8;
            const __nv_bfloat16* src = (plane ? g_w_lo : g_w_hi) + gsrc;
            CP_ASYNC16(stg + (uint32_t)plane * 8192u + swz64((uint32_t)(r * 64 + kc * 16)),
                       (const void*)src);
        }
#pragma unroll
        for (int p = 0; p < 2; p++) {
            int e = tid + p * 256;
            int plane = (e >> 8) & 1, row = (e >> 2) & 63, kc = e & 3;
            int pix = s_slots[row];
            int y = pix >> 5, x = pix & 31;
            size_t gsrc = ((size_t)((b * 40 + y + dy) * 40 + (x + dx))) * CC + q * 32 + kc * 8;
            const __nv_bfloat16* src = (plane ? g_xp_lo : g_xp_hi) + gsrc;
            CP_ASYNC16(stg + 16384u + (uint32_t)plane * 4096u + swz64((uint32_t)(row * 64 + kc * 16)),
                       (const void*)src);
        }
    };

    issue(0, 0);
    CP_COMMIT();
    const int NIT = 4 * TAPS;
    for (int it = 0; it < NIT; it++) {
        int s = it & 1;
        if (it + 1 < NIT) issue(it + 1, s ^ 1);
        CP_COMMIT();
        CP_WAIT1();
        __syncthreads();
        uint32_t stg = sb + (uint32_t)s * RB_STG;
#pragma unroll
        for (int kb = 0; kb < 2; kb++) {
            uint32_t ah[2][4], al[2][4];
#pragma unroll
            for (int mt = 0; mt < 2; mt++) {
                int arow = mbase + mt * 16 + (lane & 15);
                int kcs = kb * 2 + (lane >> 4);
                uint32_t so = swz64((uint32_t)(arow * 64 + kcs * 16));
                ldsm_x4(ah[mt], stg + so);
                ldsm_x4(al[mt], stg + 8192u + so);
            }
#pragma unroll
            for (int ntp = 0; ntp < 2; ntp++) {
                int m = lane >> 3;
                int row = nbase + ntp * 16 + ((m & 2) << 2) + (lane & 7);
                int kcs = kb * 2 + (m & 1);
                uint32_t so = swz64((uint32_t)(row * 64 + kcs * 16));
                uint32_t bh[4], bl[4];
                ldsm_x4(bh, stg + 16384u + so);
                ldsm_x4(bl, stg + 16384u + 4096u + so);
#pragma unroll
                for (int mt = 0; mt < 2; mt++) {
                    mma_bf16(acc[mt][2 * ntp],     ah[mt], bh);
                    mma_bf16(acc[mt][2 * ntp],     ah[mt], bl);
                    mma_bf16(acc[mt][2 * ntp],     al[mt], bh);
                    mma_bf16(acc[mt][2 * ntp + 1], ah[mt], bh + 2);
                    mma_bf16(acc[mt][2 * ntp + 1], ah[mt], bl + 2);
                    mma_bf16(acc[mt][2 * ntp + 1], al[mt], bh + 2);
                }
            }
        }
        __syncthreads();
    }
#pragma unroll
    for (int mt = 0; mt < 2; mt++) {
        int m0 = ocb + mbase + mt * 16 + (lane >> 2);
        float* d0 = g_rpart + ((size_t)((qs * BB + b) * OC + m0)) * SLOTS;
        float* d1 = d0 + 8 * SLOTS;
#pragma unroll
        for (int nt = 0; nt < 4; nt++) {
            int n = nbase + nt * 8 + (lane & 3) * 2;
            d0[n]     = acc[mt][nt][0];
            d0[n + 1] = acc[mt][nt][1];
            d1[n]     = acc[mt][nt][2];
            d1[n + 1] = acc[mt][nt][3];
        }
    }
}

// ================= K2c: combine + exact squash + final argmax ===============
#define K2C_SMEM (OC * SLOTS * 4 + NCAPS * SLOTS * 4 + SLOTS * 4)
__global__ __launch_bounds__(256) void k2c_pick(const float* __restrict__ cb) {
    extern __shared__ char smem[];
    float* v     = (float*)smem;
    float* sval  = (float*)(smem + OC * SLOTS * 4);
    int*   sl    = (int*)(smem + OC * SLOTS * 4 + NCAPS * SLOTS * 4);
    int b = blockIdx.x, tid = threadIdx.x;
    if (tid < SLOTS) sl[tid] = g_slots[b * SLOTS + tid];
    for (int idx = tid; idx < OC * SLOTS; idx += 256) {
        int oc = idx >> 6;
        float s = cb[oc];
#pragma unroll
        for (int qs = 0; qs < 4; qs++)
            s += g_rpart[((size_t)((qs * BB + b) * OC)) * SLOTS + idx];
        v[idx] = s;
    }
    __syncthreads();
    if (tid < SLOTS) {
        float mk[8];
#pragma unroll
        for (int k = 0; k < 8; k++) mk[k] = -INFINITY;
        for (int c = 0; c < CAPC; c++) {
            float vv[8]; float sq = 0.f;
#pragma unroll
            for (int k = 0; k < 8; k++) {
                vv[k] = v[(k * CAPC + c) * SLOTS + tid];
                sq += vv[k] * vv[k];
            }
            float sf = sq / ((1.f + sq) * sqrtf(sq + 1e-8f));
#pragma unroll
            for (int k = 0; k < 8; k++) mk[k] = fmaxf(mk[k], vv[k] * sf);
        }
#pragma unroll
        for (int k = 0; k < 8; k++) sval[k * SLOTS + tid] = mk[k];
    }
    __syncthreads();
    if (tid < NCAPS) {
        float best = -INFINITY; int bp = 0x7fffffff;
        for (int s = 0; s < SLOTS; s++) {
            float vv = sval[tid * SLOTS + s];
            int px = sl[s];
            if (vv > best || (vv == best && px < bp)) { best = vv; bp = px; }
        }
        g_idx[b * NCAPS + tid] = bp;
    }
}

// ================= K3, K6..K12 (exact path) =================================
__global__ void k3_norm() {
    int i = blockIdx.x * 256 + threadIdx.x;
    int b = i >> 10, hw = i & 1023;
    const float* p = g_x + (size_t)b * CC * HWW + hw;
    float s = 0.f;
    for (int c = 0; c < CC; c++) { float v = p[c * HWW]; s += v * v; }
    g_norm[i] = sqrtf(s);
}

__global__ void k6_smean() {
    int i = blockIdx.x * 256 + threadIdx.x;
    int c = i >> 3, k = i & 7;
    float s = 0.f;
    for (int b = 0; b < BB; b++) {
        int hw = g_idx[b * 8 + k];
        float n = fmaxf(g_norm[b * HWW + hw], 1e-12f);
        s += g_x[((size_t)(b * CC + c)) * HWW + hw] / n;
    }
    g_smean[c * 8 + k] = s * (1.f / 16.f);
}

__global__ __launch_bounds__(256) void k7_cm() {
    __shared__ float ss[CC * 8];
    for (int e = threadIdx.x; e < CC * 8; e += 256) ss[e] = g_smean[e];
    __syncthreads();
    int i = blockIdx.x * 256 + threadIdx.x;
    int b = i >> 10, hw = i & 1023;
    const float* xp = g_x + (size_t)b * CC * HWW + hw;
    float acc[8] = {};
    for (int c = 0; c < CC; c++) {
        float xv = xp[c * HWW];
#pragma unroll
        for (int k = 0; k < 8; k++) acc[k] += xv * ss[c * 8 + k];
    }
    float inv = 1.f / fmaxf(g_norm[i], 1e-12f);
#pragma unroll
    for (int k = 0; k < 8; k++) g_cm[(b * 8 + k) * HWW + hw] = acc[k] * inv;
}

__global__ void k8_minmax() {
    int bk = blockIdx.x;
    __shared__ float smn[256], smx[256];
    int tid = threadIdx.x;
    float mn = INFINITY, mx = -INFINITY;
    for (int hw = tid; hw < HWW; hw += 256) {
        float v = g_cm[bk * HWW + hw];
        mn = fminf(mn, v); mx = fmaxf(mx, v);
    }
    smn[tid] = mn; smx[tid] = mx;
    __syncthreads();
    for (int s = 128; s > 0; s >>= 1) {
        if (tid < s) {
            smn[tid] = fminf(smn[tid], smn[tid + s]);
            smx[tid] = fmaxf(smx[tid], smx[tid + s]);
        }
        __syncthreads();
    }
    if (tid == 0) { g_mm[bk * 2] = smn[0]; g_mm[bk * 2 + 1] = smx[0]; }
}

__global__ void k9_cmnorm() {
    int i = blockIdx.x * 256 + threadIdx.x;
    int b = i >> 10, hw = i & 1023;
    float s = 0.f;
#pragma unroll
    for (int k = 0; k < 8; k++) {
        int bk = b * 8 + k;
        float mn = g_mm[bk * 2], mx = g_mm[bk * 2 + 1];
        float v = (g_cm[bk * HWW + hw] - mn) / (mx - mn + 1e-12f);
        g_cm[bk * HWW + hw] = v;
        s += v;
    }
    g_cmmean[i] = s * 0.125f;
}

__global__ void k10_proto() {
    int c = blockIdx.x;
    float acc[8] = {};
    for (int i = threadIdx.x; i < BB * HWW; i += 256) {
        int b = i >> 10, hw = i & 1023;
        float xv = g_x[((size_t)(b * CC + c)) * HWW + hw];
#pragma unroll
        for (int k = 0; k < 8; k++) acc[k] += xv * g_cm[(b * 8 + k) * HWW + hw];
    }
    __shared__ float red[256];
    for (int k = 0; k < 8; k++) {
        red[threadIdx.x] = acc[k];
        __syncthreads();
        for (int s = 128; s > 0; s >>= 1) {
            if (threadIdx.x < s) red[threadIdx.x] += red[threadIdx.x + s];
            __syncthreads();
        }
        if (threadIdx.x == 0) g_proto[k * CC + c] = red[0] * (1.f / (BB * HWW));
        __syncthreads();
    }
}

__global__ void k11_pm(float* __restrict__ out) {
    int c = threadIdx.x;
    float s = 0.f;
#pragma unroll
    for (int k = 0; k < 8; k++) s += g_proto[k * CC + c];
    s *= 0.125f;
    g_pm[c] = s;
    __shared__ float red[512];
    red[c] = s * s;
    __syncthreads();
    for (int st = 256; st > 0; st >>= 1) {
        if (c < st) red[c] += red[c + st];
        __syncthreads();
    }
    float nrm = fmaxf(sqrtf(red[0]), 1e-12f);
    out[c] = s / nrm;
}

__global__ __launch_bounds__(256) void k12_out(float* __restrict__ out) {
    __shared__ float spm[CC];
    for (int e = threadIdx.x; e < CC; e += 256) spm[e] = g_pm[e];
    __syncthreads();
    int i = blockIdx.x * 256 + threadIdx.x;
    int b = i >> 10, hw = i & 1023;
    float cmm = g_cmmean[i];
    const float* xp = g_x + (size_t)b * CC * HWW + hw;
    float ss2 = 0.f;
    for (int c = 0; c < CC; c++) {
        float v = xp[c * HWW] * (spm[c] + cmm);
        ss2 += v * v;
    }
    float inv = 1.f / fmaxf(sqrtf(ss2), 1e-12f);
    float* op = out + CC + (size_t)b * CC * HWW + hw;
    for (int c = 0; c < CC; c++)
        op[c * HWW] = xp[c * HWW] * (spm[c] + cmm) * inv;
}

// ================= launcher ==================================================
extern "C" void kernel_launch(void* const* d_in, const int* in_sizes, int n_in,
                              void* d_out, int out_size) {
    const float* x5     = (const float*)d_in[0];
    const float* conv_w = (const float*)d_in[1];
    const float* conv_b = (const float*)d_in[2];
    const float* caps_w = (const float*)d_in[3];
    const float* caps_b = (const float*)d_in[4];
    float* out = (float*)d_out;
    (void)in_sizes; (void)n_in; (void)out_size;

    cudaFuncSetAttribute(k1_mma,      cudaFuncAttributeMaxDynamicSharedMemorySize, K1_SMEM);
    cudaFuncSetAttribute(k2a_mma,     cudaFuncAttributeMaxDynamicSharedMemorySize, K2A_SMEM);
    cudaFuncSetAttribute(k2b_rescore, cudaFuncAttributeMaxDynamicSharedMemorySize, K2B_SMEM);
    cudaFuncSetAttribute(k2c_pick,    cudaFuncAttributeMaxDynamicSharedMemorySize, K2C_SMEM);

    kp_w1   <<<1024, 256>>>(conv_w);
    kp5     <<<dim3(32, 16), 256>>>(x5);
    kp_w    <<<2048, 256>>>(caps_w);
    kp_xz   <<<6400, 256>>>();
    k1_mma  <<<dim3(4, 4, 16), 256, K1_SMEM>>>(x5, conv_b);
    kp_x    <<<dim3(32, 16), 256>>>();
    k2a_mma <<<dim3(4, 2, 16), 256, K2A_SMEM>>>(caps_b);
    k3_norm <<<64, 256>>>();
    k4_sqmax<<<64, 256>>>();
    k5_top8 <<<128, 256>>>();
    k2b_rescore<<<dim3(4, 2, 16), 256, K2B_SMEM>>>();
    k2c_pick<<<16, 256, K2C_SMEM>>>(caps_b);
    k6_smean<<<16, 256>>>();
    k7_cm   <<<64, 256>>>();
    k8_minmax<<<128, 256>>>();
    k9_cmnorm<<<64, 256>>>();
    k10_proto<<<512, 256>>>();
    k11_pm  <<<1, 512>>>(out);
    k12_out <<<64, 256>>>(out);
}

// round 10
// speedup vs baseline: 7.3022x; 1.2891x over previous
#include <cuda_runtime.h>
#include <cuda_bf16.h>
#include <math.h>
#include <stdint.h>

#define BB   16
#define CC   512
#define HWW  1024
#define NCAPS 8
#define CAPC 32
#define OC   256
#define TAPS 81
#define SLOTS 64
#define TOPK  8

// ================= helpers =================
__device__ __forceinline__ uint32_t smem_u32(const void* p) {
    uint32_t a;
    asm("{ .reg .u64 t; cvta.to.shared.u64 t, %1; cvt.u32.u64 %0, t; }" : "=r"(a) : "l"(p));
    return a;
}
#define CP_ASYNC16(dst, src) \
    asm volatile("cp.async.cg.shared.global [%0], [%1], 16;" :: "r"(dst), "l"(src) : "memory")
#define CP_COMMIT() asm volatile("cp.async.commit_group;" ::: "memory")
#define CP_WAIT0()  asm volatile("cp.async.wait_group 0;" ::: "memory")
#define CP_WAIT1()  asm volatile("cp.async.wait_group 1;" ::: "memory")

__device__ __forceinline__ void ldsm_x4(uint32_t* r, uint32_t addr) {
    asm volatile("ldmatrix.sync.aligned.m8n8.x4.shared.b16 {%0,%1,%2,%3}, [%4];"
                 : "=r"(r[0]), "=r"(r[1]), "=r"(r[2]), "=r"(r[3]) : "r"(addr));
}
__device__ __forceinline__ void mma_bf16(float* c, const uint32_t* a, const uint32_t* b) {
    asm volatile("mma.sync.aligned.m16n8k16.row.col.f32.bf16.bf16.f32 "
                 "{%0,%1,%2,%3}, {%4,%5,%6,%7}, {%8,%9}, {%0,%1,%2,%3};"
                 : "+f"(c[0]), "+f"(c[1]), "+f"(c[2]), "+f"(c[3])
                 : "r"(a[0]), "r"(a[1]), "r"(a[2]), "r"(a[3]), "r"(b[0]), "r"(b[1]));
}
__device__ __forceinline__ void mma_s8(int* c, const uint32_t* a, const uint32_t* b) {
    asm volatile("mma.sync.aligned.m16n8k32.row.col.s32.s8.s8.s32 "
                 "{%0,%1,%2,%3}, {%4,%5,%6,%7}, {%8,%9}, {%0,%1,%2,%3};"
                 : "+r"(c[0]), "+r"(c[1]), "+r"(c[2]), "+r"(c[3])
                 : "r"(a[0]), "r"(a[1]), "r"(a[2]), "r"(a[3]), "r"(b[0]), "r"(b[1]));
}
__device__ __forceinline__ uint32_t swz64(uint32_t o) { return o ^ ((o >> 3) & 0x70); }

// ================= scratch =================
__device__ __align__(128) float g_x[BB * CC * HWW];
__device__ __align__(128) float g_cap[(size_t)BB * OC * HWW];
__device__ float g_cap4[BB * NCAPS * HWW];
__device__ int   g_idx[BB * NCAPS];
__device__ int   g_slots[BB * SLOTS];
__device__ float g_rpart[4 * BB * OC * SLOTS];
__device__ float g_norm[BB * HWW];
__device__ float g_smean[CC * NCAPS];
__device__ float g_cm[BB * NCAPS * HWW];
__device__ float g_mm[BB * NCAPS * 2];
__device__ float g_cmmean[BB * HWW];
__device__ float g_proto[NCAPS * CC];
__device__ float g_pm[CC];
__device__ __align__(128) __nv_bfloat16 g_w_hi[TAPS * OC * CC];
__device__ __align__(128) __nv_bfloat16 g_w_lo[TAPS * OC * CC];
__device__ __align__(128) __nv_bfloat16 g_xp_hi[BB * 40 * 40 * CC];
__device__ __align__(128) __nv_bfloat16 g_xp_lo[BB * 40 * 40 * CC];
// int8 ranking operands + scales
__device__ __align__(128) int8_t g_w_s8[TAPS * OC * CC];
__device__ __align__(128) int8_t g_xp_s8[BB * 40 * 40 * CC];
__device__ unsigned int g_wmax_bits;   // zero-init; atomicMax of |w| bits (idempotent)
__device__ unsigned int g_xmax_bits;
// k1 operands
__device__ __align__(128) __nv_bfloat16 g_cw_hi[CC * CC];
__device__ __align__(128) __nv_bfloat16 g_cw_lo[CC * CC];
__device__ __align__(128) __nv_bfloat16 g_x5t_hi[BB * HWW * CC];
__device__ __align__(128) __nv_bfloat16 g_x5t_lo[BB * HWW * CC];

// ================= KP_W1: split conv_w into bf16 hi/lo ======================
__global__ void kp_w1(const float* __restrict__ w) {
    int i = blockIdx.x * 256 + threadIdx.x;
    float v = w[i];
    __nv_bfloat16 h = __float2bfloat16(v);
    g_cw_hi[i] = h;
    g_cw_lo[i] = __float2bfloat16(v - __bfloat162float(h));
}

// ================= KP5: transpose x5 -> pixel-major bf16 hi/lo ==============
__global__ __launch_bounds__(256) void kp5(const float* __restrict__ x5) {
    __shared__ float tile[32][33];
    int b = blockIdx.y, h = blockIdx.x;
    int tid = threadIdx.x;
    for (int c0 = 0; c0 < CC; c0 += 32) {
#pragma unroll
        for (int s = 0; s < 4; s++) {
            int cl = (tid >> 5) + s * 8, w = tid & 31;
            tile[cl][w] = x5[((size_t)(b * CC + c0 + cl)) * HWW + h * 32 + w];
        }
        __syncthreads();
#pragma unroll
        for (int s = 0; s < 4; s++) {
            int wl = (tid >> 5) + s * 8, ci = tid & 31;
            float v = tile[ci][wl];
            size_t dst = ((size_t)(b * HWW + h * 32 + wl)) * CC + c0 + ci;
            __nv_bfloat16 hh = __float2bfloat16(v);
            g_x5t_hi[dst] = hh;
            g_x5t_lo[dst] = __float2bfloat16(v - __bfloat162float(hh));
        }
        __syncthreads();
    }
}

// ================= K1: split-bf16 mma: x = W@x5 + b + x5 ====================
#define K1_STG 49152u
#define K1_SMEM 98304
__global__ __launch_bounds__(256, 1) void k1_mma(const float* __restrict__ x5,
                                                 const float* __restrict__ bias) {
    extern __shared__ char smem[];
    uint32_t sb = smem_u32(smem);
    int tid = threadIdx.x, wid = tid >> 5, lane = tid & 31;
    int pix0 = blockIdx.x * 256;
    int ocb  = blockIdx.y * 128;
    int b    = blockIdx.z;
    int mbase = (wid >> 2) * 64;
    int nbase = (wid & 3) * 64;

    float acc[4][8][4];
#pragma unroll
    for (int mt = 0; mt < 4; mt++)
#pragma unroll
        for (int nt = 0; nt < 8; nt++)
#pragma unroll
            for (int j = 0; j < 4; j++) acc[mt][nt][j] = 0.f;

    auto issue = [&](int kch, int s) {
        uint32_t stg = sb + (uint32_t)s * K1_STG;
#pragma unroll
        for (int p = 0; p < 4; p++) {
            int e = tid + p * 256;
            int plane = e >> 9, r = (e >> 2) & 127, kc = e & 3;
            size_t gsrc = (size_t)(ocb + r) * CC + kch * 32 + kc * 8;
            const __nv_bfloat16* src = (plane ? g_cw_lo : g_cw_hi) + gsrc;
            CP_ASYNC16(stg + (uint32_t)plane * 8192u + swz64((uint32_t)(r * 64 + kc * 16)),
                       (const void*)src);
        }
#pragma unroll
        for (int p = 0; p < 8; p++) {
            int e = tid + p * 256;
            int plane = e >> 10, row = (e >> 2) & 255, kc = e & 3;
            size_t gsrc = ((size_t)(b * HWW + pix0 + row)) * CC + kch * 32 + kc * 8;
            const __nv_bfloat16* src = (plane ? g_x5t_lo : g_x5t_hi) + gsrc;
            CP_ASYNC16(stg + 16384u + (uint32_t)plane * 16384u + swz64((uint32_t)(row * 64 + kc * 16)),
                       (const void*)src);
        }
    };

    issue(0, 0);
    CP_COMMIT();
    for (int kch = 0; kch < 16; kch++) {
        int s = kch & 1;
        if (kch + 1 < 16) issue(kch + 1, s ^ 1);
        CP_COMMIT();
        CP_WAIT1();
        __syncthreads();
        uint32_t stg = sb + (uint32_t)s * K1_STG;
#pragma unroll
        for (int kb = 0; kb < 2; kb++) {
            uint32_t ah[4][4], al[4][4];
#pragma unroll
            for (int mt = 0; mt < 4; mt++) {
                int arow = mbase + mt * 16 + (lane & 15);
                int kcs = kb * 2 + (lane >> 4);
                uint32_t so = swz64((uint32_t)(arow * 64 + kcs * 16));
                ldsm_x4(ah[mt], stg + so);
                ldsm_x4(al[mt], stg + 8192u + so);
            }
#pragma unroll
            for (int ntp = 0; ntp < 4; ntp++) {
                int m = lane >> 3;
                int row = nbase + ntp * 16 + ((m & 2) << 2) + (lane & 7);
                int kcs = kb * 2 + (m & 1);
                uint32_t so = swz64((uint32_t)(row * 64 + kcs * 16));
                uint32_t bh[4], bl[4];
                ldsm_x4(bh, stg + 16384u + so);
                ldsm_x4(bl, stg + 32768u + so);
#pragma unroll
                for (int mt = 0; mt < 4; mt++) {
                    mma_bf16(acc[mt][2 * ntp],     ah[mt], bh);
                    mma_bf16(acc[mt][2 * ntp],     ah[mt], bl);
                    mma_bf16(acc[mt][2 * ntp],     al[mt], bh);
                    mma_bf16(acc[mt][2 * ntp + 1], ah[mt], bh + 2);
                    mma_bf16(acc[mt][2 * ntp + 1], ah[mt], bl + 2);
                    mma_bf16(acc[mt][2 * ntp + 1], al[mt], bh + 2);
                }
            }
        }
        __syncthreads();
    }
#pragma unroll
    for (int mt = 0; mt < 4; mt++) {
        int m0 = ocb + mbase + mt * 16 + (lane >> 2);
        float bi0 = bias[m0], bi1 = bias[m0 + 8];
        size_t base0 = ((size_t)(b * CC + m0)) * HWW + pix0;
        size_t base1 = ((size_t)(b * CC + m0 + 8)) * HWW + pix0;
#pragma unroll
        for (int nt = 0; nt < 8; nt++) {
            int n = nbase + nt * 8 + (lane & 3) * 2;
            g_x[base0 + n]     = acc[mt][nt][0] + bi0 + x5[base0 + n];
            g_x[base0 + n + 1] = acc[mt][nt][1] + bi0 + x5[base0 + n + 1];
            g_x[base1 + n]     = acc[mt][nt][2] + bi1 + x5[base1 + n];
            g_x[base1 + n + 1] = acc[mt][nt][3] + bi1 + x5[base1 + n + 1];
        }
    }
}

// ================= KPW: transpose caps_w -> bf16 hi/lo + max|w| =============
__global__ __launch_bounds__(256) void kp_w(const float* __restrict__ cw) {
    __shared__ float tile[64 * 81];
    __shared__ float red[256];
    int o  = blockIdx.x >> 3;
    int c0 = (blockIdx.x & 7) * 64;
    int tid = threadIdx.x;
    for (int e = tid; e < 64 * 81; e += 256) {
        int c_l = e / 81, t = e - c_l * 81;
        tile[e] = cw[((size_t)o * CC + c0 + c_l) * TAPS + t];
    }
    __syncthreads();
    float amax = 0.f;
    for (int e = tid; e < 81 * 64; e += 256) {
        int t = e >> 6, c_l = e & 63;
        float v = tile[c_l * 81 + t];
        amax = fmaxf(amax, fabsf(v));
        __nv_bfloat16 h = __float2bfloat16(v);
        size_t di = ((size_t)(t * OC + o)) * CC + c0 + c_l;
        g_w_hi[di] = h;
        g_w_lo[di] = __float2bfloat16(v - __bfloat162float(h));
    }
    red[tid] = amax;
    __syncthreads();
    for (int s = 128; s > 0; s >>= 1) {
        if (tid < s) red[tid] = fmaxf(red[tid], red[tid + s]);
        __syncthreads();
    }
    if (tid == 0) atomicMax(&g_wmax_bits, __float_as_uint(red[0]));
}

// ================= KP_WQ: quantize weights to int8 ==========================
__global__ void kp_wq() {
    float qi = 127.f / __uint_as_float(g_wmax_bits);
    int i = blockIdx.x * 256 + threadIdx.x;   // 8 elems each; 1327104 total
    uint4 h = ((const uint4*)g_w_hi)[i];
    uint4 l = ((const uint4*)g_w_lo)[i];
    const __nv_bfloat16* hp = (const __nv_bfloat16*)&h;
    const __nv_bfloat16* lp = (const __nv_bfloat16*)&l;
    char r[8];
#pragma unroll
    for (int j = 0; j < 8; j++) {
        float v = __bfloat162float(hp[j]) + __bfloat162float(lp[j]);
        int q = __float2int_rn(v * qi);
        q = max(-127, min(127, q));
        r[j] = (char)q;
    }
    ((uint2*)g_w_s8)[i] = *(uint2*)r;
}

// ================= KPZ: zero padded x planes (bf16 + int8) ==================
__global__ void kp_xz() {
    int i = blockIdx.x * 256 + threadIdx.x;   // 1,638,400
    uint4 z = {0, 0, 0, 0};
    ((uint4*)g_xp_hi)[i] = z;
    ((uint4*)g_xp_lo)[i] = z;
    if (i < 819200) ((uint4*)g_xp_s8)[i] = z;
}

// ================= KPX: transpose g_x -> padded bf16 hi/lo + max|x| =========
__global__ __launch_bounds__(256) void kp_x() {
    __shared__ float tile[32][33];
    __shared__ float red[256];
    int b = blockIdx.y, h = blockIdx.x;
    int tid = threadIdx.x;
    float amax = 0.f;
    for (int c0 = 0; c0 < CC; c0 += 32) {
#pragma unroll
        for (int s = 0; s < 4; s++) {
            int cl = (tid >> 5) + s * 8, w = tid & 31;
            tile[cl][w] = g_x[((size_t)(b * CC + c0 + cl)) * HWW + h * 32 + w];
        }
        __syncthreads();
#pragma unroll
        for (int s = 0; s < 4; s++) {
            int wl = (tid >> 5) + s * 8, ci = tid & 31;
            float v = tile[ci][wl];
            amax = fmaxf(amax, fabsf(v));
            size_t dst = ((size_t)((b * 40 + h + 4) * 40 + wl + 4)) * CC + c0 + ci;
            __nv_bfloat16 hh = __float2bfloat16(v);
            g_xp_hi[dst] = hh;
            g_xp_lo[dst] = __float2bfloat16(v - __bfloat162float(hh));
        }
        __syncthreads();
    }
    red[tid] = amax;
    __syncthreads();
    for (int s = 128; s > 0; s >>= 1) {
        if (tid < s) red[tid] = fmaxf(red[tid], red[tid + s]);
        __syncthreads();
    }
    if (tid == 0) atomicMax(&g_xmax_bits, __float_as_uint(red[0]));
}

// ================= KP_XQ: quantize interior x pixels to int8 ================
__global__ void kp_xq() {
    float qi = 127.f / __uint_as_float(g_xmax_bits);
    int i = blockIdx.x * 256 + threadIdx.x;   // 1,048,576 chunks of 8 ci
    int cig = i & 63;
    int pix = i >> 6;
    int b = pix >> 10, hw = pix & 1023;
    size_t row = ((size_t)((b * 40 + (hw >> 5) + 4) * 40 + (hw & 31) + 4)) * CC + cig * 8;
    uint4 h = *(const uint4*)(g_xp_hi + row);
    uint4 l = *(const uint4*)(g_xp_lo + row);
    const __nv_bfloat16* hp = (const __nv_bfloat16*)&h;
    const __nv_bfloat16* lp = (const __nv_bfloat16*)&l;
    char r[8];
#pragma unroll
    for (int j = 0; j < 8; j++) {
        float v = __bfloat162float(hp[j]) + __bfloat162float(lp[j]);
        int q = __float2int_rn(v * qi);
        q = max(-127, min(127, q));
        r[j] = (char)q;
    }
    *(uint2*)(g_xp_s8 + row) = *(uint2*)r;
}

// ================= K2a: int8 ranking conv (approx) ==========================
// smem: B slab 2 planes x 10240 = 20480; A 3 stages x (2 planes x 2048) = 12288
#define S8_BSLAB 0u
#define S8_BSTR  10240u
#define S8_A     20480u
#define K2A_SMEM 32768
__global__ __launch_bounds__(256, 1) void k2a_s8(const float* __restrict__ cb) {
    extern __shared__ char smem[];
    uint32_t sb = smem_u32(smem);
    int tid = threadIdx.x, wid = tid >> 5, lane = tid & 31;
    int bh8  = blockIdx.x * 8;
    int pix0 = blockIdx.x * 256;
    int ocb  = blockIdx.y * 128;
    int b    = blockIdx.z;
    int mbase = (wid >> 2) * 64;
    int nbase = (wid & 3) * 64;

    int acc[4][8][4];
#pragma unroll
    for (int mt = 0; mt < 4; mt++)
#pragma unroll
        for (int nt = 0; nt < 8; nt++)
#pragma unroll
            for (int j = 0; j < 4; j++) acc[mt][nt][j] = 0;

    for (int q = 0; q < 16; q++) {
        __syncthreads();
        // B slab: 640 px x 32B (2 chunk planes)
        for (int e = tid; e < 1280; e += 256) {
            int px = e >> 1, kc = e & 1;
            int pr = px / 40, pc = px - pr * 40;
            const int8_t* src = g_xp_s8 +
                ((size_t)((b * 40 + bh8 + pr) * 40 + pc)) * CC + q * 32 + kc * 16;
            CP_ASYNC16(sb + S8_BSLAB + (uint32_t)kc * S8_BSTR + (uint32_t)px * 16u,
                       (const void*)src);
        }
        CP_COMMIT();
        // prime A stages 0,1
#pragma unroll
        for (int t0 = 0; t0 < 2; t0++) {
            int r = tid >> 1, kc = tid & 1;
            const int8_t* src = g_w_s8 + ((size_t)(t0 * OC + ocb + r)) * CC + q * 32 + kc * 16;
            CP_ASYNC16(sb + S8_A + (uint32_t)t0 * 4096u + (uint32_t)kc * 2048u + (uint32_t)r * 16u,
                       (const void*)src);
            CP_COMMIT();
        }
        CP_WAIT0();
        __syncthreads();

        for (int tap = 0; tap < TAPS; tap++) {
            int st = tap - (tap / 3) * 3;
            int dy = tap / 9, dx = tap - dy * 9;
            CP_WAIT1();
            __syncthreads();
            if (tap + 2 < TAPS) {
                int tnx = tap + 2;
                int stn = tnx - (tnx / 3) * 3;
                int r = tid >> 1, kc = tid & 1;
                const int8_t* src = g_w_s8 + ((size_t)(tnx * OC + ocb + r)) * CC + q * 32 + kc * 16;
                CP_ASYNC16(sb + S8_A + (uint32_t)stn * 4096u + (uint32_t)kc * 2048u + (uint32_t)r * 16u,
                           (const void*)src);
            }
            CP_COMMIT();
            uint32_t abase = sb + S8_A + (uint32_t)st * 4096u;
            uint32_t a[4][4];
#pragma unroll
            for (int mt = 0; mt < 4; mt++) {
                int arow = mbase + mt * 16 + (lane & 15);
                int kcs = lane >> 4;
                ldsm_x4(a[mt], abase + (uint32_t)kcs * 2048u + (uint32_t)arow * 16u);
            }
#pragma unroll
            for (int ntp = 0; ntp < 4; ntp++) {
                int m = lane >> 3;
                int n_ = nbase + ntp * 16 + ((m & 2) << 2) + (lane & 7);
                int hl = n_ >> 5, w = n_ & 31;
                int kcs = m & 1;
                int px = (hl + dy) * 40 + (w + dx);
                uint32_t bq[4];
                ldsm_x4(bq, sb + S8_BSLAB + (uint32_t)kcs * S8_BSTR + (uint32_t)px * 16u);
#pragma unroll
                for (int mt = 0; mt < 4; mt++) {
                    mma_s8(acc[mt][2 * ntp],     a[mt], bq);
                    mma_s8(acc[mt][2 * ntp + 1], a[mt], bq + 2);
                }
            }
        }
    }
    float s = (__uint_as_float(g_wmax_bits) * (1.f / 127.f)) *
              (__uint_as_float(g_xmax_bits) * (1.f / 127.f));
#pragma unroll
    for (int mt = 0; mt < 4; mt++) {
        int m0 = ocb + mbase + mt * 16 + (lane >> 2);
        float bi0 = cb[m0], bi1 = cb[m0 + 8];
        float* d0 = g_cap + ((size_t)(b * OC + m0)) * HWW + pix0;
        float* d1 = g_cap + ((size_t)(b * OC + m0 + 8)) * HWW + pix0;
#pragma unroll
        for (int nt = 0; nt < 8; nt++) {
            int n = nbase + nt * 8 + (lane & 3) * 2;
            d0[n]     = (float)acc[mt][nt][0] * s + bi0;
            d0[n + 1] = (float)acc[mt][nt][1] * s + bi0;
            d1[n]     = (float)acc[mt][nt][2] * s + bi1;
            d1[n + 1] = (float)acc[mt][nt][3] * s + bi1;
        }
    }
}

// ================= K4: squash + max over CAP_C (approx values) ==============
__global__ void k4_sqmax() {
    int i = blockIdx.x * 256 + threadIdx.x;
    int b = i >> 10, hw = i & 1023;
    const float* cp = g_cap + (size_t)b * OC * HWW + hw;
    float m[8];
#pragma unroll
    for (int k = 0; k < 8; k++) m[k] = -INFINITY;
    for (int c = 0; c < CAPC; c++) {
        float v[8]; float sq = 0.f;
#pragma unroll
        for (int k = 0; k < 8; k++) { v[k] = cp[(size_t)(k * CAPC + c) * HWW]; sq += v[k] * v[k]; }
        float s = sq / ((1.f + sq) * sqrtf(sq + 1e-8f));
#pragma unroll
        for (int k = 0; k < 8; k++) m[k] = fmaxf(m[k], v[k] * s);
    }
#pragma unroll
    for (int k = 0; k < 8; k++) g_cap4[(b * 8 + k) * HWW + hw] = m[k];
}

// ================= K5: top-8 candidate pixels per (b,k) =====================
__global__ void k5_top8() {
    int bk = blockIdx.x;
    int b = bk >> 3, k = bk & 7;
    __shared__ float val[1024];
    __shared__ float sv[256];
    __shared__ int   si[256];
    int tid = threadIdx.x;
    for (int hw = tid; hw < HWW; hw += 256) val[hw] = g_cap4[bk * HWW + hw];
    __syncthreads();
    for (int j = 0; j < TOPK; j++) {
        float best = -INFINITY; int bi = 0x7fffffff;
        for (int hw = tid; hw < HWW; hw += 256) {
            float v = val[hw];
            if (v > best || (v == best && hw < bi)) { best = v; bi = hw; }
        }
        sv[tid] = best; si[tid] = bi;
        __syncthreads();
        for (int s = 128; s > 0; s >>= 1) {
            if (tid < s) {
                if (sv[tid + s] > sv[tid] ||
                    (sv[tid + s] == sv[tid] && si[tid + s] < si[tid])) {
                    sv[tid] = sv[tid + s]; si[tid] = si[tid + s];
                }
            }
            __syncthreads();
        }
        if (tid == 0) {
            g_slots[b * SLOTS + k * TOPK + j] = si[0];
            val[si[0]] = -INFINITY;
        }
        __syncthreads();
    }
}

// ================= K2b: 3-term exact rescore at candidate pixels ============
#define RB_STG 24576u
#define K2B_SMEM 49664
__global__ __launch_bounds__(256, 1) void k2b_rescore() {
    extern __shared__ char smem[];
    uint32_t sb = smem_u32(smem);
    int* s_slots = (int*)(smem + 49152);
    int tid = threadIdx.x, wid = tid >> 5, lane = tid & 31;
    int qs  = blockIdx.x;
    int ocb = blockIdx.y * 128;
    int b   = blockIdx.z;
    int mbase = (wid >> 1) * 32;
    int nbase = (wid & 1) * 32;

    if (tid < SLOTS) s_slots[tid] = g_slots[b * SLOTS + tid];
    __syncthreads();

    float acc[2][4][4];
#pragma unroll
    for (int mt = 0; mt < 2; mt++)
#pragma unroll
        for (int nt = 0; nt < 4; nt++)
#pragma unroll
            for (int j = 0; j < 4; j++) acc[mt][nt][j] = 0.f;

    auto issue = [&](int it, int s) {
        int q = qs * 4 + it / 81;
        int tap = it - (it / 81) * 81;
        int dy = tap / 9, dx = tap - dy * 9;
        uint32_t stg = sb + (uint32_t)s * RB_STG;
#pragma unroll
        for (int p = 0; p < 4; p++) {
            int e = tid + p * 256;
            int plane = e >> 9, r = (e >> 2) & 127, kc = e & 3;
            size_t gsrc = ((size_t)(tap * OC + ocb + r)) * CC + q * 32 + kc * 8;
            const __nv_bfloat16* src = (plane ? g_w_lo : g_w_hi) + gsrc;
            CP_ASYNC16(stg + (uint32_t)plane * 8192u + swz64((uint32_t)(r * 64 + kc * 16)),
                       (const void*)src);
        }
#pragma unroll
        for (int p = 0; p < 2; p++) {
            int e = tid + p * 256;
            int plane = (e >> 8) & 1, row = (e >> 2) & 63, kc = e & 3;
            int pix = s_slots[row];
            int y = pix >> 5, x = pix & 31;
            size_t gsrc = ((size_t)((b * 40 + y + dy) * 40 + (x + dx))) * CC + q * 32 + kc * 8;
            const __nv_bfloat16* src = (plane ? g_xp_lo : g_xp_hi) + gsrc;
            CP_ASYNC16(stg + 16384u + (uint32_t)plane * 4096u + swz64((uint32_t)(row * 64 + kc * 16)),
                       (const void*)src);
        }
    };

    issue(0, 0);
    CP_COMMIT();
    const int NIT = 4 * TAPS;
    for (int it = 0; it < NIT; it++) {
        int s = it & 1;
        if (it + 1 < NIT) issue(it + 1, s ^ 1);
        CP_COMMIT();
        CP_WAIT1();
        __syncthreads();
        uint32_t stg = sb + (uint32_t)s * RB_STG;
#pragma unroll
        for (int kb = 0; kb < 2; kb++) {
            uint32_t ah[2][4], al[2][4];
#pragma unroll
            for (int mt = 0; mt < 2; mt++) {
                int arow = mbase + mt * 16 + (lane & 15);
                int kcs = kb * 2 + (lane >> 4);
                uint32_t so = swz64((uint32_t)(arow * 64 + kcs * 16));
                ldsm_x4(ah[mt], stg + so);
                ldsm_x4(al[mt], stg + 8192u + so);
            }
#pragma unroll
            for (int ntp = 0; ntp < 2; ntp++) {
                int m = lane >> 3;
                int row = nbase + ntp * 16 + ((m & 2) << 2) + (lane & 7);
                int kcs = kb * 2 + (m & 1);
                uint32_t so = swz64((uint32_t)(row * 64 + kcs * 16));
                uint32_t bh[4], bl[4];
                ldsm_x4(bh, stg + 16384u + so);
                ldsm_x4(bl, stg + 16384u + 4096u + so);
#pragma unroll
                for (int mt = 0; mt < 2; mt++) {
                    mma_bf16(acc[mt][2 * ntp],     ah[mt], bh);
                    mma_bf16(acc[mt][2 * ntp],     ah[mt], bl);
                    mma_bf16(acc[mt][2 * ntp],     al[mt], bh);
                    mma_bf16(acc[mt][2 * ntp + 1], ah[mt], bh + 2);
                    mma_bf16(acc[mt][2 * ntp + 1], ah[mt], bl + 2);
                    mma_bf16(acc[mt][2 * ntp + 1], al[mt], bh + 2);
                }
            }
        }
        __syncthreads();
    }
#pragma unroll
    for (int mt = 0; mt < 2; mt++) {
        int m0 = ocb + mbase + mt * 16 + (lane >> 2);
        float* d0 = g_rpart + ((size_t)((qs * BB + b) * OC + m0)) * SLOTS;
        float* d1 = d0 + 8 * SLOTS;
#pragma unroll
        for (int nt = 0; nt < 4; nt++) {
            int n = nbase + nt * 8 + (lane & 3) * 2;
            d0[n]     = acc[mt][nt][0];
            d0[n + 1] = acc[mt][nt][1];
            d1[n]     = acc[mt][nt][2];
            d1[n + 1] = acc[mt][nt][3];
        }
    }
}

// ================= K2c: combine + exact squash + final argmax ===============
#define K2C_SMEM (OC * SLOTS * 4 + NCAPS * SLOTS * 4 + SLOTS * 4)
__global__ __launch_bounds__(256) void k2c_pick(const float* __restrict__ cb) {
    extern __shared__ char smem[];
    float* v     = (float*)smem;
    float* sval  = (float*)(smem + OC * SLOTS * 4);
    int*   sl    = (int*)(smem + OC * SLOTS * 4 + NCAPS * SLOTS * 4);
    int b = blockIdx.x, tid = threadIdx.x;
    if (tid < SLOTS) sl[tid] = g_slots[b * SLOTS + tid];
    for (int idx = tid; idx < OC * SLOTS; idx += 256) {
        int oc = idx >> 6;
        float s = cb[oc];
#pragma unroll
        for (int qs = 0; qs < 4; qs++)
            s += g_rpart[((size_t)((qs * BB + b) * OC)) * SLOTS + idx];
        v[idx] = s;
    }
    __syncthreads();
    if (tid < SLOTS) {
        float mk[8];
#pragma unroll
        for (int k = 0; k < 8; k++) mk[k] = -INFINITY;
        for (int c = 0; c < CAPC; c++) {
            float vv[8]; float sq = 0.f;
#pragma unroll
            for (int k = 0; k < 8; k++) {
                vv[k] = v[(k * CAPC + c) * SLOTS + tid];
                sq += vv[k] * vv[k];
            }
            float sf = sq / ((1.f + sq) * sqrtf(sq + 1e-8f));
#pragma unroll
            for (int k = 0; k < 8; k++) mk[k] = fmaxf(mk[k], vv[k] * sf);
        }
#pragma unroll
        for (int k = 0; k < 8; k++) sval[k * SLOTS + tid] = mk[k];
    }
    __syncthreads();
    if (tid < NCAPS) {
        float best = -INFINITY; int bp = 0x7fffffff;
        for (int s = 0; s < SLOTS; s++) {
            float vv = sval[tid * SLOTS + s];
            int px = sl[s];
            if (vv > best || (vv == best && px < bp)) { best = vv; bp = px; }
        }
        g_idx[b * NCAPS + tid] = bp;
    }
}

// ================= K3, K6..K12 (exact path) =================================
__global__ void k3_norm() {
    int i = blockIdx.x * 256 + threadIdx.x;
    int b = i >> 10, hw = i & 1023;
    const float* p = g_x + (size_t)b * CC * HWW + hw;
    float s = 0.f;
    for (int c = 0; c < CC; c++) { float v = p[c * HWW]; s += v * v; }
    g_norm[i] = sqrtf(s);
}

__global__ void k6_smean() {
    int i = blockIdx.x * 256 + threadIdx.x;
    int c = i >> 3, k = i & 7;
    float s = 0.f;
    for (int b = 0; b < BB; b++) {
        int hw = g_idx[b * 8 + k];
        float n = fmaxf(g_norm[b * HWW + hw], 1e-12f);
        s += g_x[((size_t)(b * CC + c)) * HWW + hw] / n;
    }
    g_smean[c * 8 + k] = s * (1.f / 16.f);
}

__global__ __launch_bounds__(256) void k7_cm() {
    __shared__ float ss[CC * 8];
    for (int e = threadIdx.x; e < CC * 8; e += 256) ss[e] = g_smean[e];
    __syncthreads();
    int i = blockIdx.x * 256 + threadIdx.x;
    int b = i >> 10, hw = i & 1023;
    const float* xp = g_x + (size_t)b * CC * HWW + hw;
    float acc[8] = {};
    for (int c = 0; c < CC; c++) {
        float xv = xp[c * HWW];
#pragma unroll
        for (int k = 0; k < 8; k++) acc[k] += xv * ss[c * 8 + k];
    }
    float inv = 1.f / fmaxf(g_norm[i], 1e-12f);
#pragma unroll
    for (int k = 0; k < 8; k++) g_cm[(b * 8 + k) * HWW + hw] = acc[k] * inv;
}

__global__ void k8_minmax() {
    int bk = blockIdx.x;
    __shared__ float smn[256], smx[256];
    int tid = threadIdx.x;
    float mn = INFINITY, mx = -INFINITY;
    for (int hw = tid; hw < HWW; hw += 256) {
        float v = g_cm[bk * HWW + hw];
        mn = fminf(mn, v); mx = fmaxf(mx, v);
    }
    smn[tid] = mn; smx[tid] = mx;
    __syncthreads();
    for (int s = 128; s > 0; s >>= 1) {
        if (tid < s) {
            smn[tid] = fminf(smn[tid], smn[tid + s]);
            smx[tid] = fmaxf(smx[tid], smx[tid + s]);
        }
        __syncthreads();
    }
    if (tid == 0) { g_mm[bk * 2] = smn[0]; g_mm[bk * 2 + 1] = smx[0]; }
}

__global__ void k9_cmnorm() {
    int i = blockIdx.x * 256 + threadIdx.x;
    int b = i >> 10, hw = i & 1023;
    float s = 0.f;
#pragma unroll
    for (int k = 0; k < 8; k++) {
        int bk = b * 8 + k;
        float mn = g_mm[bk * 2], mx = g_mm[bk * 2 + 1];
        float v = (g_cm[bk * HWW + hw] - mn) / (mx - mn + 1e-12f);
        g_cm[bk * HWW + hw] = v;
        s += v;
    }
    g_cmmean[i] = s * 0.125f;
}

__global__ void k10_proto() {
    int c = blockIdx.x;
    float acc[8] = {};
    for (int i = threadIdx.x; i < BB * HWW; i += 256) {
        int b = i >> 10, hw = i & 1023;
        float xv = g_x[((size_t)(b * CC + c)) * HWW + hw];
#pragma unroll
        for (int k = 0; k < 8; k++) acc[k] += xv * g_cm[(b * 8 + k) * HWW + hw];
    }
    __shared__ float red[256];
    for (int k = 0; k < 8; k++) {
        red[threadIdx.x] = acc[k];
        __syncthreads();
        for (int s = 128; s > 0; s >>= 1) {
            if (threadIdx.x < s) red[threadIdx.x] += red[threadIdx.x + s];
            __syncthreads();
        }
        if (threadIdx.x == 0) g_proto[k * CC + c] = red[0] * (1.f / (BB * HWW));
        __syncthreads();
    }
}

__global__ void k11_pm(float* __restrict__ out) {
    int c = threadIdx.x;
    float s = 0.f;
#pragma unroll
    for (int k = 0; k < 8; k++) s += g_proto[k * CC + c];
    s *= 0.125f;
    g_pm[c] = s;
    __shared__ float red[512];
    red[c] = s * s;
    __syncthreads();
    for (int st = 256; st > 0; st >>= 1) {
        if (c < st) red[c] += red[c + st];
        __syncthreads();
    }
    float nrm = fmaxf(sqrtf(red[0]), 1e-12f);
    out[c] = s / nrm;
}

__global__ __launch_bounds__(256) void k12_out(float* __restrict__ out) {
    __shared__ float spm[CC];
    for (int e = threadIdx.x; e < CC; e += 256) spm[e] = g_pm[e];
    __syncthreads();
    int i = blockIdx.x * 256 + threadIdx.x;
    int b = i >> 10, hw = i & 1023;
    float cmm = g_cmmean[i];
    const float* xp = g_x + (size_t)b * CC * HWW + hw;
    float ss2 = 0.f;
    for (int c = 0; c < CC; c++) {
        float v = xp[c * HWW] * (spm[c] + cmm);
        ss2 += v * v;
    }
    float inv = 1.f / fmaxf(sqrtf(ss2), 1e-12f);
    float* op = out + CC + (size_t)b * CC * HWW + hw;
    for (int c = 0; c < CC; c++)
        op[c * HWW] = xp[c * HWW] * (spm[c] + cmm) * inv;
}

// ================= launcher ==================================================
extern "C" void kernel_launch(void* const* d_in, const int* in_sizes, int n_in,
                              void* d_out, int out_size) {
    const float* x5     = (const float*)d_in[0];
    const float* conv_w = (const float*)d_in[1];
    const float* conv_b = (const float*)d_in[2];
    const float* caps_w = (const float*)d_in[3];
    const float* caps_b = (const float*)d_in[4];
    float* out = (float*)d_out;
    (void)in_sizes; (void)n_in; (void)out_size;

    cudaFuncSetAttribute(k1_mma,      cudaFuncAttributeMaxDynamicSharedMemorySize, K1_SMEM);
    cudaFuncSetAttribute(k2a_s8,      cudaFuncAttributeMaxDynamicSharedMemorySize, K2A_SMEM);
    cudaFuncSetAttribute(k2b_rescore, cudaFuncAttributeMaxDynamicSharedMemorySize, K2B_SMEM);
    cudaFuncSetAttribute(k2c_pick,    cudaFuncAttributeMaxDynamicSharedMemorySize, K2C_SMEM);

    kp_w1   <<<1024, 256>>>(conv_w);
    kp5     <<<dim3(32, 16), 256>>>(x5);
    kp_w    <<<2048, 256>>>(caps_w);
    kp_wq   <<<5184, 256>>>();
    kp_xz   <<<6400, 256>>>();
    k1_mma  <<<dim3(4, 4, 16), 256, K1_SMEM>>>(x5, conv_b);
    kp_x    <<<dim3(32, 16), 256>>>();
    kp_xq   <<<4096, 256>>>();
    k2a_s8  <<<dim3(4, 2, 16), 256, K2A_SMEM>>>(caps_b);
    k3_norm <<<64, 256>>>();
    k4_sqmax<<<64, 256>>>();
    k5_top8 <<<128, 256>>>();
    k2b_rescore<<<dim3(4, 2, 16), 256, K2B_SMEM>>>();
    k2c_pick<<<16, 256, K2C_SMEM>>>(caps_b);
    k6_smean<<<16, 256>>>();
    k7_cm   <<<64, 256>>>();
    k8_minmax<<<128, 256>>>();
    k9_cmnorm<<<64, 256>>>();
    k10_proto<<<512, 256>>>();
    k11_pm  <<<1, 512>>>(out);
    k12_out <<<64, 256>>>(out);
}

// round 11
// speedup vs baseline: 7.4154x; 1.0155x over previous
#include <cuda_runtime.h>
#include <cuda_bf16.h>
#include <math.h>
#include <stdint.h>

#define BB   16
#define CC   512
#define HWW  1024
#define NCAPS 8
#define CAPC 32
#define OC   256
#define TAPS 81
#define SLOTS 64
#define TOPK  8
#define KSPLIT 8

// ================= helpers =================
__device__ __forceinline__ uint32_t smem_u32(const void* p) {
    uint32_t a;
    asm("{ .reg .u64 t; cvta.to.shared.u64 t, %1; cvt.u32.u64 %0, t; }" : "=r"(a) : "l"(p));
    return a;
}
#define CP_ASYNC16(dst, src) \
    asm volatile("cp.async.cg.shared.global [%0], [%1], 16;" :: "r"(dst), "l"(src) : "memory")
#define CP_COMMIT() asm volatile("cp.async.commit_group;" ::: "memory")
#define CP_WAIT0()  asm volatile("cp.async.wait_group 0;" ::: "memory")
#define CP_WAIT1()  asm volatile("cp.async.wait_group 1;" ::: "memory")

__device__ __forceinline__ void ldsm_x4(uint32_t* r, uint32_t addr) {
    asm volatile("ldmatrix.sync.aligned.m8n8.x4.shared.b16 {%0,%1,%2,%3}, [%4];"
                 : "=r"(r[0]), "=r"(r[1]), "=r"(r[2]), "=r"(r[3]) : "r"(addr));
}
__device__ __forceinline__ void mma_bf16(float* c, const uint32_t* a, const uint32_t* b) {
    asm volatile("mma.sync.aligned.m16n8k16.row.col.f32.bf16.bf16.f32 "
                 "{%0,%1,%2,%3}, {%4,%5,%6,%7}, {%8,%9}, {%0,%1,%2,%3};"
                 : "+f"(c[0]), "+f"(c[1]), "+f"(c[2]), "+f"(c[3])
                 : "r"(a[0]), "r"(a[1]), "r"(a[2]), "r"(a[3]), "r"(b[0]), "r"(b[1]));
}
__device__ __forceinline__ void mma_s8(int* c, const uint32_t* a, const uint32_t* b) {
    asm volatile("mma.sync.aligned.m16n8k32.row.col.s32.s8.s8.s32 "
                 "{%0,%1,%2,%3}, {%4,%5,%6,%7}, {%8,%9}, {%0,%1,%2,%3};"
                 : "+r"(c[0]), "+r"(c[1]), "+r"(c[2]), "+r"(c[3])
                 : "r"(a[0]), "r"(a[1]), "r"(a[2]), "r"(a[3]), "r"(b[0]), "r"(b[1]));
}
__device__ __forceinline__ uint32_t swz64(uint32_t o) { return o ^ ((o >> 3) & 0x70); }

// ================= scratch =================
__device__ __align__(128) float g_x[BB * CC * HWW];
__device__ __align__(128) float g_cap[(size_t)BB * OC * HWW];
__device__ float g_cap4[BB * NCAPS * HWW];
__device__ int   g_idx[BB * NCAPS];
__device__ int   g_slots[BB * SLOTS];
__device__ float g_rpart[KSPLIT * BB * OC * SLOTS];
__device__ float g_norm[BB * HWW];
__device__ float g_smean[CC * NCAPS];
__device__ float g_cm[BB * NCAPS * HWW];
__device__ float g_mm[BB * NCAPS * 2];
__device__ float g_cmmean[BB * HWW];
__device__ float g_proto[NCAPS * CC];
__device__ float g_pm[CC];
__device__ __align__(128) __nv_bfloat16 g_w_hi[TAPS * OC * CC];
__device__ __align__(128) __nv_bfloat16 g_w_lo[TAPS * OC * CC];
__device__ __align__(128) __nv_bfloat16 g_xp_hi[BB * 40 * 40 * CC];
__device__ __align__(128) __nv_bfloat16 g_xp_lo[BB * 40 * 40 * CC];
__device__ __align__(128) int8_t g_w_s8[TAPS * OC * CC];
__device__ __align__(128) int8_t g_xp_s8[BB * 40 * 40 * CC];
__device__ unsigned int g_wmax_bits;   // atomicMax of float bits; idempotent across replays
__device__ unsigned int g_xmax_bits;
__device__ __align__(128) __nv_bfloat16 g_cw_hi[CC * CC];
__device__ __align__(128) __nv_bfloat16 g_cw_lo[CC * CC];
__device__ __align__(128) __nv_bfloat16 g_x5t_hi[BB * HWW * CC];
__device__ __align__(128) __nv_bfloat16 g_x5t_lo[BB * HWW * CC];

// ================= KP_W1: split conv_w into bf16 hi/lo ======================
__global__ void kp_w1(const float* __restrict__ w) {
    int i = blockIdx.x * 256 + threadIdx.x;
    float v = w[i];
    __nv_bfloat16 h = __float2bfloat16(v);
    g_cw_hi[i] = h;
    g_cw_lo[i] = __float2bfloat16(v - __bfloat162float(h));
}

// ================= KP5: transpose x5 -> pixel-major bf16 hi/lo ==============
__global__ __launch_bounds__(256) void kp5(const float* __restrict__ x5) {
    __shared__ float tile[32][33];
    int b = blockIdx.y, h = blockIdx.x;
    int tid = threadIdx.x;
    for (int c0 = 0; c0 < CC; c0 += 32) {
#pragma unroll
        for (int s = 0; s < 4; s++) {
            int cl = (tid >> 5) + s * 8, w = tid & 31;
            tile[cl][w] = x5[((size_t)(b * CC + c0 + cl)) * HWW + h * 32 + w];
        }
        __syncthreads();
#pragma unroll
        for (int s = 0; s < 4; s++) {
            int wl = (tid >> 5) + s * 8, ci = tid & 31;
            float v = tile[ci][wl];
            size_t dst = ((size_t)(b * HWW + h * 32 + wl)) * CC + c0 + ci;
            __nv_bfloat16 hh = __float2bfloat16(v);
            g_x5t_hi[dst] = hh;
            g_x5t_lo[dst] = __float2bfloat16(v - __bfloat162float(hh));
        }
        __syncthreads();
    }
}

// ================= K1: split-bf16 mma: x = W@x5 + b + x5 (+ global amax) ====
#define K1_STG 49152u
#define K1_SMEM 98304
__global__ __launch_bounds__(256, 1) void k1_mma(const float* __restrict__ x5,
                                                 const float* __restrict__ bias) {
    extern __shared__ char smem[];
    uint32_t sb = smem_u32(smem);
    int tid = threadIdx.x, wid = tid >> 5, lane = tid & 31;
    int pix0 = blockIdx.x * 256;
    int ocb  = blockIdx.y * 128;
    int b    = blockIdx.z;
    int mbase = (wid >> 2) * 64;
    int nbase = (wid & 3) * 64;

    float acc[4][8][4];
#pragma unroll
    for (int mt = 0; mt < 4; mt++)
#pragma unroll
        for (int nt = 0; nt < 8; nt++)
#pragma unroll
            for (int j = 0; j < 4; j++) acc[mt][nt][j] = 0.f;

    auto issue = [&](int kch, int s) {
        uint32_t stg = sb + (uint32_t)s * K1_STG;
#pragma unroll
        for (int p = 0; p < 4; p++) {
            int e = tid + p * 256;
            int plane = e >> 9, r = (e >> 2) & 127, kc = e & 3;
            size_t gsrc = (size_t)(ocb + r) * CC + kch * 32 + kc * 8;
            const __nv_bfloat16* src = (plane ? g_cw_lo : g_cw_hi) + gsrc;
            CP_ASYNC16(stg + (uint32_t)plane * 8192u + swz64((uint32_t)(r * 64 + kc * 16)),
                       (const void*)src);
        }
#pragma unroll
        for (int p = 0; p < 8; p++) {
            int e = tid + p * 256;
            int plane = e >> 10, row = (e >> 2) & 255, kc = e & 3;
            size_t gsrc = ((size_t)(b * HWW + pix0 + row)) * CC + kch * 32 + kc * 8;
            const __nv_bfloat16* src = (plane ? g_x5t_lo : g_x5t_hi) + gsrc;
            CP_ASYNC16(stg + 16384u + (uint32_t)plane * 16384u + swz64((uint32_t)(row * 64 + kc * 16)),
                       (const void*)src);
        }
    };

    issue(0, 0);
    CP_COMMIT();
    for (int kch = 0; kch < 16; kch++) {
        int s = kch & 1;
        if (kch + 1 < 16) issue(kch + 1, s ^ 1);
        CP_COMMIT();
        CP_WAIT1();
        __syncthreads();
        uint32_t stg = sb + (uint32_t)s * K1_STG;
#pragma unroll
        for (int kb = 0; kb < 2; kb++) {
            uint32_t ah[4][4], al[4][4];
#pragma unroll
            for (int mt = 0; mt < 4; mt++) {
                int arow = mbase + mt * 16 + (lane & 15);
                int kcs = kb * 2 + (lane >> 4);
                uint32_t so = swz64((uint32_t)(arow * 64 + kcs * 16));
                ldsm_x4(ah[mt], stg + so);
                ldsm_x4(al[mt], stg + 8192u + so);
            }
#pragma unroll
            for (int ntp = 0; ntp < 4; ntp++) {
                int m = lane >> 3;
                int row = nbase + ntp * 16 + ((m & 2) << 2) + (lane & 7);
                int kcs = kb * 2 + (m & 1);
                uint32_t so = swz64((uint32_t)(row * 64 + kcs * 16));
                uint32_t bh[4], bl[4];
                ldsm_x4(bh, stg + 16384u + so);
                ldsm_x4(bl, stg + 32768u + so);
#pragma unroll
                for (int mt = 0; mt < 4; mt++) {
                    mma_bf16(acc[mt][2 * ntp],     ah[mt], bh);
                    mma_bf16(acc[mt][2 * ntp],     ah[mt], bl);
                    mma_bf16(acc[mt][2 * ntp],     al[mt], bh);
                    mma_bf16(acc[mt][2 * ntp + 1], ah[mt], bh + 2);
                    mma_bf16(acc[mt][2 * ntp + 1], ah[mt], bl + 2);
                    mma_bf16(acc[mt][2 * ntp + 1], al[mt], bh + 2);
                }
            }
        }
        __syncthreads();
    }
    // epilogue: + bias + x5 residual; track |x| max for int8 scale
    float am = 0.f;
#pragma unroll
    for (int mt = 0; mt < 4; mt++) {
        int m0 = ocb + mbase + mt * 16 + (lane >> 2);
        float bi0 = bias[m0], bi1 = bias[m0 + 8];
        size_t base0 = ((size_t)(b * CC + m0)) * HWW + pix0;
        size_t base1 = ((size_t)(b * CC + m0 + 8)) * HWW + pix0;
#pragma unroll
        for (int nt = 0; nt < 8; nt++) {
            int n = nbase + nt * 8 + (lane & 3) * 2;
            float v0 = acc[mt][nt][0] + bi0 + x5[base0 + n];
            float v1 = acc[mt][nt][1] + bi0 + x5[base0 + n + 1];
            float v2 = acc[mt][nt][2] + bi1 + x5[base1 + n];
            float v3 = acc[mt][nt][3] + bi1 + x5[base1 + n + 1];
            g_x[base0 + n]     = v0;
            g_x[base0 + n + 1] = v1;
            g_x[base1 + n]     = v2;
            g_x[base1 + n + 1] = v3;
            am = fmaxf(am, fmaxf(fmaxf(fabsf(v0), fabsf(v1)), fmaxf(fabsf(v2), fabsf(v3))));
        }
    }
#pragma unroll
    for (int off = 16; off; off >>= 1)
        am = fmaxf(am, __shfl_xor_sync(0xffffffffu, am, off));
    if (lane == 0) atomicMax(&g_xmax_bits, __float_as_uint(am));
}

// ================= KPW: transpose caps_w -> bf16 hi/lo + max|w| =============
__global__ __launch_bounds__(256) void kp_w(const float* __restrict__ cw) {
    __shared__ float tile[64 * 81];
    __shared__ float red[256];
    int o  = blockIdx.x >> 3;
    int c0 = (blockIdx.x & 7) * 64;
    int tid = threadIdx.x;
    for (int e = tid; e < 64 * 81; e += 256) {
        int c_l = e / 81, t = e - c_l * 81;
        tile[e] = cw[((size_t)o * CC + c0 + c_l) * TAPS + t];
    }
    __syncthreads();
    float amax = 0.f;
    for (int e = tid; e < 81 * 64; e += 256) {
        int t = e >> 6, c_l = e & 63;
        float v = tile[c_l * 81 + t];
        amax = fmaxf(amax, fabsf(v));
        __nv_bfloat16 h = __float2bfloat16(v);
        size_t di = ((size_t)(t * OC + o)) * CC + c0 + c_l;
        g_w_hi[di] = h;
        g_w_lo[di] = __float2bfloat16(v - __bfloat162float(h));
    }
    red[tid] = amax;
    __syncthreads();
    for (int s = 128; s > 0; s >>= 1) {
        if (tid < s) red[tid] = fmaxf(red[tid], red[tid + s]);
        __syncthreads();
    }
    if (tid == 0) atomicMax(&g_wmax_bits, __float_as_uint(red[0]));
}

// ================= KP_WQ: quantize weights to int8 ==========================
__global__ void kp_wq() {
    float qi = 127.f / __uint_as_float(g_wmax_bits);
    int i = blockIdx.x * 256 + threadIdx.x;
    uint4 h = ((const uint4*)g_w_hi)[i];
    uint4 l = ((const uint4*)g_w_lo)[i];
    const __nv_bfloat16* hp = (const __nv_bfloat16*)&h;
    const __nv_bfloat16* lp = (const __nv_bfloat16*)&l;
    char r[8];
#pragma unroll
    for (int j = 0; j < 8; j++) {
        float v = __bfloat162float(hp[j]) + __bfloat162float(lp[j]);
        int q = __float2int_rn(v * qi);
        q = max(-127, min(127, q));
        r[j] = (char)q;
    }
    ((uint2*)g_w_s8)[i] = *(uint2*)r;
}

// ================= KPZ: zero padded x planes (bf16 + int8) ==================
__global__ void kp_xz() {
    int i = blockIdx.x * 256 + threadIdx.x;
    uint4 z = {0, 0, 0, 0};
    ((uint4*)g_xp_hi)[i] = z;
    ((uint4*)g_xp_lo)[i] = z;
    if (i < 819200) ((uint4*)g_xp_s8)[i] = z;
}

// ================= KPX: transpose g_x -> bf16 hi/lo + int8 + norm ===========
__global__ __launch_bounds__(256) void kp_x() {
    __shared__ float tile[32][33];
    int b = blockIdx.y, h = blockIdx.x;
    int tid = threadIdx.x;
    int lane = tid & 31;
    float qi = 127.f / __uint_as_float(g_xmax_bits);
    float nsum[4] = {0.f, 0.f, 0.f, 0.f};
    for (int c0 = 0; c0 < CC; c0 += 32) {
#pragma unroll
        for (int s = 0; s < 4; s++) {
            int cl = (tid >> 5) + s * 8, w = tid & 31;
            tile[cl][w] = g_x[((size_t)(b * CC + c0 + cl)) * HWW + h * 32 + w];
        }
        __syncthreads();
#pragma unroll
        for (int s = 0; s < 4; s++) {
            int wl = (tid >> 5) + s * 8, ci = lane;
            float v = tile[ci][wl];
            size_t dst = ((size_t)((b * 40 + h + 4) * 40 + wl + 4)) * CC + c0 + ci;
            __nv_bfloat16 hh = __float2bfloat16(v);
            g_xp_hi[dst] = hh;
            g_xp_lo[dst] = __float2bfloat16(v - __bfloat162float(hh));
            int q = __float2int_rn(v * qi);
            q = max(-127, min(127, q));
            g_xp_s8[dst] = (int8_t)q;
            float vv = v * v;
#pragma unroll
            for (int off = 16; off; off >>= 1)
                vv += __shfl_xor_sync(0xffffffffu, vv, off);
            nsum[s] += vv;
        }
        __syncthreads();
    }
    if (lane == 0) {
#pragma unroll
        for (int s = 0; s < 4; s++)
            g_norm[b * HWW + h * 32 + (tid >> 5) + s * 8] = sqrtf(nsum[s]);
    }
}

// ================= K2a: int8 ranking conv (approx) ==========================
#define S8_BSLAB 0u
#define S8_BSTR  10240u
#define S8_A     20480u
#define K2A_SMEM 32768
__global__ __launch_bounds__(256, 1) void k2a_s8(const float* __restrict__ cb) {
    extern __shared__ char smem[];
    uint32_t sb = smem_u32(smem);
    int tid = threadIdx.x, wid = tid >> 5, lane = tid & 31;
    int bh8  = blockIdx.x * 8;
    int pix0 = blockIdx.x * 256;
    int ocb  = blockIdx.y * 128;
    int b    = blockIdx.z;
    int mbase = (wid >> 2) * 64;
    int nbase = (wid & 3) * 64;

    int acc[4][8][4];
#pragma unroll
    for (int mt = 0; mt < 4; mt++)
#pragma unroll
        for (int nt = 0; nt < 8; nt++)
#pragma unroll
            for (int j = 0; j < 4; j++) acc[mt][nt][j] = 0;

    for (int q = 0; q < 16; q++) {
        __syncthreads();
        for (int e = tid; e < 1280; e += 256) {
            int px = e >> 1, kc = e & 1;
            int pr = px / 40, pc = px - pr * 40;
            const int8_t* src = g_xp_s8 +
                ((size_t)((b * 40 + bh8 + pr) * 40 + pc)) * CC + q * 32 + kc * 16;
            CP_ASYNC16(sb + S8_BSLAB + (uint32_t)kc * S8_BSTR + (uint32_t)px * 16u,
                       (const void*)src);
        }
        CP_COMMIT();
#pragma unroll
        for (int t0 = 0; t0 < 2; t0++) {
            int r = tid >> 1, kc = tid & 1;
            const int8_t* src = g_w_s8 + ((size_t)(t0 * OC + ocb + r)) * CC + q * 32 + kc * 16;
            CP_ASYNC16(sb + S8_A + (uint32_t)t0 * 4096u + (uint32_t)kc * 2048u + (uint32_t)r * 16u,
                       (const void*)src);
            CP_COMMIT();
        }
        CP_WAIT0();
        __syncthreads();

        for (int tap = 0; tap < TAPS; tap++) {
            int st = tap - (tap / 3) * 3;
            int dy = tap / 9, dx = tap - dy * 9;
            CP_WAIT1();
            __syncthreads();
            if (tap + 2 < TAPS) {
                int tnx = tap + 2;
                int stn = tnx - (tnx / 3) * 3;
                int r = tid >> 1, kc = tid & 1;
                const int8_t* src = g_w_s8 + ((size_t)(tnx * OC + ocb + r)) * CC + q * 32 + kc * 16;
                CP_ASYNC16(sb + S8_A + (uint32_t)stn * 4096u + (uint32_t)kc * 2048u + (uint32_t)r * 16u,
                           (const void*)src);
            }
            CP_COMMIT();
            uint32_t abase = sb + S8_A + (uint32_t)st * 4096u;
            uint32_t a[4][4];
#pragma unroll
            for (int mt = 0; mt < 4; mt++) {
                int arow = mbase + mt * 16 + (lane & 15);
                int kcs = lane >> 4;
                ldsm_x4(a[mt], abase + (uint32_t)kcs * 2048u + (uint32_t)arow * 16u);
            }
#pragma unroll
            for (int ntp = 0; ntp < 4; ntp++) {
                int m = lane >> 3;
                int n_ = nbase + ntp * 16 + ((m & 2) << 2) + (lane & 7);
                int hl = n_ >> 5, w = n_ & 31;
                int kcs = m & 1;
                int px = (hl + dy) * 40 + (w + dx);
                uint32_t bq[4];
                ldsm_x4(bq, sb + S8_BSLAB + (uint32_t)kcs * S8_BSTR + (uint32_t)px * 16u);
#pragma unroll
                for (int mt = 0; mt < 4; mt++) {
                    mma_s8(acc[mt][2 * ntp],     a[mt], bq);
                    mma_s8(acc[mt][2 * ntp + 1], a[mt], bq + 2);
                }
            }
        }
    }
    float s = (__uint_as_float(g_wmax_bits) * (1.f / 127.f)) *
              (__uint_as_float(g_xmax_bits) * (1.f / 127.f));
#pragma unroll
    for (int mt = 0; mt < 4; mt++) {
        int m0 = ocb + mbase + mt * 16 + (lane >> 2);
        float bi0 = cb[m0], bi1 = cb[m0 + 8];
        float* d0 = g_cap + ((size_t)(b * OC + m0)) * HWW + pix0;
        float* d1 = g_cap + ((size_t)(b * OC + m0 + 8)) * HWW + pix0;
#pragma unroll
        for (int nt = 0; nt < 8; nt++) {
            int n = nbase + nt * 8 + (lane & 3) * 2;
            d0[n]     = (float)acc[mt][nt][0] * s + bi0;
            d0[n + 1] = (float)acc[mt][nt][1] * s + bi0;
            d1[n]     = (float)acc[mt][nt][2] * s + bi1;
            d1[n + 1] = (float)acc[mt][nt][3] * s + bi1;
        }
    }
}

// ================= K4: squash + max over CAP_C (approx values) ==============
__global__ void k4_sqmax() {
    int i = blockIdx.x * 256 + threadIdx.x;
    int b = i >> 10, hw = i & 1023;
    const float* cp = g_cap + (size_t)b * OC * HWW + hw;
    float m[8];
#pragma unroll
    for (int k = 0; k < 8; k++) m[k] = -INFINITY;
    for (int c = 0; c < CAPC; c++) {
        float v[8]; float sq = 0.f;
#pragma unroll
        for (int k = 0; k < 8; k++) { v[k] = cp[(size_t)(k * CAPC + c) * HWW]; sq += v[k] * v[k]; }
        float s = sq / ((1.f + sq) * sqrtf(sq + 1e-8f));
#pragma unroll
        for (int k = 0; k < 8; k++) m[k] = fmaxf(m[k], v[k] * s);
    }
#pragma unroll
    for (int k = 0; k < 8; k++) g_cap4[(b * 8 + k) * HWW + hw] = m[k];
}

// ================= K5: top-8 candidate pixels per (b,k) =====================
__global__ void k5_top8() {
    int bk = blockIdx.x;
    int b = bk >> 3, k = bk & 7;
    __shared__ float val[1024];
    __shared__ float sv[256];
    __shared__ int   si[256];
    int tid = threadIdx.x;
    for (int hw = tid; hw < HWW; hw += 256) val[hw] = g_cap4[bk * HWW + hw];
    __syncthreads();
    for (int j = 0; j < TOPK; j++) {
        float best = -INFINITY; int bi = 0x7fffffff;
        for (int hw = tid; hw < HWW; hw += 256) {
            float v = val[hw];
            if (v > best || (v == best && hw < bi)) { best = v; bi = hw; }
        }
        sv[tid] = best; si[tid] = bi;
        __syncthreads();
        for (int s = 128; s > 0; s >>= 1) {
            if (tid < s) {
                if (sv[tid + s] > sv[tid] ||
                    (sv[tid + s] == sv[tid] && si[tid + s] < si[tid])) {
                    sv[tid] = sv[tid + s]; si[tid] = si[tid + s];
                }
            }
            __syncthreads();
        }
        if (tid == 0) {
            g_slots[b * SLOTS + k * TOPK + j] = si[0];
            val[si[0]] = -INFINITY;
        }
        __syncthreads();
    }
}

// ================= K2b: 3-term exact rescore, split-K=8 =====================
#define RB_STG 24576u
#define K2B_SMEM 49664
__global__ __launch_bounds__(256, 1) void k2b_rescore() {
    extern __shared__ char smem[];
    uint32_t sb = smem_u32(smem);
    int* s_slots = (int*)(smem + 49152);
    int tid = threadIdx.x, wid = tid >> 5, lane = tid & 31;
    int qs  = blockIdx.x;            // 0..7, 2 q-chunks each
    int ocb = blockIdx.y * 128;
    int b   = blockIdx.z;
    int mbase = (wid >> 1) * 32;
    int nbase = (wid & 1) * 32;

    if (tid < SLOTS) s_slots[tid] = g_slots[b * SLOTS + tid];
    __syncthreads();

    float acc[2][4][4];
#pragma unroll
    for (int mt = 0; mt < 2; mt++)
#pragma unroll
        for (int nt = 0; nt < 4; nt++)
#pragma unroll
            for (int j = 0; j < 4; j++) acc[mt][nt][j] = 0.f;

    auto issue = [&](int it, int s) {
        int q = qs * 2 + it / 81;
        int tap = it - (it / 81) * 81;
        int dy = tap / 9, dx = tap - dy * 9;
        uint32_t stg = sb + (uint32_t)s * RB_STG;
#pragma unroll
        for (int p = 0; p < 4; p++) {
            int e = tid + p * 256;
            int plane = e >> 9, r = (e >> 2) & 127, kc = e & 3;
            size_t gsrc = ((size_t)(tap * OC + ocb + r)) * CC + q * 32 + kc * 8;
            const __nv_bfloat16* src = (plane ? g_w_lo : g_w_hi) + gsrc;
            CP_ASYNC16(stg + (uint32_t)plane * 8192u + swz64((uint32_t)(r * 64 + kc * 16)),
                       (const void*)src);
        }
#pragma unroll
        for (int p = 0; p < 2; p++) {
            int e = tid + p * 256;
            int plane = (e >> 8) & 1, row = (e >> 2) & 63, kc = e & 3;
            int pix = s_slots[row];
            int y = pix >> 5, x = pix & 31;
            size_t gsrc = ((size_t)((b * 40 + y + dy) * 40 + (x + dx))) * CC + q * 32 + kc * 8;
            const __nv_bfloat16* src = (plane ? g_xp_lo : g_xp_hi) + gsrc;
            CP_ASYNC16(stg + 16384u + (uint32_t)plane * 4096u + swz64((uint32_t)(row * 64 + kc * 16)),
                       (const void*)src);
        }
    };

    issue(0, 0);
    CP_COMMIT();
    const int NIT = 2 * TAPS;
    for (int it = 0; it < NIT; it++) {
        int s = it & 1;
        if (it + 1 < NIT) issue(it + 1, s ^ 1);
        CP_COMMIT();
        CP_WAIT1();
        __syncthreads();
        uint32_t stg = sb + (uint32_t)s * RB_STG;
#pragma unroll
        for (int kb = 0; kb < 2; kb++) {
            uint32_t ah[2][4], al[2][4];
#pragma unroll
            for (int mt = 0; mt < 2; mt++) {
                int arow = mbase + mt * 16 + (lane & 15);
                int kcs = kb * 2 + (lane >> 4);
                uint32_t so = swz64((uint32_t)(arow * 64 + kcs * 16));
                ldsm_x4(ah[mt], stg + so);
                ldsm_x4(al[mt], stg + 8192u + so);
            }
#pragma unroll
            for (int ntp = 0; ntp < 2; ntp++) {
                int m = lane >> 3;
                int row = nbase + ntp * 16 + ((m & 2) << 2) + (lane & 7);
                int kcs = kb * 2 + (m & 1);
                uint32_t so = swz64((uint32_t)(row * 64 + kcs * 16));
                uint32_t bh[4], bl[4];
                ldsm_x4(bh, stg + 16384u + so);
                ldsm_x4(bl, stg + 16384u + 4096u + so);
#pragma unroll
                for (int mt = 0; mt < 2; mt++) {
                    mma_bf16(acc[mt][2 * ntp],     ah[mt], bh);
                    mma_bf16(acc[mt][2 * ntp],     ah[mt], bl);
                    mma_bf16(acc[mt][2 * ntp],     al[mt], bh);
                    mma_bf16(acc[mt][2 * ntp + 1], ah[mt], bh + 2);
                    mma_bf16(acc[mt][2 * ntp + 1], ah[mt], bl + 2);
                    mma_bf16(acc[mt][2 * ntp + 1], al[mt], bh + 2);
                }
            }
        }
        __syncthreads();
    }
#pragma unroll
    for (int mt = 0; mt < 2; mt++) {
        int m0 = ocb + mbase + mt * 16 + (lane >> 2);
        float* d0 = g_rpart + ((size_t)((qs * BB + b) * OC + m0)) * SLOTS;
        float* d1 = d0 + 8 * SLOTS;
#pragma unroll
        for (int nt = 0; nt < 4; nt++) {
            int n = nbase + nt * 8 + (lane & 3) * 2;
            d0[n]     = acc[mt][nt][0];
            d0[n + 1] = acc[mt][nt][1];
            d1[n]     = acc[mt][nt][2];
            d1[n + 1] = acc[mt][nt][3];
        }
    }
}

// ================= K2c: combine + exact squash + final argmax ===============
#define K2C_SMEM (OC * SLOTS * 4 + NCAPS * SLOTS * 4 + SLOTS * 4)
__global__ __launch_bounds__(256) void k2c_pick(const float* __restrict__ cb) {
    extern __shared__ char smem[];
    float* v     = (float*)smem;
    float* sval  = (float*)(smem + OC * SLOTS * 4);
    int*   sl    = (int*)(smem + OC * SLOTS * 4 + NCAPS * SLOTS * 4);
    int b = blockIdx.x, tid = threadIdx.x;
    if (tid < SLOTS) sl[tid] = g_slots[b * SLOTS + tid];
    for (int idx = tid; idx < OC * SLOTS; idx += 256) {
        int oc = idx >> 6;
        float s = cb[oc];
#pragma unroll
        for (int qs = 0; qs < KSPLIT; qs++)
            s += g_rpart[((size_t)((qs * BB + b) * OC)) * SLOTS + idx];
        v[idx] = s;
    }
    __syncthreads();
    if (tid < SLOTS) {
        float mk[8];
#pragma unroll
        for (int k = 0; k < 8; k++) mk[k] = -INFINITY;
        for (int c = 0; c < CAPC; c++) {
            float vv[8]; float sq = 0.f;
#pragma unroll
            for (int k = 0; k < 8; k++) {
                vv[k] = v[(k * CAPC + c) * SLOTS + tid];
                sq += vv[k] * vv[k];
            }
            float sf = sq / ((1.f + sq) * sqrtf(sq + 1e-8f));
#pragma unroll
            for (int k = 0; k < 8; k++) mk[k] = fmaxf(mk[k], vv[k] * sf);
        }
#pragma unroll
        for (int k = 0; k < 8; k++) sval[k * SLOTS + tid] = mk[k];
    }
    __syncthreads();
    if (tid < NCAPS) {
        float best = -INFINITY; int bp = 0x7fffffff;
        for (int s = 0; s < SLOTS; s++) {
            float vv = sval[tid * SLOTS + s];
            int px = sl[s];
            if (vv > best || (vv == best && px < bp)) { best = vv; bp = px; }
        }
        g_idx[b * NCAPS + tid] = bp;
    }
}

// ================= K6..K12 (exact path) =====================================
__global__ void k6_smean() {
    int i = blockIdx.x * 256 + threadIdx.x;
    int c = i >> 3, k = i & 7;
    float s = 0.f;
    for (int b = 0; b < BB; b++) {
        int hw = g_idx[b * 8 + k];
        float n = fmaxf(g_norm[b * HWW + hw], 1e-12f);
        s += g_x[((size_t)(b * CC + c)) * HWW + hw] / n;
    }
    g_smean[c * 8 + k] = s * (1.f / 16.f);
}

__global__ __launch_bounds__(256) void k7_cm() {
    __shared__ float ss[CC * 8];
    for (int e = threadIdx.x; e < CC * 8; e += 256) ss[e] = g_smean[e];
    __syncthreads();
    int i = blockIdx.x * 256 + threadIdx.x;
    int b = i >> 10, hw = i & 1023;
    const float* xp = g_x + (size_t)b * CC * HWW + hw;
    float acc[8] = {};
    for (int c = 0; c < CC; c++) {
        float xv = xp[c * HWW];
#pragma unroll
        for (int k = 0; k < 8; k++) acc[k] += xv * ss[c * 8 + k];
    }
    float inv = 1.f / fmaxf(g_norm[i], 1e-12f);
#pragma unroll
    for (int k = 0; k < 8; k++) g_cm[(b * 8 + k) * HWW + hw] = acc[k] * inv;
}

__global__ void k8_minmax() {
    int bk = blockIdx.x;
    __shared__ float smn[256], smx[256];
    int tid = threadIdx.x;
    float mn = INFINITY, mx = -INFINITY;
    for (int hw = tid; hw < HWW; hw += 256) {
        float v = g_cm[bk * HWW + hw];
        mn = fminf(mn, v); mx = fmaxf(mx, v);
    }
    smn[tid] = mn; smx[tid] = mx;
    __syncthreads();
    for (int s = 128; s > 0; s >>= 1) {
        if (tid < s) {
            smn[tid] = fminf(smn[tid], smn[tid + s]);
            smx[tid] = fmaxf(smx[tid], smx[tid + s]);
        }
        __syncthreads();
    }
    if (tid == 0) { g_mm[bk * 2] = smn[0]; g_mm[bk * 2 + 1] = smx[0]; }
}

__global__ void k9_cmnorm() {
    int i = blockIdx.x * 256 + threadIdx.x;
    int b = i >> 10, hw = i & 1023;
    float s = 0.f;
#pragma unroll
    for (int k = 0; k < 8; k++) {
        int bk = b * 8 + k;
        float mn = g_mm[bk * 2], mx = g_mm[bk * 2 + 1];
        float v = (g_cm[bk * HWW + hw] - mn) / (mx - mn + 1e-12f);
        g_cm[bk * HWW + hw] = v;
        s += v;
    }
    g_cmmean[i] = s * 0.125f;
}

__global__ void k10_proto() {
    int c = blockIdx.x;
    float acc[8] = {};
    for (int i = threadIdx.x; i < BB * HWW; i += 256) {
        int b = i >> 10, hw = i & 1023;
        float xv = g_x[((size_t)(b * CC + c)) * HWW + hw];
#pragma unroll
        for (int k = 0; k < 8; k++) acc[k] += xv * g_cm[(b * 8 + k) * HWW + hw];
    }
    __shared__ float red[256];
    for (int k = 0; k < 8; k++) {
        red[threadIdx.x] = acc[k];
        __syncthreads();
        for (int s = 128; s > 0; s >>= 1) {
            if (threadIdx.x < s) red[threadIdx.x] += red[threadIdx.x + s];
            __syncthreads();
        }
        if (threadIdx.x == 0) g_proto[k * CC + c] = red[0] * (1.f / (BB * HWW));
        __syncthreads();
    }
}

__global__ void k11_pm(float* __restrict__ out) {
    int c = threadIdx.x;
    float s = 0.f;
#pragma unroll
    for (int k = 0; k < 8; k++) s += g_proto[k * CC + c];
    s *= 0.125f;
    g_pm[c] = s;
    __shared__ float red[512];
    red[c] = s * s;
    __syncthreads();
    for (int st = 256; st > 0; st >>= 1) {
        if (c < st) red[c] += red[c + st];
        __syncthreads();
    }
    float nrm = fmaxf(sqrtf(red[0]), 1e-12f);
    out[c] = s / nrm;
}

__global__ __launch_bounds__(256) void k12_out(float* __restrict__ out) {
    __shared__ float spm[CC];
    for (int e = threadIdx.x; e < CC; e += 256) spm[e] = g_pm[e];
    __syncthreads();
    int i = blockIdx.x * 256 + threadIdx.x;
    int b = i >> 10, hw = i & 1023;
    float cmm = g_cmmean[i];
    const float* xp = g_x + (size_t)b * CC * HWW + hw;
    float ss2 = 0.f;
    for (int c = 0; c < CC; c++) {
        float v = xp[c * HWW] * (spm[c] + cmm);
        ss2 += v * v;
    }
    float inv = 1.f / fmaxf(sqrtf(ss2), 1e-12f);
    float* op = out + CC + (size_t)b * CC * HWW + hw;
    for (int c = 0; c < CC; c++)
        op[c * HWW] = xp[c * HWW] * (spm[c] + cmm) * inv;
}

// ================= launcher ==================================================
extern "C" void kernel_launch(void* const* d_in, const int* in_sizes, int n_in,
                              void* d_out, int out_size) {
    const float* x5     = (const float*)d_in[0];
    const float* conv_w = (const float*)d_in[1];
    const float* conv_b = (const float*)d_in[2];
    const float* caps_w = (const float*)d_in[3];
    const float* caps_b = (const float*)d_in[4];
    float* out = (float*)d_out;
    (void)in_sizes; (void)n_in; (void)out_size;

    cudaFuncSetAttribute(k1_mma,      cudaFuncAttributeMaxDynamicSharedMemorySize, K1_SMEM);
    cudaFuncSetAttribute(k2a_s8,      cudaFuncAttributeMaxDynamicSharedMemorySize, K2A_SMEM);
    cudaFuncSetAttribute(k2b_rescore, cudaFuncAttributeMaxDynamicSharedMemorySize, K2B_SMEM);
    cudaFuncSetAttribute(k2c_pick,    cudaFuncAttributeMaxDynamicSharedMemorySize, K2C_SMEM);

    kp_w1   <<<1024, 256>>>(conv_w);
    kp5     <<<dim3(32, 16), 256>>>(x5);
    kp_w    <<<2048, 256>>>(caps_w);
    kp_wq   <<<5184, 256>>>();
    kp_xz   <<<6400, 256>>>();
    k1_mma  <<<dim3(4, 4, 16), 256, K1_SMEM>>>(x5, conv_b);
    kp_x    <<<dim3(32, 16), 256>>>();
    k2a_s8  <<<dim3(4, 2, 16), 256, K2A_SMEM>>>(caps_b);
    k4_sqmax<<<64, 256>>>();
    k5_top8 <<<128, 256>>>();
    k2b_rescore<<<dim3(KSPLIT, 2, 16), 256, K2B_SMEM>>>();
    k2c_pick<<<16, 256, K2C_SMEM>>>(caps_b);
    k6_smean<<<16, 256>>>();
    k7_cm   <<<64, 256>>>();
    k8_minmax<<<128, 256>>>();
    k9_cmnorm<<<64, 256>>>();
    k10_proto<<<512, 256>>>();
    k11_pm  <<<1, 512>>>(out);
    k12_out <<<64, 256>>>(out);
}

// round 12
// speedup vs baseline: 7.9060x; 1.0662x over previous
#include <cuda_runtime.h>
#include <cuda_bf16.h>
#include <math.h>
#include <stdint.h>

#define BB   16
#define CC   512
#define HWW  1024
#define NCAPS 8
#define CAPC 32
#define OC   256
#define TAPS 81
#define SLOTS 64
#define TOPK  8
#define KSPLIT 8

// ================= helpers =================
__device__ __forceinline__ uint32_t smem_u32(const void* p) {
    uint32_t a;
    asm("{ .reg .u64 t; cvta.to.shared.u64 t, %1; cvt.u32.u64 %0, t; }" : "=r"(a) : "l"(p));
    return a;
}
#define CP_ASYNC16(dst, src) \
    asm volatile("cp.async.cg.shared.global [%0], [%1], 16;" :: "r"(dst), "l"(src) : "memory")
#define CP_COMMIT() asm volatile("cp.async.commit_group;" ::: "memory")
#define CP_WAIT0()  asm volatile("cp.async.wait_group 0;" ::: "memory")
#define CP_WAIT1()  asm volatile("cp.async.wait_group 1;" ::: "memory")

__device__ __forceinline__ void ldsm_x4(uint32_t* r, uint32_t addr) {
    asm volatile("ldmatrix.sync.aligned.m8n8.x4.shared.b16 {%0,%1,%2,%3}, [%4];"
                 : "=r"(r[0]), "=r"(r[1]), "=r"(r[2]), "=r"(r[3]) : "r"(addr));
}
__device__ __forceinline__ void mma_bf16(float* c, const uint32_t* a, const uint32_t* b) {
    asm volatile("mma.sync.aligned.m16n8k16.row.col.f32.bf16.bf16.f32 "
                 "{%0,%1,%2,%3}, {%4,%5,%6,%7}, {%8,%9}, {%0,%1,%2,%3};"
                 : "+f"(c[0]), "+f"(c[1]), "+f"(c[2]), "+f"(c[3])
                 : "r"(a[0]), "r"(a[1]), "r"(a[2]), "r"(a[3]), "r"(b[0]), "r"(b[1]));
}
__device__ __forceinline__ void mma_s8(int* c, const uint32_t* a, const uint32_t* b) {
    asm volatile("mma.sync.aligned.m16n8k32.row.col.s32.s8.s8.s32 "
                 "{%0,%1,%2,%3}, {%4,%5,%6,%7}, {%8,%9}, {%0,%1,%2,%3};"
                 : "+r"(c[0]), "+r"(c[1]), "+r"(c[2]), "+r"(c[3])
                 : "r"(a[0]), "r"(a[1]), "r"(a[2]), "r"(a[3]), "r"(b[0]), "r"(b[1]));
}
__device__ __forceinline__ uint32_t swz64(uint32_t o) { return o ^ ((o >> 3) & 0x70); }

// ================= scratch =================
__device__ __align__(128) float g_x[BB * CC * HWW];
__device__ __align__(128) float g_cap[(size_t)BB * OC * HWW];
__device__ float g_cap4[BB * NCAPS * HWW];
__device__ int   g_idx[BB * NCAPS];
__device__ int   g_slots[BB * SLOTS];
__device__ float g_rpart[KSPLIT * BB * OC * SLOTS];
__device__ float g_norm[BB * HWW];
__device__ float g_smean[CC * NCAPS];
__device__ float g_cm[BB * NCAPS * HWW];
__device__ float g_mm[BB * NCAPS * 2];
__device__ float g_cmmean[BB * HWW];
__device__ float g_proto[NCAPS * CC];
__device__ float g_pm[CC];
__device__ __align__(128) __nv_bfloat16 g_w_hi[TAPS * OC * CC];
__device__ __align__(128) __nv_bfloat16 g_w_lo[TAPS * OC * CC];
__device__ __align__(128) __nv_bfloat16 g_xp_hi[BB * 40 * 40 * CC];
__device__ __align__(128) __nv_bfloat16 g_xp_lo[BB * 40 * 40 * CC];
__device__ __align__(128) int8_t g_w_s8[TAPS * OC * CC];
__device__ __align__(128) int8_t g_xp_s8[BB * 40 * 40 * CC];
__device__ unsigned int g_wmax_bits;
__device__ unsigned int g_xmax_bits;
__device__ __align__(128) __nv_bfloat16 g_cw_hi[CC * CC];
__device__ __align__(128) __nv_bfloat16 g_cw_lo[CC * CC];
__device__ __align__(128) __nv_bfloat16 g_x5t_hi[BB * HWW * CC];
__device__ __align__(128) __nv_bfloat16 g_x5t_lo[BB * HWW * CC];

// ================= KP_W1 ====================================================
__global__ void kp_w1(const float* __restrict__ w) {
    int i = blockIdx.x * 256 + threadIdx.x;
    float v = w[i];
    __nv_bfloat16 h = __float2bfloat16(v);
    g_cw_hi[i] = h;
    g_cw_lo[i] = __float2bfloat16(v - __bfloat162float(h));
}

// ================= KP5 ======================================================
__global__ __launch_bounds__(256) void kp5(const float* __restrict__ x5) {
    __shared__ float tile[32][33];
    int b = blockIdx.y, h = blockIdx.x;
    int tid = threadIdx.x;
    for (int c0 = 0; c0 < CC; c0 += 32) {
#pragma unroll
        for (int s = 0; s < 4; s++) {
            int cl = (tid >> 5) + s * 8, w = tid & 31;
            tile[cl][w] = x5[((size_t)(b * CC + c0 + cl)) * HWW + h * 32 + w];
        }
        __syncthreads();
#pragma unroll
        for (int s = 0; s < 4; s++) {
            int wl = (tid >> 5) + s * 8, ci = tid & 31;
            float v = tile[ci][wl];
            size_t dst = ((size_t)(b * HWW + h * 32 + wl)) * CC + c0 + ci;
            __nv_bfloat16 hh = __float2bfloat16(v);
            g_x5t_hi[dst] = hh;
            g_x5t_lo[dst] = __float2bfloat16(v - __bfloat162float(hh));
        }
        __syncthreads();
    }
}

// ================= K1: split-bf16 mma ======================================
#define K1_STG 49152u
#define K1_SMEM 98304
__global__ __launch_bounds__(256, 1) void k1_mma(const float* __restrict__ x5,
                                                 const float* __restrict__ bias) {
    extern __shared__ char smem[];
    uint32_t sb = smem_u32(smem);
    int tid = threadIdx.x, wid = tid >> 5, lane = tid & 31;
    int pix0 = blockIdx.x * 256;
    int ocb  = blockIdx.y * 128;
    int b    = blockIdx.z;
    int mbase = (wid >> 2) * 64;
    int nbase = (wid & 3) * 64;

    float acc[4][8][4];
#pragma unroll
    for (int mt = 0; mt < 4; mt++)
#pragma unroll
        for (int nt = 0; nt < 8; nt++)
#pragma unroll
            for (int j = 0; j < 4; j++) acc[mt][nt][j] = 0.f;

    auto issue = [&](int kch, int s) {
        uint32_t stg = sb + (uint32_t)s * K1_STG;
#pragma unroll
        for (int p = 0; p < 4; p++) {
            int e = tid + p * 256;
            int plane = e >> 9, r = (e >> 2) & 127, kc = e & 3;
            size_t gsrc = (size_t)(ocb + r) * CC + kch * 32 + kc * 8;
            const __nv_bfloat16* src = (plane ? g_cw_lo : g_cw_hi) + gsrc;
            CP_ASYNC16(stg + (uint32_t)plane * 8192u + swz64((uint32_t)(r * 64 + kc * 16)),
                       (const void*)src);
        }
#pragma unroll
        for (int p = 0; p < 8; p++) {
            int e = tid + p * 256;
            int plane = e >> 10, row = (e >> 2) & 255, kc = e & 3;
            size_t gsrc = ((size_t)(b * HWW + pix0 + row)) * CC + kch * 32 + kc * 8;
            const __nv_bfloat16* src = (plane ? g_x5t_lo : g_x5t_hi) + gsrc;
            CP_ASYNC16(stg + 16384u + (uint32_t)plane * 16384u + swz64((uint32_t)(row * 64 + kc * 16)),
                       (const void*)src);
        }
    };

    issue(0, 0);
    CP_COMMIT();
    for (int kch = 0; kch < 16; kch++) {
        int s = kch & 1;
        if (kch + 1 < 16) issue(kch + 1, s ^ 1);
        CP_COMMIT();
        CP_WAIT1();
        __syncthreads();
        uint32_t stg = sb + (uint32_t)s * K1_STG;
#pragma unroll
        for (int kb = 0; kb < 2; kb++) {
            uint32_t ah[4][4], al[4][4];
#pragma unroll
            for (int mt = 0; mt < 4; mt++) {
                int arow = mbase + mt * 16 + (lane & 15);
                int kcs = kb * 2 + (lane >> 4);
                uint32_t so = swz64((uint32_t)(arow * 64 + kcs * 16));
                ldsm_x4(ah[mt], stg + so);
                ldsm_x4(al[mt], stg + 8192u + so);
            }
#pragma unroll
            for (int ntp = 0; ntp < 4; ntp++) {
                int m = lane >> 3;
                int row = nbase + ntp * 16 + ((m & 2) << 2) + (lane & 7);
                int kcs = kb * 2 + (m & 1);
                uint32_t so = swz64((uint32_t)(row * 64 + kcs * 16));
                uint32_t bh[4], bl[4];
                ldsm_x4(bh, stg + 16384u + so);
                ldsm_x4(bl, stg + 32768u + so);
#pragma unroll
                for (int mt = 0; mt < 4; mt++) {
                    mma_bf16(acc[mt][2 * ntp],     ah[mt], bh);
                    mma_bf16(acc[mt][2 * ntp],     ah[mt], bl);
                    mma_bf16(acc[mt][2 * ntp],     al[mt], bh);
                    mma_bf16(acc[mt][2 * ntp + 1], ah[mt], bh + 2);
                    mma_bf16(acc[mt][2 * ntp + 1], ah[mt], bl + 2);
                    mma_bf16(acc[mt][2 * ntp + 1], al[mt], bh + 2);
                }
            }
        }
        __syncthreads();
    }
    float am = 0.f;
#pragma unroll
    for (int mt = 0; mt < 4; mt++) {
        int m0 = ocb + mbase + mt * 16 + (lane >> 2);
        float bi0 = bias[m0], bi1 = bias[m0 + 8];
        size_t base0 = ((size_t)(b * CC + m0)) * HWW + pix0;
        size_t base1 = ((size_t)(b * CC + m0 + 8)) * HWW + pix0;
#pragma unroll
        for (int nt = 0; nt < 8; nt++) {
            int n = nbase + nt * 8 + (lane & 3) * 2;
            float v0 = acc[mt][nt][0] + bi0 + x5[base0 + n];
            float v1 = acc[mt][nt][1] + bi0 + x5[base0 + n + 1];
            float v2 = acc[mt][nt][2] + bi1 + x5[base1 + n];
            float v3 = acc[mt][nt][3] + bi1 + x5[base1 + n + 1];
            g_x[base0 + n]     = v0;
            g_x[base0 + n + 1] = v1;
            g_x[base1 + n]     = v2;
            g_x[base1 + n + 1] = v3;
            am = fmaxf(am, fmaxf(fmaxf(fabsf(v0), fabsf(v1)), fmaxf(fabsf(v2), fabsf(v3))));
        }
    }
#pragma unroll
    for (int off = 16; off; off >>= 1)
        am = fmaxf(am, __shfl_xor_sync(0xffffffffu, am, off));
    if (lane == 0) atomicMax(&g_xmax_bits, __float_as_uint(am));
}

// ================= KPW ======================================================
__global__ __launch_bounds__(256) void kp_w(const float* __restrict__ cw) {
    __shared__ float tile[64 * 81];
    __shared__ float red[256];
    int o  = blockIdx.x >> 3;
    int c0 = (blockIdx.x & 7) * 64;
    int tid = threadIdx.x;
    for (int e = tid; e < 64 * 81; e += 256) {
        int c_l = e / 81, t = e - c_l * 81;
        tile[e] = cw[((size_t)o * CC + c0 + c_l) * TAPS + t];
    }
    __syncthreads();
    float amax = 0.f;
    for (int e = tid; e < 81 * 64; e += 256) {
        int t = e >> 6, c_l = e & 63;
        float v = tile[c_l * 81 + t];
        amax = fmaxf(amax, fabsf(v));
        __nv_bfloat16 h = __float2bfloat16(v);
        size_t di = ((size_t)(t * OC + o)) * CC + c0 + c_l;
        g_w_hi[di] = h;
        g_w_lo[di] = __float2bfloat16(v - __bfloat162float(h));
    }
    red[tid] = amax;
    __syncthreads();
    for (int s = 128; s > 0; s >>= 1) {
        if (tid < s) red[tid] = fmaxf(red[tid], red[tid + s]);
        __syncthreads();
    }
    if (tid == 0) atomicMax(&g_wmax_bits, __float_as_uint(red[0]));
}

// ================= KP_WQ ====================================================
__global__ void kp_wq() {
    float qi = 127.f / __uint_as_float(g_wmax_bits);
    int i = blockIdx.x * 256 + threadIdx.x;
    uint4 h = ((const uint4*)g_w_hi)[i];
    uint4 l = ((const uint4*)g_w_lo)[i];
    const __nv_bfloat16* hp = (const __nv_bfloat16*)&h;
    const __nv_bfloat16* lp = (const __nv_bfloat16*)&l;
    char r[8];
#pragma unroll
    for (int j = 0; j < 8; j++) {
        float v = __bfloat162float(hp[j]) + __bfloat162float(lp[j]);
        int q = __float2int_rn(v * qi);
        q = max(-127, min(127, q));
        r[j] = (char)q;
    }
    ((uint2*)g_w_s8)[i] = *(uint2*)r;
}

// ================= KPZ ======================================================
__global__ void kp_xz() {
    int i = blockIdx.x * 256 + threadIdx.x;
    uint4 z = {0, 0, 0, 0};
    ((uint4*)g_xp_hi)[i] = z;
    ((uint4*)g_xp_lo)[i] = z;
    if (i < 819200) ((uint4*)g_xp_s8)[i] = z;
}

// ================= KPX ======================================================
__global__ __launch_bounds__(256) void kp_x() {
    __shared__ float tile[32][33];
    int b = blockIdx.y, h = blockIdx.x;
    int tid = threadIdx.x;
    int lane = tid & 31;
    float qi = 127.f / __uint_as_float(g_xmax_bits);
    float nsum[4] = {0.f, 0.f, 0.f, 0.f};
    for (int c0 = 0; c0 < CC; c0 += 32) {
#pragma unroll
        for (int s = 0; s < 4; s++) {
            int cl = (tid >> 5) + s * 8, w = tid & 31;
            tile[cl][w] = g_x[((size_t)(b * CC + c0 + cl)) * HWW + h * 32 + w];
        }
        __syncthreads();
#pragma unroll
        for (int s = 0; s < 4; s++) {
            int wl = (tid >> 5) + s * 8, ci = lane;
            float v = tile[ci][wl];
            size_t dst = ((size_t)((b * 40 + h + 4) * 40 + wl + 4)) * CC + c0 + ci;
            __nv_bfloat16 hh = __float2bfloat16(v);
            g_xp_hi[dst] = hh;
            g_xp_lo[dst] = __float2bfloat16(v - __bfloat162float(hh));
            int q = __float2int_rn(v * qi);
            q = max(-127, min(127, q));
            g_xp_s8[dst] = (int8_t)q;
            float vv = v * v;
#pragma unroll
            for (int off = 16; off; off >>= 1)
                vv += __shfl_xor_sync(0xffffffffu, vv, off);
            nsum[s] += vv;
        }
        __syncthreads();
    }
    if (lane == 0) {
#pragma unroll
        for (int s = 0; s < 4; s++)
            g_norm[b * HWW + h * 32 + (tid >> 5) + s * 8] = sqrtf(nsum[s]);
    }
}

// ================= K2a: int8 ranking conv, row-batched A ====================
// smem: B slab 2x10240=20480 ; A row ring 3 x 36864 = 110592 ; total 131072
#define S8_BSLAB 0u
#define S8_BSTR  10240u
#define S8_A     20480u
#define S8_ROW   36864u
#define K2A_SMEM 131072
__global__ __launch_bounds__(256, 1) void k2a_s8(const float* __restrict__ cb) {
    extern __shared__ char smem[];
    uint32_t sb = smem_u32(smem);
    int tid = threadIdx.x, wid = tid >> 5, lane = tid & 31;
    int bh8  = blockIdx.x * 8;
    int pix0 = blockIdx.x * 256;
    int ocb  = blockIdx.y * 128;
    int b    = blockIdx.z;
    int mbase = (wid >> 2) * 64;
    int nbase = (wid & 3) * 64;

    int acc[4][8][4];
#pragma unroll
    for (int mt = 0; mt < 4; mt++)
#pragma unroll
        for (int nt = 0; nt < 8; nt++)
#pragma unroll
            for (int j = 0; j < 4; j++) acc[mt][nt][j] = 0;

    int r_ = tid >> 1, kc_ = tid & 1;
    for (int q = 0; q < 16; q++) {
        __syncthreads();
        // B slab: 640 px x 32B (2 chunk planes)
        for (int e = tid; e < 1280; e += 256) {
            int px = e >> 1, kc = e & 1;
            int pr = px / 40, pc = px - pr * 40;
            const int8_t* src = g_xp_s8 +
                ((size_t)((b * 40 + bh8 + pr) * 40 + pc)) * CC + q * 32 + kc * 16;
            CP_ASYNC16(sb + S8_BSLAB + (uint32_t)kc * S8_BSTR + (uint32_t)px * 16u,
                       (const void*)src);
        }
        CP_COMMIT();
        // prime A row 0 (taps 0..8) into ring buf 0
#pragma unroll
        for (int p = 0; p < 9; p++) {
            const int8_t* src = g_w_s8 + ((size_t)(p * OC + ocb + r_)) * CC + q * 32 + kc_ * 16;
            CP_ASYNC16(sb + S8_A + (uint32_t)p * 4096u + (uint32_t)kc_ * 2048u + (uint32_t)r_ * 16u,
                       (const void*)src);
        }
        CP_COMMIT();

        for (int dy = 0; dy < 9; dy++) {
            if (dy + 1 < 9) {
                uint32_t bufn = (uint32_t)((dy + 1) % 3) * S8_ROW;
#pragma unroll
                for (int p = 0; p < 9; p++) {
                    const int8_t* src = g_w_s8 +
                        ((size_t)(((dy + 1) * 9 + p) * OC + ocb + r_)) * CC + q * 32 + kc_ * 16;
                    CP_ASYNC16(sb + S8_A + bufn + (uint32_t)p * 4096u +
                               (uint32_t)kc_ * 2048u + (uint32_t)r_ * 16u, (const void*)src);
                }
            }
            CP_COMMIT();
            CP_WAIT1();
            __syncthreads();
            uint32_t rowbase = sb + S8_A + (uint32_t)(dy % 3) * S8_ROW;
            for (int dx = 0; dx < 9; dx++) {
                uint32_t abase = rowbase + (uint32_t)dx * 4096u;
                uint32_t a[4][4];
#pragma unroll
                for (int mt = 0; mt < 4; mt++) {
                    int arow = mbase + mt * 16 + (lane & 15);
                    int kcs = lane >> 4;
                    ldsm_x4(a[mt], abase + (uint32_t)kcs * 2048u + (uint32_t)arow * 16u);
                }
#pragma unroll
                for (int ntp = 0; ntp < 4; ntp++) {
                    int m = lane >> 3;
                    int n_ = nbase + ntp * 16 + ((m & 2) << 2) + (lane & 7);
                    int hl = n_ >> 5, w = n_ & 31;
                    int kcs = m & 1;
                    int px = (hl + dy) * 40 + (w + dx);
                    uint32_t bq[4];
                    ldsm_x4(bq, sb + S8_BSLAB + (uint32_t)kcs * S8_BSTR + (uint32_t)px * 16u);
#pragma unroll
                    for (int mt = 0; mt < 4; mt++) {
                        mma_s8(acc[mt][2 * ntp],     a[mt], bq);
                        mma_s8(acc[mt][2 * ntp + 1], a[mt], bq + 2);
                    }
                }
            }
        }
    }
    float s = (__uint_as_float(g_wmax_bits) * (1.f / 127.f)) *
              (__uint_as_float(g_xmax_bits) * (1.f / 127.f));
#pragma unroll
    for (int mt = 0; mt < 4; mt++) {
        int m0 = ocb + mbase + mt * 16 + (lane >> 2);
        float bi0 = cb[m0], bi1 = cb[m0 + 8];
        float* d0 = g_cap + ((size_t)(b * OC + m0)) * HWW + pix0;
        float* d1 = g_cap + ((size_t)(b * OC + m0 + 8)) * HWW + pix0;
#pragma unroll
        for (int nt = 0; nt < 8; nt++) {
            int n = nbase + nt * 8 + (lane & 3) * 2;
            d0[n]     = (float)acc[mt][nt][0] * s + bi0;
            d0[n + 1] = (float)acc[mt][nt][1] * s + bi0;
            d1[n]     = (float)acc[mt][nt][2] * s + bi1;
            d1[n + 1] = (float)acc[mt][nt][3] * s + bi1;
        }
    }
}

// ================= K4: squash + max over CAP_C ==============================
__global__ void k4_sqmax() {
    int i = blockIdx.x * 128 + threadIdx.x;
    int b = i >> 10, hw = i & 1023;
    const float* cp = g_cap + (size_t)b * OC * HWW + hw;
    float m[8];
#pragma unroll
    for (int k = 0; k < 8; k++) m[k] = -INFINITY;
    for (int c = 0; c < CAPC; c++) {
        float v[8]; float sq = 0.f;
#pragma unroll
        for (int k = 0; k < 8; k++) { v[k] = cp[(size_t)(k * CAPC + c) * HWW]; sq += v[k] * v[k]; }
        float s = sq / ((1.f + sq) * sqrtf(sq + 1e-8f));
#pragma unroll
        for (int k = 0; k < 8; k++) m[k] = fmaxf(m[k], v[k] * s);
    }
#pragma unroll
    for (int k = 0; k < 8; k++) g_cap4[(b * 8 + k) * HWW + hw] = m[k];
}

// ================= K5: top-8 candidate pixels per (b,k) =====================
__global__ void k5_top8() {
    int bk = blockIdx.x;
    int b = bk >> 3, k = bk & 7;
    __shared__ float val[1024];
    __shared__ float sv[256];
    __shared__ int   si[256];
    int tid = threadIdx.x;
    for (int hw = tid; hw < HWW; hw += 256) val[hw] = g_cap4[bk * HWW + hw];
    __syncthreads();
    for (int j = 0; j < TOPK; j++) {
        float best = -INFINITY; int bi = 0x7fffffff;
        for (int hw = tid; hw < HWW; hw += 256) {
            float v = val[hw];
            if (v > best || (v == best && hw < bi)) { best = v; bi = hw; }
        }
        sv[tid] = best; si[tid] = bi;
        __syncthreads();
        for (int s = 128; s > 0; s >>= 1) {
            if (tid < s) {
                if (sv[tid + s] > sv[tid] ||
                    (sv[tid + s] == sv[tid] && si[tid + s] < si[tid])) {
                    sv[tid] = sv[tid + s]; si[tid] = si[tid + s];
                }
            }
            __syncthreads();
        }
        if (tid == 0) {
            g_slots[b * SLOTS + k * TOPK + j] = si[0];
            val[si[0]] = -INFINITY;
        }
        __syncthreads();
    }
}

// ================= K2b: 3-term exact rescore, split-K=8 =====================
#define RB_STG 24576u
#define K2B_SMEM 49664
__global__ __launch_bounds__(256, 1) void k2b_rescore() {
    extern __shared__ char smem[];
    uint32_t sb = smem_u32(smem);
    int* s_slots = (int*)(smem + 49152);
    int tid = threadIdx.x, wid = tid >> 5, lane = tid & 31;
    int qs  = blockIdx.x;
    int ocb = blockIdx.y * 128;
    int b   = blockIdx.z;
    int mbase = (wid >> 1) * 32;
    int nbase = (wid & 1) * 32;

    if (tid < SLOTS) s_slots[tid] = g_slots[b * SLOTS + tid];
    __syncthreads();

    float acc[2][4][4];
#pragma unroll
    for (int mt = 0; mt < 2; mt++)
#pragma unroll
        for (int nt = 0; nt < 4; nt++)
#pragma unroll
            for (int j = 0; j < 4; j++) acc[mt][nt][j] = 0.f;

    auto issue = [&](int it, int s) {
        int q = qs * 2 + it / 81;
        int tap = it - (it / 81) * 81;
        int dy = tap / 9, dx = tap - dy * 9;
        uint32_t stg = sb + (uint32_t)s * RB_STG;
#pragma unroll
        for (int p = 0; p < 4; p++) {
            int e = tid + p * 256;
            int plane = e >> 9, r = (e >> 2) & 127, kc = e & 3;
            size_t gsrc = ((size_t)(tap * OC + ocb + r)) * CC + q * 32 + kc * 8;
            const __nv_bfloat16* src = (plane ? g_w_lo : g_w_hi) + gsrc;
            CP_ASYNC16(stg + (uint32_t)plane * 8192u + swz64((uint32_t)(r * 64 + kc * 16)),
                       (const void*)src);
        }
#pragma unroll
        for (int p = 0; p < 2; p++) {
            int e = tid + p * 256;
            int plane = (e >> 8) & 1, row = (e >> 2) & 63, kc = e & 3;
            int pix = s_slots[row];
            int y = pix >> 5, x = pix & 31;
            size_t gsrc = ((size_t)((b * 40 + y + dy) * 40 + (x + dx))) * CC + q * 32 + kc * 8;
            const __nv_bfloat16* src = (plane ? g_xp_lo : g_xp_hi) + gsrc;
            CP_ASYNC16(stg + 16384u + (uint32_t)plane * 4096u + swz64((uint32_t)(row * 64 + kc * 16)),
                       (const void*)src);
        }
    };

    issue(0, 0);
    CP_COMMIT();
    const int NIT = 2 * TAPS;
    for (int it = 0; it < NIT; it++) {
        int s = it & 1;
        if (it + 1 < NIT) issue(it + 1, s ^ 1);
        CP_COMMIT();
        CP_WAIT1();
        __syncthreads();
        uint32_t stg = sb + (uint32_t)s * RB_STG;
#pragma unroll
        for (int kb = 0; kb < 2; kb++) {
            uint32_t ah[2][4], al[2][4];
#pragma unroll
            for (int mt = 0; mt < 2; mt++) {
                int arow = mbase + mt * 16 + (lane & 15);
                int kcs = kb * 2 + (lane >> 4);
                uint32_t so = swz64((uint32_t)(arow * 64 + kcs * 16));
                ldsm_x4(ah[mt], stg + so);
                ldsm_x4(al[mt], stg + 8192u + so);
            }
#pragma unroll
            for (int ntp = 0; ntp < 2; ntp++) {
                int m = lane >> 3;
                int row = nbase + ntp * 16 + ((m & 2) << 2) + (lane & 7);
                int kcs = kb * 2 + (m & 1);
                uint32_t so = swz64((uint32_t)(row * 64 + kcs * 16));
                uint32_t bh[4], bl[4];
                ldsm_x4(bh, stg + 16384u + so);
                ldsm_x4(bl, stg + 16384u + 4096u + so);
#pragma unroll
                for (int mt = 0; mt < 2; mt++) {
                    mma_bf16(acc[mt][2 * ntp],     ah[mt], bh);
                    mma_bf16(acc[mt][2 * ntp],     ah[mt], bl);
                    mma_bf16(acc[mt][2 * ntp],     al[mt], bh);
                    mma_bf16(acc[mt][2 * ntp + 1], ah[mt], bh + 2);
                    mma_bf16(acc[mt][2 * ntp + 1], ah[mt], bl + 2);
                    mma_bf16(acc[mt][2 * ntp + 1], al[mt], bh + 2);
                }
            }
        }
        __syncthreads();
    }
#pragma unroll
    for (int mt = 0; mt < 2; mt++) {
        int m0 = ocb + mbase + mt * 16 + (lane >> 2);
        float* d0 = g_rpart + ((size_t)((qs * BB + b) * OC + m0)) * SLOTS;
        float* d1 = d0 + 8 * SLOTS;
#pragma unroll
        for (int nt = 0; nt < 4; nt++) {
            int n = nbase + nt * 8 + (lane & 3) * 2;
            d0[n]     = acc[mt][nt][0];
            d0[n + 1] = acc[mt][nt][1];
            d1[n]     = acc[mt][nt][2];
            d1[n + 1] = acc[mt][nt][3];
        }
    }
}

// ================= K2c ======================================================
#define K2C_SMEM (OC * SLOTS * 4 + NCAPS * SLOTS * 4 + SLOTS * 4)
__global__ __launch_bounds__(256) void k2c_pick(const float* __restrict__ cb) {
    extern __shared__ char smem[];
    float* v     = (float*)smem;
    float* sval  = (float*)(smem + OC * SLOTS * 4);
    int*   sl    = (int*)(smem + OC * SLOTS * 4 + NCAPS * SLOTS * 4);
    int b = blockIdx.x, tid = threadIdx.x;
    if (tid < SLOTS) sl[tid] = g_slots[b * SLOTS + tid];
    for (int idx = tid; idx < OC * SLOTS; idx += 256) {
        int oc = idx >> 6;
        float s = cb[oc];
#pragma unroll
        for (int qs = 0; qs < KSPLIT; qs++)
            s += g_rpart[((size_t)((qs * BB + b) * OC)) * SLOTS + idx];
        v[idx] = s;
    }
    __syncthreads();
    if (tid < SLOTS) {
        float mk[8];
#pragma unroll
        for (int k = 0; k < 8; k++) mk[k] = -INFINITY;
        for (int c = 0; c < CAPC; c++) {
            float vv[8]; float sq = 0.f;
#pragma unroll
            for (int k = 0; k < 8; k++) {
                vv[k] = v[(k * CAPC + c) * SLOTS + tid];
                sq += vv[k] * vv[k];
            }
            float sf = sq / ((1.f + sq) * sqrtf(sq + 1e-8f));
#pragma unroll
            for (int k = 0; k < 8; k++) mk[k] = fmaxf(mk[k], vv[k] * sf);
        }
#pragma unroll
        for (int k = 0; k < 8; k++) sval[k * SLOTS + tid] = mk[k];
    }
    __syncthreads();
    if (tid < NCAPS) {
        float best = -INFINITY; int bp = 0x7fffffff;
        for (int s = 0; s < SLOTS; s++) {
            float vv = sval[tid * SLOTS + s];
            int px = sl[s];
            if (vv > best || (vv == best && px < bp)) { best = vv; bp = px; }
        }
        g_idx[b * NCAPS + tid] = bp;
    }
}

// ================= K6..K12 (exact path) =====================================
__global__ void k6_smean() {
    int i = blockIdx.x * 256 + threadIdx.x;
    int c = i >> 3, k = i & 7;
    float s = 0.f;
    for (int b = 0; b < BB; b++) {
        int hw = g_idx[b * 8 + k];
        float n = fmaxf(g_norm[b * HWW + hw], 1e-12f);
        s += g_x[((size_t)(b * CC + c)) * HWW + hw] / n;
    }
    g_smean[c * 8 + k] = s * (1.f / 16.f);
}

__global__ __launch_bounds__(128) void k7_cm() {
    __shared__ float ss[CC * 8];
    for (int e = threadIdx.x; e < CC * 8; e += 128) ss[e] = g_smean[e];
    __syncthreads();
    int i = blockIdx.x * 128 + threadIdx.x;
    int b = i >> 10, hw = i & 1023;
    const float* xp = g_x + (size_t)b * CC * HWW + hw;
    float acc[8] = {};
    for (int c = 0; c < CC; c++) {
        float xv = xp[c * HWW];
#pragma unroll
        for (int k = 0; k < 8; k++) acc[k] += xv * ss[c * 8 + k];
    }
    float inv = 1.f / fmaxf(g_norm[i], 1e-12f);
#pragma unroll
    for (int k = 0; k < 8; k++) g_cm[(b * 8 + k) * HWW + hw] = acc[k] * inv;
}

__global__ void k8_minmax() {
    int bk = blockIdx.x;
    __shared__ float smn[256], smx[256];
    int tid = threadIdx.x;
    float mn = INFINITY, mx = -INFINITY;
    for (int hw = tid; hw < HWW; hw += 256) {
        float v = g_cm[bk * HWW + hw];
        mn = fminf(mn, v); mx = fmaxf(mx, v);
    }
    smn[tid] = mn; smx[tid] = mx;
    __syncthreads();
    for (int s = 128; s > 0; s >>= 1) {
        if (tid < s) {
            smn[tid] = fminf(smn[tid], smn[tid + s]);
            smx[tid] = fmaxf(smx[tid], smx[tid + s]);
        }
        __syncthreads();
    }
    if (tid == 0) { g_mm[bk * 2] = smn[0]; g_mm[bk * 2 + 1] = smx[0]; }
}

__global__ void k9_cmnorm() {
    int i = blockIdx.x * 128 + threadIdx.x;
    int b = i >> 10, hw = i & 1023;
    float s = 0.f;
#pragma unroll
    for (int k = 0; k < 8; k++) {
        int bk = b * 8 + k;
        float mn = g_mm[bk * 2], mx = g_mm[bk * 2 + 1];
        float v = (g_cm[bk * HWW + hw] - mn) / (mx - mn + 1e-12f);
        g_cm[bk * HWW + hw] = v;
        s += v;
    }
    g_cmmean[i] = s * 0.125f;
}

// ================= K10: proto, 8 channels per block =========================
__global__ __launch_bounds__(256) void k10_proto() {
    int c0 = blockIdx.x * 8;
    int tid = threadIdx.x, wid = tid >> 5, lane = tid & 31;
    float acc[8][8];
#pragma unroll
    for (int cl = 0; cl < 8; cl++)
#pragma unroll
        for (int k = 0; k < 8; k++) acc[cl][k] = 0.f;
    for (int i = tid; i < BB * HWW; i += 256) {
        int b = i >> 10, hw = i & 1023;
        float cmv[8];
#pragma unroll
        for (int k = 0; k < 8; k++) cmv[k] = g_cm[(b * 8 + k) * HWW + hw];
#pragma unroll
        for (int cl = 0; cl < 8; cl++) {
            float xv = g_x[((size_t)(b * CC + c0 + cl)) * HWW + hw];
#pragma unroll
            for (int k = 0; k < 8; k++) acc[cl][k] += xv * cmv[k];
        }
    }
    __shared__ float wred[8][64];
#pragma unroll
    for (int cl = 0; cl < 8; cl++)
#pragma unroll
        for (int k = 0; k < 8; k++) {
            float v = acc[cl][k];
#pragma unroll
            for (int off = 16; off; off >>= 1)
                v += __shfl_xor_sync(0xffffffffu, v, off);
            if (lane == 0) wred[wid][cl * 8 + k] = v;
        }
    __syncthreads();
    if (tid < 64) {
        float s = 0.f;
#pragma unroll
        for (int w = 0; w < 8; w++) s += wred[w][tid];
        int cl = tid >> 3, k = tid & 7;
        g_proto[k * CC + c0 + cl] = s * (1.f / (BB * HWW));
    }
}

__global__ void k11_pm(float* __restrict__ out) {
    int c = threadIdx.x;
    float s = 0.f;
#pragma unroll
    for (int k = 0; k < 8; k++) s += g_proto[k * CC + c];
    s *= 0.125f;
    g_pm[c] = s;
    __shared__ float red[512];
    red[c] = s * s;
    __syncthreads();
    for (int st = 256; st > 0; st >>= 1) {
        if (c < st) red[c] += red[c + st];
        __syncthreads();
    }
    float nrm = fmaxf(sqrtf(red[0]), 1e-12f);
    out[c] = s / nrm;
}

__global__ __launch_bounds__(128) void k12_out(float* __restrict__ out) {
    __shared__ float spm[CC];
    for (int e = threadIdx.x; e < CC; e += 128) spm[e] = g_pm[e];
    __syncthreads();
    int i = blockIdx.x * 128 + threadIdx.x;
    int b = i >> 10, hw = i & 1023;
    float cmm = g_cmmean[i];
    const float* xp = g_x + (size_t)b * CC * HWW + hw;
    float ss2 = 0.f;
    for (int c = 0; c < CC; c++) {
        float v = xp[c * HWW] * (spm[c] + cmm);
        ss2 += v * v;
    }
    float inv = 1.f / fmaxf(sqrtf(ss2), 1e-12f);
    float* op = out + CC + (size_t)b * CC * HWW + hw;
    for (int c = 0; c < CC; c++)
        op[c * HWW] = xp[c * HWW] * (spm[c] + cmm) * inv;
}

// ================= launcher ==================================================
extern "C" void kernel_launch(void* const* d_in, const int* in_sizes, int n_in,
                              void* d_out, int out_size) {
    const float* x5     = (const float*)d_in[0];
    const float* conv_w = (const float*)d_in[1];
    const float* conv_b = (const float*)d_in[2];
    const float* caps_w = (const float*)d_in[3];
    const float* caps_b = (const float*)d_in[4];
    float* out = (float*)d_out;
    (void)in_sizes; (void)n_in; (void)out_size;

    cudaFuncSetAttribute(k1_mma,      cudaFuncAttributeMaxDynamicSharedMemorySize, K1_SMEM);
    cudaFuncSetAttribute(k2a_s8,      cudaFuncAttributeMaxDynamicSharedMemorySize, K2A_SMEM);
    cudaFuncSetAttribute(k2b_rescore, cudaFuncAttributeMaxDynamicSharedMemorySize, K2B_SMEM);
    cudaFuncSetAttribute(k2c_pick,    cudaFuncAttributeMaxDynamicSharedMemorySize, K2C_SMEM);

    kp_w1   <<<1024, 256>>>(conv_w);
    kp5     <<<dim3(32, 16), 256>>>(x5);
    kp_w    <<<2048, 256>>>(caps_w);
    kp_wq   <<<5184, 256>>>();
    kp_xz   <<<6400, 256>>>();
    k1_mma  <<<dim3(4, 4, 16), 256, K1_SMEM>>>(x5, conv_b);
    kp_x    <<<dim3(32, 16), 256>>>();
    k2a_s8  <<<dim3(4, 2, 16), 256, K2A_SMEM>>>(caps_b);
    k4_sqmax<<<128, 128>>>();
    k5_top8 <<<128, 256>>>();
    k2b_rescore<<<dim3(KSPLIT, 2, 16), 256, K2B_SMEM>>>();
    k2c_pick<<<16, 256, K2C_SMEM>>>(caps_b);
    k6_smean<<<16, 256>>>();
    k7_cm   <<<128, 128>>>();
    k8_minmax<<<128, 256>>>();
    k9_cmnorm<<<128, 128>>>();
    k10_proto<<<64, 256>>>();
    k11_pm  <<<1, 512>>>(out);
    k12_out <<<128, 128>>>(out);
}

// round 13
// speedup vs baseline: 8.1266x; 1.0279x over previous
#include <cuda_runtime.h>
#include <cuda_bf16.h>
#include <math.h>
#include <stdint.h>

#define BB   16
#define CC   512
#define HWW  1024
#define NCAPS 8
#define CAPC 32
#define OC   256
#define TAPS 81
#define SLOTS 64
#define TOPK  8
#define KSPLIT 8

// ================= helpers =================
__device__ __forceinline__ uint32_t smem_u32(const void* p) {
    uint32_t a;
    asm("{ .reg .u64 t; cvta.to.shared.u64 t, %1; cvt.u32.u64 %0, t; }" : "=r"(a) : "l"(p));
    return a;
}
#define CP_ASYNC16(dst, src) \
    asm volatile("cp.async.cg.shared.global [%0], [%1], 16;" :: "r"(dst), "l"(src) : "memory")
#define CP_COMMIT() asm volatile("cp.async.commit_group;" ::: "memory")
#define CP_WAIT0()  asm volatile("cp.async.wait_group 0;" ::: "memory")
#define CP_WAIT1()  asm volatile("cp.async.wait_group 1;" ::: "memory")

__device__ __forceinline__ void ldsm_x4(uint32_t* r, uint32_t addr) {
    asm volatile("ldmatrix.sync.aligned.m8n8.x4.shared.b16 {%0,%1,%2,%3}, [%4];"
                 : "=r"(r[0]), "=r"(r[1]), "=r"(r[2]), "=r"(r[3]) : "r"(addr));
}
__device__ __forceinline__ void mma_bf16(float* c, const uint32_t* a, const uint32_t* b) {
    asm volatile("mma.sync.aligned.m16n8k16.row.col.f32.bf16.bf16.f32 "
                 "{%0,%1,%2,%3}, {%4,%5,%6,%7}, {%8,%9}, {%0,%1,%2,%3};"
                 : "+f"(c[0]), "+f"(c[1]), "+f"(c[2]), "+f"(c[3])
                 : "r"(a[0]), "r"(a[1]), "r"(a[2]), "r"(a[3]), "r"(b[0]), "r"(b[1]));
}
__device__ __forceinline__ void mma_s8(int* c, const uint32_t* a, const uint32_t* b) {
    asm volatile("mma.sync.aligned.m16n8k32.row.col.s32.s8.s8.s32 "
                 "{%0,%1,%2,%3}, {%4,%5,%6,%7}, {%8,%9}, {%0,%1,%2,%3};"
                 : "+r"(c[0]), "+r"(c[1]), "+r"(c[2]), "+r"(c[3])
                 : "r"(a[0]), "r"(a[1]), "r"(a[2]), "r"(a[3]), "r"(b[0]), "r"(b[1]));
}
__device__ __forceinline__ uint32_t swz64(uint32_t o) { return o ^ ((o >> 3) & 0x70); }

// ================= scratch =================
__device__ __align__(128) float g_x[BB * CC * HWW];
__device__ __align__(128) float g_cap[(size_t)BB * OC * HWW];
__device__ float g_cap4[BB * NCAPS * HWW];
__device__ int   g_idx[BB * NCAPS];
__device__ int   g_slots[BB * SLOTS];
__device__ float g_rpart[KSPLIT * BB * OC * SLOTS];
__device__ float g_norm[BB * HWW];
__device__ float g_smean[CC * NCAPS];
__device__ float g_cm[BB * NCAPS * HWW];
__device__ float g_mm[BB * NCAPS * 2];
__device__ float g_cmmean[BB * HWW];
__device__ float g_proto[NCAPS * CC];
__device__ float g_pm[CC];
__device__ __align__(128) __nv_bfloat16 g_w_hi[TAPS * OC * CC];
__device__ __align__(128) __nv_bfloat16 g_w_lo[TAPS * OC * CC];
// halo regions of the padded planes are NEVER written -> stay zero from BSS init
__device__ __align__(128) __nv_bfloat16 g_xp_hi[BB * 40 * 40 * CC];
__device__ __align__(128) __nv_bfloat16 g_xp_lo[BB * 40 * 40 * CC];
__device__ __align__(128) int8_t g_w_s8[TAPS * OC * CC];
__device__ __align__(128) int8_t g_xp_s8[BB * 40 * 40 * CC];
__device__ unsigned int g_wmax_bits;
__device__ unsigned int g_xmax_bits;
__device__ __align__(128) __nv_bfloat16 g_cw_hi[CC * CC];
__device__ __align__(128) __nv_bfloat16 g_cw_lo[CC * CC];
__device__ __align__(128) __nv_bfloat16 g_x5t_hi[BB * HWW * CC];
__device__ __align__(128) __nv_bfloat16 g_x5t_lo[BB * HWW * CC];

// ================= KP_PRE: kp5 (blocks 0..511) + kp_w1 (blocks 512..1535) ===
__global__ __launch_bounds__(256) void kp_pre(const float* __restrict__ x5,
                                              const float* __restrict__ w) {
    __shared__ float tile[32][33];
    int tid = threadIdx.x;
    if (blockIdx.x >= 512) {
        int i = (blockIdx.x - 512) * 256 + tid;
        float v = w[i];
        __nv_bfloat16 h = __float2bfloat16(v);
        g_cw_hi[i] = h;
        g_cw_lo[i] = __float2bfloat16(v - __bfloat162float(h));
        return;
    }
    int b = blockIdx.x >> 5, h = blockIdx.x & 31;
    for (int c0 = 0; c0 < CC; c0 += 32) {
#pragma unroll
        for (int s = 0; s < 4; s++) {
            int cl = (tid >> 5) + s * 8, w_ = tid & 31;
            tile[cl][w_] = x5[((size_t)(b * CC + c0 + cl)) * HWW + h * 32 + w_];
        }
        __syncthreads();
#pragma unroll
        for (int s = 0; s < 4; s++) {
            int wl = (tid >> 5) + s * 8, ci = tid & 31;
            float v = tile[ci][wl];
            size_t dst = ((size_t)(b * HWW + h * 32 + wl)) * CC + c0 + ci;
            __nv_bfloat16 hh = __float2bfloat16(v);
            g_x5t_hi[dst] = hh;
            g_x5t_lo[dst] = __float2bfloat16(v - __bfloat162float(hh));
        }
        __syncthreads();
    }
}

// ================= K1: split-bf16 mma ======================================
#define K1_STG 49152u
#define K1_SMEM 98304
__global__ __launch_bounds__(256, 1) void k1_mma(const float* __restrict__ x5,
                                                 const float* __restrict__ bias) {
    extern __shared__ char smem[];
    uint32_t sb = smem_u32(smem);
    int tid = threadIdx.x, wid = tid >> 5, lane = tid & 31;
    int pix0 = blockIdx.x * 256;
    int ocb  = blockIdx.y * 128;
    int b    = blockIdx.z;
    int mbase = (wid >> 2) * 64;
    int nbase = (wid & 3) * 64;

    float acc[4][8][4];
#pragma unroll
    for (int mt = 0; mt < 4; mt++)
#pragma unroll
        for (int nt = 0; nt < 8; nt++)
#pragma unroll
            for (int j = 0; j < 4; j++) acc[mt][nt][j] = 0.f;

    auto issue = [&](int kch, int s) {
        uint32_t stg = sb + (uint32_t)s * K1_STG;
#pragma unroll
        for (int p = 0; p < 4; p++) {
            int e = tid + p * 256;
            int plane = e >> 9, r = (e >> 2) & 127, kc = e & 3;
            size_t gsrc = (size_t)(ocb + r) * CC + kch * 32 + kc * 8;
            const __nv_bfloat16* src = (plane ? g_cw_lo : g_cw_hi) + gsrc;
            CP_ASYNC16(stg + (uint32_t)plane * 8192u + swz64((uint32_t)(r * 64 + kc * 16)),
                       (const void*)src);
        }
#pragma unroll
        for (int p = 0; p < 8; p++) {
            int e = tid + p * 256;
            int plane = e >> 10, row = (e >> 2) & 255, kc = e & 3;
            size_t gsrc = ((size_t)(b * HWW + pix0 + row)) * CC + kch * 32 + kc * 8;
            const __nv_bfloat16* src = (plane ? g_x5t_lo : g_x5t_hi) + gsrc;
            CP_ASYNC16(stg + 16384u + (uint32_t)plane * 16384u + swz64((uint32_t)(row * 64 + kc * 16)),
                       (const void*)src);
        }
    };

    issue(0, 0);
    CP_COMMIT();
    for (int kch = 0; kch < 16; kch++) {
        int s = kch & 1;
        if (kch + 1 < 16) issue(kch + 1, s ^ 1);
        CP_COMMIT();
        CP_WAIT1();
        __syncthreads();
        uint32_t stg = sb + (uint32_t)s * K1_STG;
#pragma unroll
        for (int kb = 0; kb < 2; kb++) {
            uint32_t ah[4][4], al[4][4];
#pragma unroll
            for (int mt = 0; mt < 4; mt++) {
                int arow = mbase + mt * 16 + (lane & 15);
                int kcs = kb * 2 + (lane >> 4);
                uint32_t so = swz64((uint32_t)(arow * 64 + kcs * 16));
                ldsm_x4(ah[mt], stg + so);
                ldsm_x4(al[mt], stg + 8192u + so);
            }
#pragma unroll
            for (int ntp = 0; ntp < 4; ntp++) {
                int m = lane >> 3;
                int row = nbase + ntp * 16 + ((m & 2) << 2) + (lane & 7);
                int kcs = kb * 2 + (m & 1);
                uint32_t so = swz64((uint32_t)(row * 64 + kcs * 16));
                uint32_t bh[4], bl[4];
                ldsm_x4(bh, stg + 16384u + so);
                ldsm_x4(bl, stg + 32768u + so);
#pragma unroll
                for (int mt = 0; mt < 4; mt++) {
                    mma_bf16(acc[mt][2 * ntp],     ah[mt], bh);
                    mma_bf16(acc[mt][2 * ntp],     ah[mt], bl);
                    mma_bf16(acc[mt][2 * ntp],     al[mt], bh);
                    mma_bf16(acc[mt][2 * ntp + 1], ah[mt], bh + 2);
                    mma_bf16(acc[mt][2 * ntp + 1], ah[mt], bl + 2);
                    mma_bf16(acc[mt][2 * ntp + 1], al[mt], bh + 2);
                }
            }
        }
        __syncthreads();
    }
    float am = 0.f;
#pragma unroll
    for (int mt = 0; mt < 4; mt++) {
        int m0 = ocb + mbase + mt * 16 + (lane >> 2);
        float bi0 = bias[m0], bi1 = bias[m0 + 8];
        size_t base0 = ((size_t)(b * CC + m0)) * HWW + pix0;
        size_t base1 = ((size_t)(b * CC + m0 + 8)) * HWW + pix0;
#pragma unroll
        for (int nt = 0; nt < 8; nt++) {
            int n = nbase + nt * 8 + (lane & 3) * 2;
            float v0 = acc[mt][nt][0] + bi0 + x5[base0 + n];
            float v1 = acc[mt][nt][1] + bi0 + x5[base0 + n + 1];
            float v2 = acc[mt][nt][2] + bi1 + x5[base1 + n];
            float v3 = acc[mt][nt][3] + bi1 + x5[base1 + n + 1];
            g_x[base0 + n]     = v0;
            g_x[base0 + n + 1] = v1;
            g_x[base1 + n]     = v2;
            g_x[base1 + n + 1] = v3;
            am = fmaxf(am, fmaxf(fmaxf(fabsf(v0), fabsf(v1)), fmaxf(fabsf(v2), fabsf(v3))));
        }
    }
#pragma unroll
    for (int off = 16; off; off >>= 1)
        am = fmaxf(am, __shfl_xor_sync(0xffffffffu, am, off));
    if (lane == 0) atomicMax(&g_xmax_bits, __float_as_uint(am));
}

// ================= KPW ======================================================
__global__ __launch_bounds__(256) void kp_w(const float* __restrict__ cw) {
    __shared__ float tile[64 * 81];
    __shared__ float red[256];
    int o  = blockIdx.x >> 3;
    int c0 = (blockIdx.x & 7) * 64;
    int tid = threadIdx.x;
    for (int e = tid; e < 64 * 81; e += 256) {
        int c_l = e / 81, t = e - c_l * 81;
        tile[e] = cw[((size_t)o * CC + c0 + c_l) * TAPS + t];
    }
    __syncthreads();
    float amax = 0.f;
    for (int e = tid; e < 81 * 64; e += 256) {
        int t = e >> 6, c_l = e & 63;
        float v = tile[c_l * 81 + t];
        amax = fmaxf(amax, fabsf(v));
        __nv_bfloat16 h = __float2bfloat16(v);
        size_t di = ((size_t)(t * OC + o)) * CC + c0 + c_l;
        g_w_hi[di] = h;
        g_w_lo[di] = __float2bfloat16(v - __bfloat162float(h));
    }
    red[tid] = amax;
    __syncthreads();
    for (int s = 128; s > 0; s >>= 1) {
        if (tid < s) red[tid] = fmaxf(red[tid], red[tid + s]);
        __syncthreads();
    }
    if (tid == 0) atomicMax(&g_wmax_bits, __float_as_uint(red[0]));
}

// ================= KP_WQ ====================================================
__global__ void kp_wq() {
    float qi = 127.f / __uint_as_float(g_wmax_bits);
    int i = blockIdx.x * 256 + threadIdx.x;
    uint4 h = ((const uint4*)g_w_hi)[i];
    uint4 l = ((const uint4*)g_w_lo)[i];
    const __nv_bfloat16* hp = (const __nv_bfloat16*)&h;
    const __nv_bfloat16* lp = (const __nv_bfloat16*)&l;
    char r[8];
#pragma unroll
    for (int j = 0; j < 8; j++) {
        float v = __bfloat162float(hp[j]) + __bfloat162float(lp[j]);
        int q = __float2int_rn(v * qi);
        q = max(-127, min(127, q));
        r[j] = (char)q;
    }
    ((uint2*)g_w_s8)[i] = *(uint2*)r;
}

// ================= KPX ======================================================
__global__ __launch_bounds__(256) void kp_x() {
    __shared__ float tile[32][33];
    int b = blockIdx.y, h = blockIdx.x;
    int tid = threadIdx.x;
    int lane = tid & 31;
    float qi = 127.f / __uint_as_float(g_xmax_bits);
    float nsum[4] = {0.f, 0.f, 0.f, 0.f};
    for (int c0 = 0; c0 < CC; c0 += 32) {
#pragma unroll
        for (int s = 0; s < 4; s++) {
            int cl = (tid >> 5) + s * 8, w = tid & 31;
            tile[cl][w] = g_x[((size_t)(b * CC + c0 + cl)) * HWW + h * 32 + w];
        }
        __syncthreads();
#pragma unroll
        for (int s = 0; s < 4; s++) {
            int wl = (tid >> 5) + s * 8, ci = lane;
            float v = tile[ci][wl];
            size_t dst = ((size_t)((b * 40 + h + 4) * 40 + wl + 4)) * CC + c0 + ci;
            __nv_bfloat16 hh = __float2bfloat16(v);
            g_xp_hi[dst] = hh;
            g_xp_lo[dst] = __float2bfloat16(v - __bfloat162float(hh));
            int q = __float2int_rn(v * qi);
            q = max(-127, min(127, q));
            g_xp_s8[dst] = (int8_t)q;
            float vv = v * v;
#pragma unroll
            for (int off = 16; off; off >>= 1)
                vv += __shfl_xor_sync(0xffffffffu, vv, off);
            nsum[s] += vv;
        }
        __syncthreads();
    }
    if (lane == 0) {
#pragma unroll
        for (int s = 0; s < 4; s++)
            g_norm[b * HWW + h * 32 + (tid >> 5) + s * 8] = sqrtf(nsum[s]);
    }
}

// ================= K2a: int8 ranking conv, fully pipelined ==================
// smem: B 2 x 20480 + A ring 4 x 36864 = 188416
#define S8_BSTR  10240u
#define S8_BBUF  20480u
#define S8_ABASE 40960u
#define S8_ROW   36864u
#define K2A_SMEM 188416
__global__ __launch_bounds__(256, 1) void k2a_s8(const float* __restrict__ cb) {
    extern __shared__ char smem[];
    uint32_t sb = smem_u32(smem);
    int tid = threadIdx.x, wid = tid >> 5, lane = tid & 31;
    int bh8  = blockIdx.x * 8;
    int pix0 = blockIdx.x * 256;
    int ocb  = blockIdx.y * 128;
    int b    = blockIdx.z;
    int mbase = (wid >> 2) * 64;
    int nbase = (wid & 3) * 64;

    int acc[4][8][4];
#pragma unroll
    for (int mt = 0; mt < 4; mt++)
#pragma unroll
        for (int nt = 0; nt < 8; nt++)
#pragma unroll
            for (int j = 0; j < 4; j++) acc[mt][nt][j] = 0;

    int r_ = tid >> 1, kc_ = tid & 1;
    auto issueRow = [&](int R) {
        int q = R / 9, dy = R - q * 9;
        uint32_t buf = sb + S8_ABASE + (uint32_t)(R & 3) * S8_ROW;
#pragma unroll
        for (int p = 0; p < 9; p++) {
            const int8_t* src = g_w_s8 +
                ((size_t)((dy * 9 + p) * OC + ocb + r_)) * CC + q * 32 + kc_ * 16;
            CP_ASYNC16(buf + (uint32_t)p * 4096u + (uint32_t)kc_ * 2048u + (uint32_t)r_ * 16u,
                       (const void*)src);
        }
    };
    auto issueB = [&](int q) {
        uint32_t bbuf = sb + (uint32_t)(q & 1) * S8_BBUF;
        for (int e = tid; e < 1280; e += 256) {
            int px = e >> 1, kc = e & 1;
            int pr = px / 40, pc = px - pr * 40;
            const int8_t* src = g_xp_s8 +
                ((size_t)((b * 40 + bh8 + pr) * 40 + pc)) * CC + q * 32 + kc * 16;
            CP_ASYNC16(bbuf + (uint32_t)kc * S8_BSTR + (uint32_t)px * 16u, (const void*)src);
        }
    };

    issueB(0);
    issueRow(0);
    issueRow(1);
    CP_COMMIT();

    for (int R = 0; R < 144; R++) {
        int q = R / 9, dy = R - q * 9;
        if (R + 2 < 144) issueRow(R + 2);
        if (dy == 7 && q < 15) issueB(q + 1);
        CP_COMMIT();
        CP_WAIT1();
        __syncthreads();
        uint32_t rowbase = sb + S8_ABASE + (uint32_t)(R & 3) * S8_ROW;
        uint32_t bbase = sb + (uint32_t)(q & 1) * S8_BBUF;
        for (int dx = 0; dx < 9; dx++) {
            uint32_t abase = rowbase + (uint32_t)dx * 4096u;
            uint32_t a[4][4];
#pragma unroll
            for (int mt = 0; mt < 4; mt++) {
                int arow = mbase + mt * 16 + (lane & 15);
                int kcs = lane >> 4;
                ldsm_x4(a[mt], abase + (uint32_t)kcs * 2048u + (uint32_t)arow * 16u);
            }
#pragma unroll
            for (int ntp = 0; ntp < 4; ntp++) {
                int m = lane >> 3;
                int n_ = nbase + ntp * 16 + ((m & 2) << 2) + (lane & 7);
                int hl = n_ >> 5, w = n_ & 31;
                int kcs = m & 1;
                int px = (hl + dy) * 40 + (w + dx);
                uint32_t bq[4];
                ldsm_x4(bq, bbase + (uint32_t)kcs * S8_BSTR + (uint32_t)px * 16u);
#pragma unroll
                for (int mt = 0; mt < 4; mt++) {
                    mma_s8(acc[mt][2 * ntp],     a[mt], bq);
                    mma_s8(acc[mt][2 * ntp + 1], a[mt], bq + 2);
                }
            }
        }
    }
    float s = (__uint_as_float(g_wmax_bits) * (1.f / 127.f)) *
              (__uint_as_float(g_xmax_bits) * (1.f / 127.f));
#pragma unroll
    for (int mt = 0; mt < 4; mt++) {
        int m0 = ocb + mbase + mt * 16 + (lane >> 2);
        float bi0 = cb[m0], bi1 = cb[m0 + 8];
        float* d0 = g_cap + ((size_t)(b * OC + m0)) * HWW + pix0;
        float* d1 = g_cap + ((size_t)(b * OC + m0 + 8)) * HWW + pix0;
#pragma unroll
        for (int nt = 0; nt < 8; nt++) {
            int n = nbase + nt * 8 + (lane & 3) * 2;
            d0[n]     = (float)acc[mt][nt][0] * s + bi0;
            d0[n + 1] = (float)acc[mt][nt][1] * s + bi0;
            d1[n]     = (float)acc[mt][nt][2] * s + bi1;
            d1[n + 1] = (float)acc[mt][nt][3] * s + bi1;
        }
    }
}

// ================= K4: squash + max over CAP_C ==============================
__global__ void k4_sqmax() {
    int i = blockIdx.x * 128 + threadIdx.x;
    int b = i >> 10, hw = i & 1023;
    const float* cp = g_cap + (size_t)b * OC * HWW + hw;
    float m[8];
#pragma unroll
    for (int k = 0; k < 8; k++) m[k] = -INFINITY;
    for (int c = 0; c < CAPC; c++) {
        float v[8]; float sq = 0.f;
#pragma unroll
        for (int k = 0; k < 8; k++) { v[k] = cp[(size_t)(k * CAPC + c) * HWW]; sq += v[k] * v[k]; }
        float s = sq / ((1.f + sq) * sqrtf(sq + 1e-8f));
#pragma unroll
        for (int k = 0; k < 8; k++) m[k] = fmaxf(m[k], v[k] * s);
    }
#pragma unroll
    for (int k = 0; k < 8; k++) g_cap4[(b * 8 + k) * HWW + hw] = m[k];
}

// ================= K5: top-8 candidate pixels per (b,k) =====================
__global__ void k5_top8() {
    int bk = blockIdx.x;
    int b = bk >> 3, k = bk & 7;
    __shared__ float val[1024];
    __shared__ float sv[256];
    __shared__ int   si[256];
    int tid = threadIdx.x;
    for (int hw = tid; hw < HWW; hw += 256) val[hw] = g_cap4[bk * HWW + hw];
    __syncthreads();
    for (int j = 0; j < TOPK; j++) {
        float best = -INFINITY; int bi = 0x7fffffff;
        for (int hw = tid; hw < HWW; hw += 256) {
            float v = val[hw];
            if (v > best || (v == best && hw < bi)) { best = v; bi = hw; }
        }
        sv[tid] = best; si[tid] = bi;
        __syncthreads();
        for (int s = 128; s > 0; s >>= 1) {
            if (tid < s) {
                if (sv[tid + s] > sv[tid] ||
                    (sv[tid + s] == sv[tid] && si[tid + s] < si[tid])) {
                    sv[tid] = sv[tid + s]; si[tid] = si[tid + s];
                }
            }
            __syncthreads();
        }
        if (tid == 0) {
            g_slots[b * SLOTS + k * TOPK + j] = si[0];
            val[si[0]] = -INFINITY;
        }
        __syncthreads();
    }
}

// ================= K2b: 3-term exact rescore, split-K=8 =====================
#define RB_STG 24576u
#define K2B_SMEM 49664
__global__ __launch_bounds__(256, 1) void k2b_rescore() {
    extern __shared__ char smem[];
    uint32_t sb = smem_u32(smem);
    int* s_slots = (int*)(smem + 49152);
    int tid = threadIdx.x, wid = tid >> 5, lane = tid & 31;
    int qs  = blockIdx.x;
    int ocb = blockIdx.y * 128;
    int b   = blockIdx.z;
    int mbase = (wid >> 1) * 32;
    int nbase = (wid & 1) * 32;

    if (tid < SLOTS) s_slots[tid] = g_slots[b * SLOTS + tid];
    __syncthreads();

    float acc[2][4][4];
#pragma unroll
    for (int mt = 0; mt < 2; mt++)
#pragma unroll
        for (int nt = 0; nt < 4; nt++)
#pragma unroll
            for (int j = 0; j < 4; j++) acc[mt][nt][j] = 0.f;

    auto issue = [&](int it, int s) {
        int q = qs * 2 + it / 81;
        int tap = it - (it / 81) * 81;
        int dy = tap / 9, dx = tap - dy * 9;
        uint32_t stg = sb + (uint32_t)s * RB_STG;
#pragma unroll
        for (int p = 0; p < 4; p++) {
            int e = tid + p * 256;
            int plane = e >> 9, r = (e >> 2) & 127, kc = e & 3;
            size_t gsrc = ((size_t)(tap * OC + ocb + r)) * CC + q * 32 + kc * 8;
            const __nv_bfloat16* src = (plane ? g_w_lo : g_w_hi) + gsrc;
            CP_ASYNC16(stg + (uint32_t)plane * 8192u + swz64((uint32_t)(r * 64 + kc * 16)),
                       (const void*)src);
        }
#pragma unroll
        for (int p = 0; p < 2; p++) {
            int e = tid + p * 256;
            int plane = (e >> 8) & 1, row = (e >> 2) & 63, kc = e & 3;
            int pix = s_slots[row];
            int y = pix >> 5, x = pix & 31;
            size_t gsrc = ((size_t)((b * 40 + y + dy) * 40 + (x + dx))) * CC + q * 32 + kc * 8;
            const __nv_bfloat16* src = (plane ? g_xp_lo : g_xp_hi) + gsrc;
            CP_ASYNC16(stg + 16384u + (uint32_t)plane * 4096u + swz64((uint32_t)(row * 64 + kc * 16)),
                       (const void*)src);
        }
    };

    issue(0, 0);
    CP_COMMIT();
    const int NIT = 2 * TAPS;
    for (int it = 0; it < NIT; it++) {
        int s = it & 1;
        if (it + 1 < NIT) issue(it + 1, s ^ 1);
        CP_COMMIT();
        CP_WAIT1();
        __syncthreads();
        uint32_t stg = sb + (uint32_t)s * RB_STG;
#pragma unroll
        for (int kb = 0; kb < 2; kb++) {
            uint32_t ah[2][4], al[2][4];
#pragma unroll
            for (int mt = 0; mt < 2; mt++) {
                int arow = mbase + mt * 16 + (lane & 15);
                int kcs = kb * 2 + (lane >> 4);
                uint32_t so = swz64((uint32_t)(arow * 64 + kcs * 16));
                ldsm_x4(ah[mt], stg + so);
                ldsm_x4(al[mt], stg + 8192u + so);
            }
#pragma unroll
            for (int ntp = 0; ntp < 2; ntp++) {
                int m = lane >> 3;
                int row = nbase + ntp * 16 + ((m & 2) << 2) + (lane & 7);
                int kcs = kb * 2 + (m & 1);
                uint32_t so = swz64((uint32_t)(row * 64 + kcs * 16));
                uint32_t bh[4], bl[4];
                ldsm_x4(bh, stg + 16384u + so);
                ldsm_x4(bl, stg + 16384u + 4096u + so);
#pragma unroll
                for (int mt = 0; mt < 2; mt++) {
                    mma_bf16(acc[mt][2 * ntp],     ah[mt], bh);
                    mma_bf16(acc[mt][2 * ntp],     ah[mt], bl);
                    mma_bf16(acc[mt][2 * ntp],     al[mt], bh);
                    mma_bf16(acc[mt][2 * ntp + 1], ah[mt], bh + 2);
                    mma_bf16(acc[mt][2 * ntp + 1], ah[mt], bl + 2);
                    mma_bf16(acc[mt][2 * ntp + 1], al[mt], bh + 2);
                }
            }
        }
        __syncthreads();
    }
#pragma unroll
    for (int mt = 0; mt < 2; mt++) {
        int m0 = ocb + mbase + mt * 16 + (lane >> 2);
        float* d0 = g_rpart + ((size_t)((qs * BB + b) * OC + m0)) * SLOTS;
        float* d1 = d0 + 8 * SLOTS;
#pragma unroll
        for (int nt = 0; nt < 4; nt++) {
            int n = nbase + nt * 8 + (lane & 3) * 2;
            d0[n]     = acc[mt][nt][0];
            d0[n + 1] = acc[mt][nt][1];
            d1[n]     = acc[mt][nt][2];
            d1[n + 1] = acc[mt][nt][3];
        }
    }
}

// ================= K2c ======================================================
#define K2C_SMEM (OC * SLOTS * 4 + NCAPS * SLOTS * 4 + SLOTS * 4)
__global__ __launch_bounds__(256) void k2c_pick(const float* __restrict__ cb) {
    extern __shared__ char smem[];
    float* v     = (float*)smem;
    float* sval  = (float*)(smem + OC * SLOTS * 4);
    int*   sl    = (int*)(smem + OC * SLOTS * 4 + NCAPS * SLOTS * 4);
    int b = blockIdx.x, tid = threadIdx.x;
    if (tid < SLOTS) sl[tid] = g_slots[b * SLOTS + tid];
    for (int idx = tid; idx < OC * SLOTS; idx += 256) {
        int oc = idx >> 6;
        float s = cb[oc];
#pragma unroll
        for (int qs = 0; qs < KSPLIT; qs++)
            s += g_rpart[((size_t)((qs * BB + b) * OC)) * SLOTS + idx];
        v[idx] = s;
    }
    __syncthreads();
    if (tid < SLOTS) {
        float mk[8];
#pragma unroll
        for (int k = 0; k < 8; k++) mk[k] = -INFINITY;
        for (int c = 0; c < CAPC; c++) {
            float vv[8]; float sq = 0.f;
#pragma unroll
            for (int k = 0; k < 8; k++) {
                vv[k] = v[(k * CAPC + c) * SLOTS + tid];
                sq += vv[k] * vv[k];
            }
            float sf = sq / ((1.f + sq) * sqrtf(sq + 1e-8f));
#pragma unroll
            for (int k = 0; k < 8; k++) mk[k] = fmaxf(mk[k], vv[k] * sf);
        }
#pragma unroll
        for (int k = 0; k < 8; k++) sval[k * SLOTS + tid] = mk[k];
    }
    __syncthreads();
    if (tid < NCAPS) {
        float best = -INFINITY; int bp = 0x7fffffff;
        for (int s = 0; s < SLOTS; s++) {
            float vv = sval[tid * SLOTS + s];
            int px = sl[s];
            if (vv > best || (vv == best && px < bp)) { best = vv; bp = px; }
        }
        g_idx[b * NCAPS + tid] = bp;
    }
}

// ================= K6..K12 (exact path) =====================================
__global__ void k6_smean() {
    int i = blockIdx.x * 256 + threadIdx.x;
    int c = i >> 3, k = i & 7;
    float s = 0.f;
    for (int b = 0; b < BB; b++) {
        int hw = g_idx[b * 8 + k];
        float n = fmaxf(g_norm[b * HWW + hw], 1e-12f);
        s += g_x[((size_t)(b * CC + c)) * HWW + hw] / n;
    }
    g_smean[c * 8 + k] = s * (1.f / 16.f);
}

__global__ __launch_bounds__(128) void k7_cm() {
    __shared__ float ss[CC * 8];
    for (int e = threadIdx.x; e < CC * 8; e += 128) ss[e] = g_smean[e];
    __syncthreads();
    int i = blockIdx.x * 128 + threadIdx.x;
    int b = i >> 10, hw = i & 1023;
    const float* xp = g_x + (size_t)b * CC * HWW + hw;
    float acc[8] = {};
    for (int c = 0; c < CC; c++) {
        float xv = xp[c * HWW];
#pragma unroll
        for (int k = 0; k < 8; k++) acc[k] += xv * ss[c * 8 + k];
    }
    float inv = 1.f / fmaxf(g_norm[i], 1e-12f);
#pragma unroll
    for (int k = 0; k < 8; k++) g_cm[(b * 8 + k) * HWW + hw] = acc[k] * inv;
}

__global__ void k8_minmax() {
    int bk = blockIdx.x;
    __shared__ float smn[256], smx[256];
    int tid = threadIdx.x;
    float mn = INFINITY, mx = -INFINITY;
    for (int hw = tid; hw < HWW; hw += 256) {
        float v = g_cm[bk * HWW + hw];
        mn = fminf(mn, v); mx = fmaxf(mx, v);
    }
    smn[tid] = mn; smx[tid] = mx;
    __syncthreads();
    for (int s = 128; s > 0; s >>= 1) {
        if (tid < s) {
            smn[tid] = fminf(smn[tid], smn[tid + s]);
            smx[tid] = fmaxf(smx[tid], smx[tid + s]);
        }
        __syncthreads();
    }
    if (tid == 0) { g_mm[bk * 2] = smn[0]; g_mm[bk * 2 + 1] = smx[0]; }
}

__global__ void k9_cmnorm() {
    int i = blockIdx.x * 128 + threadIdx.x;
    int b = i >> 10, hw = i & 1023;
    float s = 0.f;
#pragma unroll
    for (int k = 0; k < 8; k++) {
        int bk = b * 8 + k;
        float mn = g_mm[bk * 2], mx = g_mm[bk * 2 + 1];
        float v = (g_cm[bk * HWW + hw] - mn) / (mx - mn + 1e-12f);
        g_cm[bk * HWW + hw] = v;
        s += v;
    }
    g_cmmean[i] = s * 0.125f;
}

__global__ __launch_bounds__(256) void k10_proto() {
    int c0 = blockIdx.x * 8;
    int tid = threadIdx.x, wid = tid >> 5, lane = tid & 31;
    float acc[8][8];
#pragma unroll
    for (int cl = 0; cl < 8; cl++)
#pragma unroll
        for (int k = 0; k < 8; k++) acc[cl][k] = 0.f;
    for (int i = tid; i < BB * HWW; i += 256) {
        int b = i >> 10, hw = i & 1023;
        float cmv[8];
#pragma unroll
        for (int k = 0; k < 8; k++) cmv[k] = g_cm[(b * 8 + k) * HWW + hw];
#pragma unroll
        for (int cl = 0; cl < 8; cl++) {
            float xv = g_x[((size_t)(b * CC + c0 + cl)) * HWW + hw];
#pragma unroll
            for (int k = 0; k < 8; k++) acc[cl][k] += xv * cmv[k];
        }
    }
    __shared__ float wred[8][64];
#pragma unroll
    for (int cl = 0; cl < 8; cl++)
#pragma unroll
        for (int k = 0; k < 8; k++) {
            float v = acc[cl][k];
#pragma unroll
            for (int off = 16; off; off >>= 1)
                v += __shfl_xor_sync(0xffffffffu, v, off);
            if (lane == 0) wred[wid][cl * 8 + k] = v;
        }
    __syncthreads();
    if (tid < 64) {
        float s = 0.f;
#pragma unroll
        for (int w = 0; w < 8; w++) s += wred[w][tid];
        int cl = tid >> 3, k = tid & 7;
        g_proto[k * CC + c0 + cl] = s * (1.f / (BB * HWW));
    }
}

__global__ void k11_pm(float* __restrict__ out) {
    int c = threadIdx.x;
    float s = 0.f;
#pragma unroll
    for (int k = 0; k < 8; k++) s += g_proto[k * CC + c];
    s *= 0.125f;
    g_pm[c] = s;
    __shared__ float red[512];
    red[c] = s * s;
    __syncthreads();
    for (int st = 256; st > 0; st >>= 1) {
        if (c < st) red[c] += red[c + st];
        __syncthreads();
    }
    float nrm = fmaxf(sqrtf(red[0]), 1e-12f);
    out[c] = s / nrm;
}

__global__ __launch_bounds__(128) void k12_out(float* __restrict__ out) {
    __shared__ float spm[CC];
    for (int e = threadIdx.x; e < CC; e += 128) spm[e] = g_pm[e];
    __syncthreads();
    int i = blockIdx.x * 128 + threadIdx.x;
    int b = i >> 10, hw = i & 1023;
    float cmm = g_cmmean[i];
    const float* xp = g_x + (size_t)b * CC * HWW + hw;
    float ss2 = 0.f;
    for (int c = 0; c < CC; c++) {
        float v = xp[c * HWW] * (spm[c] + cmm);
        ss2 += v * v;
    }
    float inv = 1.f / fmaxf(sqrtf(ss2), 1e-12f);
    float* op = out + CC + (size_t)b * CC * HWW + hw;
    for (int c = 0; c < CC; c++)
        op[c * HWW] = xp[c * HWW] * (spm[c] + cmm) * inv;
}

// ================= launcher ==================================================
extern "C" void kernel_launch(void* const* d_in, const int* in_sizes, int n_in,
                              void* d_out, int out_size) {
    const float* x5     = (const float*)d_in[0];
    const float* conv_w = (const float*)d_in[1];
    const float* conv_b = (const float*)d_in[2];
    const float* caps_w = (const float*)d_in[3];
    const float* caps_b = (const float*)d_in[4];
    float* out = (float*)d_out;
    (void)in_sizes; (void)n_in; (void)out_size;

    cudaFuncSetAttribute(k1_mma,      cudaFuncAttributeMaxDynamicSharedMemorySize, K1_SMEM);
    cudaFuncSetAttribute(k2a_s8,      cudaFuncAttributeMaxDynamicSharedMemorySize, K2A_SMEM);
    cudaFuncSetAttribute(k2b_rescore, cudaFuncAttributeMaxDynamicSharedMemorySize, K2B_SMEM);
    cudaFuncSetAttribute(k2c_pick,    cudaFuncAttributeMaxDynamicSharedMemorySize, K2C_SMEM);

    kp_pre  <<<1536, 256>>>(x5, conv_w);
    kp_w    <<<2048, 256>>>(caps_w);
    kp_wq   <<<5184, 256>>>();
    k1_mma  <<<dim3(4, 4, 16), 256, K1_SMEM>>>(x5, conv_b);
    kp_x    <<<dim3(32, 16), 256>>>();
    k2a_s8  <<<dim3(4, 2, 16), 256, K2A_SMEM>>>(caps_b);
    k4_sqmax<<<128, 128>>>();
    k5_top8 <<<128, 256>>>();
    k2b_rescore<<<dim3(KSPLIT, 2, 16), 256, K2B_SMEM>>>();
    k2c_pick<<<16, 256, K2C_SMEM>>>(caps_b);
    k6_smean<<<16, 256>>>();
    k7_cm   <<<128, 128>>>();
    k8_minmax<<<128, 256>>>();
    k9_cmnorm<<<128, 128>>>();
    k10_proto<<<64, 256>>>();
    k11_pm  <<<1, 512>>>(out);
    k12_out <<<128, 128>>>(out);
}

// round 14
// speedup vs baseline: 8.5135x; 1.0476x over previous
#include <cuda_runtime.h>
#include <cuda_bf16.h>
#include <math.h>
#include <stdint.h>

#define BB   16
#define CC   512
#define HWW  1024
#define NCAPS 8
#define CAPC 32
#define OC   256
#define TAPS 81
#define SLOTS 64
#define TOPK  8
#define KSPLIT 8

// ================= helpers =================
__device__ __forceinline__ uint32_t smem_u32(const void* p) {
    uint32_t a;
    asm("{ .reg .u64 t; cvta.to.shared.u64 t, %1; cvt.u32.u64 %0, t; }" : "=r"(a) : "l"(p));
    return a;
}
#define CP_ASYNC16(dst, src) \
    asm volatile("cp.async.cg.shared.global [%0], [%1], 16;" :: "r"(dst), "l"(src) : "memory")
#define CP_COMMIT() asm volatile("cp.async.commit_group;" ::: "memory")
#define CP_WAIT1()  asm volatile("cp.async.wait_group 1;" ::: "memory")

__device__ __forceinline__ void ldsm_x4(uint32_t* r, uint32_t addr) {
    asm volatile("ldmatrix.sync.aligned.m8n8.x4.shared.b16 {%0,%1,%2,%3}, [%4];"
                 : "=r"(r[0]), "=r"(r[1]), "=r"(r[2]), "=r"(r[3]) : "r"(addr));
}
__device__ __forceinline__ void mma_bf16(float* c, const uint32_t* a, const uint32_t* b) {
    asm volatile("mma.sync.aligned.m16n8k16.row.col.f32.bf16.bf16.f32 "
                 "{%0,%1,%2,%3}, {%4,%5,%6,%7}, {%8,%9}, {%0,%1,%2,%3};"
                 : "+f"(c[0]), "+f"(c[1]), "+f"(c[2]), "+f"(c[3])
                 : "r"(a[0]), "r"(a[1]), "r"(a[2]), "r"(a[3]), "r"(b[0]), "r"(b[1]));
}
__device__ __forceinline__ void mma_s8(int* c, const uint32_t* a, const uint32_t* b) {
    asm volatile("mma.sync.aligned.m16n8k32.row.col.s32.s8.s8.s32 "
                 "{%0,%1,%2,%3}, {%4,%5,%6,%7}, {%8,%9}, {%0,%1,%2,%3};"
                 : "+r"(c[0]), "+r"(c[1]), "+r"(c[2]), "+r"(c[3])
                 : "r"(a[0]), "r"(a[1]), "r"(a[2]), "r"(a[3]), "r"(b[0]), "r"(b[1]));
}
__device__ __forceinline__ uint32_t swz64(uint32_t o) { return o ^ ((o >> 3) & 0x70); }

// ================= scratch =================
__device__ __align__(128) float g_x[BB * CC * HWW];
__device__ __align__(128) float g_cap[(size_t)BB * OC * HWW];
__device__ float g_cap4[BB * NCAPS * HWW];
__device__ int   g_idx[BB * NCAPS];
__device__ int   g_slots[BB * SLOTS];
__device__ float g_rpart[KSPLIT * BB * OC * SLOTS];
__device__ float g_norm[BB * HWW];
__device__ float g_smean[CC * NCAPS];
__device__ float g_cm[BB * NCAPS * HWW];
__device__ float g_mm[BB * NCAPS * 2];
__device__ float g_cmmean[BB * HWW];
__device__ float g_proto[NCAPS * CC];
__device__ float g_pm[CC];
__device__ __align__(128) __nv_bfloat16 g_w_hi[TAPS * OC * CC];
__device__ __align__(128) __nv_bfloat16 g_w_lo[TAPS * OC * CC];
// int8 operands (halo of padded x planes never written -> zero from BSS)
__device__ __align__(128) int8_t g_w_s8[TAPS * OC * CC];     // ranking (scale 127)
__device__ __align__(128) int8_t g_w16h[TAPS * OC * CC];     // int16 rescore hi byte
__device__ __align__(128) int8_t g_w16l[TAPS * OC * CC];     // int16 rescore lo byte
__device__ __align__(128) int8_t g_xp_s8[BB * 40 * 40 * CC];
__device__ __align__(128) int8_t g_x16h[BB * 40 * 40 * CC];
__device__ __align__(128) int8_t g_x16l[BB * 40 * 40 * CC];
__device__ unsigned int g_wmax_bits;
__device__ unsigned int g_xmax_bits;
__device__ __align__(128) __nv_bfloat16 g_cw_hi[CC * CC];
__device__ __align__(128) __nv_bfloat16 g_cw_lo[CC * CC];
__device__ __align__(128) __nv_bfloat16 g_x5t_hi[BB * HWW * CC];
__device__ __align__(128) __nv_bfloat16 g_x5t_lo[BB * HWW * CC];

// ================= KP_PRE: kp5 (blocks 0..511) + kp_w1 (512..1535) ==========
__global__ __launch_bounds__(256) void kp_pre(const float* __restrict__ x5,
                                              const float* __restrict__ w) {
    __shared__ float tile[32][33];
    int tid = threadIdx.x;
    if (blockIdx.x >= 512) {
        int i = (blockIdx.x - 512) * 256 + tid;
        float v = w[i];
        __nv_bfloat16 h = __float2bfloat16(v);
        g_cw_hi[i] = h;
        g_cw_lo[i] = __float2bfloat16(v - __bfloat162float(h));
        return;
    }
    int b = blockIdx.x >> 5, h = blockIdx.x & 31;
    for (int c0 = 0; c0 < CC; c0 += 32) {
#pragma unroll
        for (int s = 0; s < 4; s++) {
            int cl = (tid >> 5) + s * 8, w_ = tid & 31;
            tile[cl][w_] = x5[((size_t)(b * CC + c0 + cl)) * HWW + h * 32 + w_];
        }
        __syncthreads();
#pragma unroll
        for (int s = 0; s < 4; s++) {
            int wl = (tid >> 5) + s * 8, ci = tid & 31;
            float v = tile[ci][wl];
            size_t dst = ((size_t)(b * HWW + h * 32 + wl)) * CC + c0 + ci;
            __nv_bfloat16 hh = __float2bfloat16(v);
            g_x5t_hi[dst] = hh;
            g_x5t_lo[dst] = __float2bfloat16(v - __bfloat162float(hh));
        }
        __syncthreads();
    }
}

// ================= K1: split-bf16 mma ======================================
#define K1_STG 49152u
#define K1_SMEM 98304
__global__ __launch_bounds__(256, 1) void k1_mma(const float* __restrict__ x5,
                                                 const float* __restrict__ bias) {
    extern __shared__ char smem[];
    uint32_t sb = smem_u32(smem);
    int tid = threadIdx.x, wid = tid >> 5, lane = tid & 31;
    int pix0 = blockIdx.x * 256;
    int ocb  = blockIdx.y * 128;
    int b    = blockIdx.z;
    int mbase = (wid >> 2) * 64;
    int nbase = (wid & 3) * 64;

    float acc[4][8][4];
#pragma unroll
    for (int mt = 0; mt < 4; mt++)
#pragma unroll
        for (int nt = 0; nt < 8; nt++)
#pragma unroll
            for (int j = 0; j < 4; j++) acc[mt][nt][j] = 0.f;

    auto issue = [&](int kch, int s) {
        uint32_t stg = sb + (uint32_t)s * K1_STG;
#pragma unroll
        for (int p = 0; p < 4; p++) {
            int e = tid + p * 256;
            int plane = e >> 9, r = (e >> 2) & 127, kc = e & 3;
            size_t gsrc = (size_t)(ocb + r) * CC + kch * 32 + kc * 8;
            const __nv_bfloat16* src = (plane ? g_cw_lo : g_cw_hi) + gsrc;
            CP_ASYNC16(stg + (uint32_t)plane * 8192u + swz64((uint32_t)(r * 64 + kc * 16)),
                       (const void*)src);
        }
#pragma unroll
        for (int p = 0; p < 8; p++) {
            int e = tid + p * 256;
            int plane = e >> 10, row = (e >> 2) & 255, kc = e & 3;
            size_t gsrc = ((size_t)(b * HWW + pix0 + row)) * CC + kch * 32 + kc * 8;
            const __nv_bfloat16* src = (plane ? g_x5t_lo : g_x5t_hi) + gsrc;
            CP_ASYNC16(stg + 16384u + (uint32_t)plane * 16384u + swz64((uint32_t)(row * 64 + kc * 16)),
                       (const void*)src);
        }
    };

    issue(0, 0);
    CP_COMMIT();
    for (int kch = 0; kch < 16; kch++) {
        int s = kch & 1;
        if (kch + 1 < 16) issue(kch + 1, s ^ 1);
        CP_COMMIT();
        CP_WAIT1();
        __syncthreads();
        uint32_t stg = sb + (uint32_t)s * K1_STG;
#pragma unroll
        for (int kb = 0; kb < 2; kb++) {
            uint32_t ah[4][4], al[4][4];
#pragma unroll
            for (int mt = 0; mt < 4; mt++) {
                int arow = mbase + mt * 16 + (lane & 15);
                int kcs = kb * 2 + (lane >> 4);
                uint32_t so = swz64((uint32_t)(arow * 64 + kcs * 16));
                ldsm_x4(ah[mt], stg + so);
                ldsm_x4(al[mt], stg + 8192u + so);
            }
#pragma unroll
            for (int ntp = 0; ntp < 4; ntp++) {
                int m = lane >> 3;
                int row = nbase + ntp * 16 + ((m & 2) << 2) + (lane & 7);
                int kcs = kb * 2 + (m & 1);
                uint32_t so = swz64((uint32_t)(row * 64 + kcs * 16));
                uint32_t bh[4], bl[4];
                ldsm_x4(bh, stg + 16384u + so);
                ldsm_x4(bl, stg + 32768u + so);
#pragma unroll
                for (int mt = 0; mt < 4; mt++) {
                    mma_bf16(acc[mt][2 * ntp],     ah[mt], bh);
                    mma_bf16(acc[mt][2 * ntp],     ah[mt], bl);
                    mma_bf16(acc[mt][2 * ntp],     al[mt], bh);
                    mma_bf16(acc[mt][2 * ntp + 1], ah[mt], bh + 2);
                    mma_bf16(acc[mt][2 * ntp + 1], ah[mt], bl + 2);
                    mma_bf16(acc[mt][2 * ntp + 1], al[mt], bh + 2);
                }
            }
        }
        __syncthreads();
    }
    float am = 0.f;
#pragma unroll
    for (int mt = 0; mt < 4; mt++) {
        int m0 = ocb + mbase + mt * 16 + (lane >> 2);
        float bi0 = bias[m0], bi1 = bias[m0 + 8];
        size_t base0 = ((size_t)(b * CC + m0)) * HWW + pix0;
        size_t base1 = ((size_t)(b * CC + m0 + 8)) * HWW + pix0;
#pragma unroll
        for (int nt = 0; nt < 8; nt++) {
            int n = nbase + nt * 8 + (lane & 3) * 2;
            float v0 = acc[mt][nt][0] + bi0 + x5[base0 + n];
            float v1 = acc[mt][nt][1] + bi0 + x5[base0 + n + 1];
            float v2 = acc[mt][nt][2] + bi1 + x5[base1 + n];
            float v3 = acc[mt][nt][3] + bi1 + x5[base1 + n + 1];
            g_x[base0 + n]     = v0;
            g_x[base0 + n + 1] = v1;
            g_x[base1 + n]     = v2;
            g_x[base1 + n + 1] = v3;
            am = fmaxf(am, fmaxf(fmaxf(fabsf(v0), fabsf(v1)), fmaxf(fabsf(v2), fabsf(v3))));
        }
    }
#pragma unroll
    for (int off = 16; off; off >>= 1)
        am = fmaxf(am, __shfl_xor_sync(0xffffffffu, am, off));
    if (lane == 0) atomicMax(&g_xmax_bits, __float_as_uint(am));
}

// ================= KPW ======================================================
__global__ __launch_bounds__(256) void kp_w(const float* __restrict__ cw) {
    __shared__ float tile[64 * 81];
    __shared__ float red[256];
    int o  = blockIdx.x >> 3;
    int c0 = (blockIdx.x & 7) * 64;
    int tid = threadIdx.x;
    for (int e = tid; e < 64 * 81; e += 256) {
        int c_l = e / 81, t = e - c_l * 81;
        tile[e] = cw[((size_t)o * CC + c0 + c_l) * TAPS + t];
    }
    __syncthreads();
    float amax = 0.f;
    for (int e = tid; e < 81 * 64; e += 256) {
        int t = e >> 6, c_l = e & 63;
        float v = tile[c_l * 81 + t];
        amax = fmaxf(amax, fabsf(v));
        __nv_bfloat16 h = __float2bfloat16(v);
        size_t di = ((size_t)(t * OC + o)) * CC + c0 + c_l;
        g_w_hi[di] = h;
        g_w_lo[di] = __float2bfloat16(v - __bfloat162float(h));
    }
    red[tid] = amax;
    __syncthreads();
    for (int s = 128; s > 0; s >>= 1) {
        if (tid < s) red[tid] = fmaxf(red[tid], red[tid + s]);
        __syncthreads();
    }
    if (tid == 0) atomicMax(&g_wmax_bits, __float_as_uint(red[0]));
}

// ================= KP_WQ: quantize weights (int8 rank + int16 pair) =========
__global__ void kp_wq() {
    float wmax = __uint_as_float(g_wmax_bits);
    float qi8  = 127.f / wmax;
    float qi16 = 32639.f / wmax;
    int i = blockIdx.x * 256 + threadIdx.x;
    uint4 h = ((const uint4*)g_w_hi)[i];
    uint4 l = ((const uint4*)g_w_lo)[i];
    const __nv_bfloat16* hp = (const __nv_bfloat16*)&h;
    const __nv_bfloat16* lp = (const __nv_bfloat16*)&l;
    char r8[8], rh[8], rl[8];
#pragma unroll
    for (int j = 0; j < 8; j++) {
        float v = __bfloat162float(hp[j]) + __bfloat162float(lp[j]);
        int q = __float2int_rn(v * qi8);
        r8[j] = (char)max(-127, min(127, q));
        int q16 = __float2int_rn(v * qi16);
        q16 = max(-32639, min(32639, q16));
        int qh = (q16 + 128) >> 8;
        rh[j] = (char)qh;
        rl[j] = (char)(q16 - (qh << 8));
    }
    ((uint2*)g_w_s8)[i] = *(uint2*)r8;
    ((uint2*)g_w16h)[i] = *(uint2*)rh;
    ((uint2*)g_w16l)[i] = *(uint2*)rl;
}

// ================= KPX: transpose g_x -> int8 planes + norm =================
__global__ __launch_bounds__(256) void kp_x() {
    __shared__ float tile[32][33];
    int b = blockIdx.y, h = blockIdx.x;
    int tid = threadIdx.x;
    int lane = tid & 31;
    float xmax = __uint_as_float(g_xmax_bits);
    float qi8  = 127.f / xmax;
    float qi16 = 32639.f / xmax;
    float nsum[4] = {0.f, 0.f, 0.f, 0.f};
    for (int c0 = 0; c0 < CC; c0 += 32) {
#pragma unroll
        for (int s = 0; s < 4; s++) {
            int cl = (tid >> 5) + s * 8, w = tid & 31;
            tile[cl][w] = g_x[((size_t)(b * CC + c0 + cl)) * HWW + h * 32 + w];
        }
        __syncthreads();
#pragma unroll
        for (int s = 0; s < 4; s++) {
            int wl = (tid >> 5) + s * 8, ci = lane;
            float v = tile[ci][wl];
            size_t dst = ((size_t)((b * 40 + h + 4) * 40 + wl + 4)) * CC + c0 + ci;
            int q = __float2int_rn(v * qi8);
            g_xp_s8[dst] = (int8_t)max(-127, min(127, q));
            int q16 = __float2int_rn(v * qi16);
            q16 = max(-32639, min(32639, q16));
            int qh = (q16 + 128) >> 8;
            g_x16h[dst] = (int8_t)qh;
            g_x16l[dst] = (int8_t)(q16 - (qh << 8));
            float vv = v * v;
#pragma unroll
            for (int off = 16; off; off >>= 1)
                vv += __shfl_xor_sync(0xffffffffu, vv, off);
            nsum[s] += vv;
        }
        __syncthreads();
    }
    if (lane == 0) {
#pragma unroll
        for (int s = 0; s < 4; s++)
            g_norm[b * HWW + h * 32 + (tid >> 5) + s * 8] = sqrtf(nsum[s]);
    }
}

// ================= K2a: int8 ranking conv, fully pipelined ==================
#define S8_BSTR  10240u
#define S8_BBUF  20480u
#define S8_ABASE 40960u
#define S8_ROW   36864u
#define K2A_SMEM 188416
__global__ __launch_bounds__(256, 1) void k2a_s8(const float* __restrict__ cb) {
    extern __shared__ char smem[];
    uint32_t sb = smem_u32(smem);
    int tid = threadIdx.x, wid = tid >> 5, lane = tid & 31;
    int bh8  = blockIdx.x * 8;
    int pix0 = blockIdx.x * 256;
    int ocb  = blockIdx.y * 128;
    int b    = blockIdx.z;
    int mbase = (wid >> 2) * 64;
    int nbase = (wid & 3) * 64;

    int acc[4][8][4];
#pragma unroll
    for (int mt = 0; mt < 4; mt++)
#pragma unroll
        for (int nt = 0; nt < 8; nt++)
#pragma unroll
            for (int j = 0; j < 4; j++) acc[mt][nt][j] = 0;

    int r_ = tid >> 1, kc_ = tid & 1;
    auto issueRow = [&](int R) {
        int q = R / 9, dy = R - q * 9;
        uint32_t buf = sb + S8_ABASE + (uint32_t)(R & 3) * S8_ROW;
#pragma unroll
        for (int p = 0; p < 9; p++) {
            const int8_t* src = g_w_s8 +
                ((size_t)((dy * 9 + p) * OC + ocb + r_)) * CC + q * 32 + kc_ * 16;
            CP_ASYNC16(buf + (uint32_t)p * 4096u + (uint32_t)kc_ * 2048u + (uint32_t)r_ * 16u,
                       (const void*)src);
        }
    };
    auto issueB = [&](int q) {
        uint32_t bbuf = sb + (uint32_t)(q & 1) * S8_BBUF;
        for (int e = tid; e < 1280; e += 256) {
            int px = e >> 1, kc = e & 1;
            int pr = px / 40, pc = px - pr * 40;
            const int8_t* src = g_xp_s8 +
                ((size_t)((b * 40 + bh8 + pr) * 40 + pc)) * CC + q * 32 + kc * 16;
            CP_ASYNC16(bbuf + (uint32_t)kc * S8_BSTR + (uint32_t)px * 16u, (const void*)src);
        }
    };

    issueB(0);
    issueRow(0);
    issueRow(1);
    CP_COMMIT();

    for (int R = 0; R < 144; R++) {
        int q = R / 9, dy = R - q * 9;
        if (R + 2 < 144) issueRow(R + 2);
        if (dy == 7 && q < 15) issueB(q + 1);
        CP_COMMIT();
        CP_WAIT1();
        __syncthreads();
        uint32_t rowbase = sb + S8_ABASE + (uint32_t)(R & 3) * S8_ROW;
        uint32_t bbase = sb + (uint32_t)(q & 1) * S8_BBUF;
        for (int dx = 0; dx < 9; dx++) {
            uint32_t abase = rowbase + (uint32_t)dx * 4096u;
            uint32_t a[4][4];
#pragma unroll
            for (int mt = 0; mt < 4; mt++) {
                int arow = mbase + mt * 16 + (lane & 15);
                int kcs = lane >> 4;
                ldsm_x4(a[mt], abase + (uint32_t)kcs * 2048u + (uint32_t)arow * 16u);
            }
#pragma unroll
            for (int ntp = 0; ntp < 4; ntp++) {
                int m = lane >> 3;
                int n_ = nbase + ntp * 16 + ((m & 2) << 2) + (lane & 7);
                int hl = n_ >> 5, w = n_ & 31;
                int kcs = m & 1;
                int px = (hl + dy) * 40 + (w + dx);
                uint32_t bq[4];
                ldsm_x4(bq, bbase + (uint32_t)kcs * S8_BSTR + (uint32_t)px * 16u);
#pragma unroll
                for (int mt = 0; mt < 4; mt++) {
                    mma_s8(acc[mt][2 * ntp],     a[mt], bq);
                    mma_s8(acc[mt][2 * ntp + 1], a[mt], bq + 2);
                }
            }
        }
    }
    float s = (__uint_as_float(g_wmax_bits) * (1.f / 127.f)) *
              (__uint_as_float(g_xmax_bits) * (1.f / 127.f));
#pragma unroll
    for (int mt = 0; mt < 4; mt++) {
        int m0 = ocb + mbase + mt * 16 + (lane >> 2);
        float bi0 = cb[m0], bi1 = cb[m0 + 8];
        float* d0 = g_cap + ((size_t)(b * OC + m0)) * HWW + pix0;
        float* d1 = g_cap + ((size_t)(b * OC + m0 + 8)) * HWW + pix0;
#pragma unroll
        for (int nt = 0; nt < 8; nt++) {
            int n = nbase + nt * 8 + (lane & 3) * 2;
            d0[n]     = (float)acc[mt][nt][0] * s + bi0;
            d0[n + 1] = (float)acc[mt][nt][1] * s + bi0;
            d1[n]     = (float)acc[mt][nt][2] * s + bi1;
            d1[n + 1] = (float)acc[mt][nt][3] * s + bi1;
        }
    }
}

// ================= K4: squash + max over CAP_C ==============================
__global__ void k4_sqmax() {
    int i = blockIdx.x * 128 + threadIdx.x;
    int b = i >> 10, hw = i & 1023;
    const float* cp = g_cap + (size_t)b * OC * HWW + hw;
    float m[8];
#pragma unroll
    for (int k = 0; k < 8; k++) m[k] = -INFINITY;
    for (int c = 0; c < CAPC; c++) {
        float v[8]; float sq = 0.f;
#pragma unroll
        for (int k = 0; k < 8; k++) { v[k] = cp[(size_t)(k * CAPC + c) * HWW]; sq += v[k] * v[k]; }
        float s = sq / ((1.f + sq) * sqrtf(sq + 1e-8f));
#pragma unroll
        for (int k = 0; k < 8; k++) m[k] = fmaxf(m[k], v[k] * s);
    }
#pragma unroll
    for (int k = 0; k < 8; k++) g_cap4[(b * 8 + k) * HWW + hw] = m[k];
}

// ================= K5: top-8 candidate pixels per (b,k) =====================
__global__ void k5_top8() {
    int bk = blockIdx.x;
    int b = bk >> 3, k = bk & 7;
    __shared__ float val[1024];
    __shared__ float sv[256];
    __shared__ int   si[256];
    int tid = threadIdx.x;
    for (int hw = tid; hw < HWW; hw += 256) val[hw] = g_cap4[bk * HWW + hw];
    __syncthreads();
    for (int j = 0; j < TOPK; j++) {
        float best = -INFINITY; int bi = 0x7fffffff;
        for (int hw = tid; hw < HWW; hw += 256) {
            float v = val[hw];
            if (v > best || (v == best && hw < bi)) { best = v; bi = hw; }
        }
        sv[tid] = best; si[tid] = bi;
        __syncthreads();
        for (int s = 128; s > 0; s >>= 1) {
            if (tid < s) {
                if (sv[tid + s] > sv[tid] ||
                    (sv[tid + s] == sv[tid] && si[tid + s] < si[tid])) {
                    sv[tid] = sv[tid + s]; si[tid] = si[tid + s];
                }
            }
            __syncthreads();
        }
        if (tid == 0) {
            g_slots[b * SLOTS + k * TOPK + j] = si[0];
            val[si[0]] = -INFINITY;
        }
        __syncthreads();
    }
}

// ================= K2b: int16-via-int8 rescore at candidate pixels ==========
// stage 12288B: A [plane2][kc2][128 rows x 16B] ; B at +8192 [plane2][kc2][64 x 16B]
#define RB16_STG 12288u
#define K2B_SMEM (4 * 12288 + 256)
__global__ __launch_bounds__(256, 1) void k2b_rescore() {
    extern __shared__ char smem[];
    uint32_t sb = smem_u32(smem);
    int* s_slots = (int*)(smem + 4 * 12288);
    int tid = threadIdx.x, wid = tid >> 5, lane = tid & 31;
    int qs  = blockIdx.x;
    int ocb = blockIdx.y * 128;
    int b   = blockIdx.z;
    int mbase = (wid >> 1) * 32;
    int nbase = (wid & 1) * 32;

    if (tid < SLOTS) s_slots[tid] = g_slots[b * SLOTS + tid];
    __syncthreads();

    int a1[2][4][4], a2[2][4][4];
#pragma unroll
    for (int mt = 0; mt < 2; mt++)
#pragma unroll
        for (int nt = 0; nt < 4; nt++)
#pragma unroll
            for (int j = 0; j < 4; j++) { a1[mt][nt][j] = 0; a2[mt][nt][j] = 0; }

    auto issue = [&](int it) {
        int q = qs * 2 + it / 81;
        int tap = it - (it / 81) * 81;
        int dy = tap / 9, dx = tap - dy * 9;
        uint32_t stg = sb + (uint32_t)(it & 3) * RB16_STG;
        // A: 512 chunks (2 plane x 2 kc x 128 rows)
#pragma unroll
        for (int p = 0; p < 2; p++) {
            int e = tid + p * 256;
            int plane = e >> 8, r = (e >> 1) & 127, kc = e & 1;
            size_t gsrc = ((size_t)(tap * OC + ocb + r)) * CC + q * 32 + kc * 16;
            const int8_t* src = (plane ? g_w16l : g_w16h) + gsrc;
            CP_ASYNC16(stg + (uint32_t)plane * 4096u + (uint32_t)kc * 2048u + (uint32_t)r * 16u,
                       (const void*)src);
        }
        // B: 256 chunks (2 plane x 2 kc x 64 rows), gathered
        {
            int e = tid;
            int plane = e >> 7, row = (e >> 1) & 63, kc = e & 1;
            int pix = s_slots[row];
            int y = pix >> 5, x = pix & 31;
            size_t gsrc = ((size_t)((b * 40 + y + dy) * 40 + (x + dx))) * CC + q * 32 + kc * 16;
            const int8_t* src = (plane ? g_x16l : g_x16h) + gsrc;
            CP_ASYNC16(stg + 8192u + (uint32_t)plane * 2048u + (uint32_t)kc * 1024u + (uint32_t)row * 16u,
                       (const void*)src);
        }
    };

    issue(0);
    issue(1);
    CP_COMMIT();
    const int NIT = 2 * TAPS;
    for (int it = 0; it < NIT; it++) {
        if (it + 2 < NIT) issue(it + 2);
        CP_COMMIT();
        CP_WAIT1();
        __syncthreads();
        uint32_t stg = sb + (uint32_t)(it & 3) * RB16_STG;
        uint32_t ah[2][4], al[2][4];
#pragma unroll
        for (int mt = 0; mt < 2; mt++) {
            int arow = mbase + mt * 16 + (lane & 15);
            int kcs = lane >> 4;
            uint32_t so = (uint32_t)kcs * 2048u + (uint32_t)arow * 16u;
            ldsm_x4(ah[mt], stg + so);
            ldsm_x4(al[mt], stg + 4096u + so);
        }
#pragma unroll
        for (int ntp = 0; ntp < 2; ntp++) {
            int m = lane >> 3;
            int row = nbase + ntp * 16 + ((m & 2) << 2) + (lane & 7);
            int kcs = m & 1;
            uint32_t so = (uint32_t)kcs * 1024u + (uint32_t)row * 16u;
            uint32_t bh[4], bl[4];
            ldsm_x4(bh, stg + 8192u + so);
            ldsm_x4(bl, stg + 8192u + 2048u + so);
#pragma unroll
            for (int mt = 0; mt < 2; mt++) {
                mma_s8(a1[mt][2 * ntp],     ah[mt], bh);
                mma_s8(a2[mt][2 * ntp],     ah[mt], bl);
                mma_s8(a2[mt][2 * ntp],     al[mt], bh);
                mma_s8(a1[mt][2 * ntp + 1], ah[mt], bh + 2);
                mma_s8(a2[mt][2 * ntp + 1], ah[mt], bl + 2);
                mma_s8(a2[mt][2 * ntp + 1], al[mt], bh + 2);
            }
        }
    }
    float swx = (__uint_as_float(g_wmax_bits) * (1.f / 32639.f)) *
                (__uint_as_float(g_xmax_bits) * (1.f / 32639.f));
#pragma unroll
    for (int mt = 0; mt < 2; mt++) {
        int m0 = ocb + mbase + mt * 16 + (lane >> 2);
        float* d0 = g_rpart + ((size_t)((qs * BB + b) * OC + m0)) * SLOTS;
        float* d1 = d0 + 8 * SLOTS;
#pragma unroll
        for (int nt = 0; nt < 4; nt++) {
            int n = nbase + nt * 8 + (lane & 3) * 2;
            d0[n]     = fmaf(65536.f, (float)a1[mt][nt][0], 256.f * (float)a2[mt][nt][0]) * swx;
            d0[n + 1] = fmaf(65536.f, (float)a1[mt][nt][1], 256.f * (float)a2[mt][nt][1]) * swx;
            d1[n]     = fmaf(65536.f, (float)a1[mt][nt][2], 256.f * (float)a2[mt][nt][2]) * swx;
            d1[n + 1] = fmaf(65536.f, (float)a1[mt][nt][3], 256.f * (float)a2[mt][nt][3]) * swx;
        }
    }
}

// ================= K2c ======================================================
#define K2C_SMEM (OC * SLOTS * 4 + NCAPS * SLOTS * 4 + SLOTS * 4)
__global__ __launch_bounds__(256) void k2c_pick(const float* __restrict__ cb) {
    extern __shared__ char smem[];
    float* v     = (float*)smem;
    float* sval  = (float*)(smem + OC * SLOTS * 4);
    int*   sl    = (int*)(smem + OC * SLOTS * 4 + NCAPS * SLOTS * 4);
    int b = blockIdx.x, tid = threadIdx.x;
    if (tid < SLOTS) sl[tid] = g_slots[b * SLOTS + tid];
    for (int idx = tid; idx < OC * SLOTS; idx += 256) {
        int oc = idx >> 6;
        float s = cb[oc];
#pragma unroll
        for (int qs = 0; qs < KSPLIT; qs++)
            s += g_rpart[((size_t)((qs * BB + b) * OC)) * SLOTS + idx];
        v[idx] = s;
    }
    __syncthreads();
    if (tid < SLOTS) {
        float mk[8];
#pragma unroll
        for (int k = 0; k < 8; k++) mk[k] = -INFINITY;
        for (int c = 0; c < CAPC; c++) {
            float vv[8]; float sq = 0.f;
#pragma unroll
            for (int k = 0; k < 8; k++) {
                vv[k] = v[(k * CAPC + c) * SLOTS + tid];
                sq += vv[k] * vv[k];
            }
            float sf = sq / ((1.f + sq) * sqrtf(sq + 1e-8f));
#pragma unroll
            for (int k = 0; k < 8; k++) mk[k] = fmaxf(mk[k], vv[k] * sf);
        }
#pragma unroll
        for (int k = 0; k < 8; k++) sval[k * SLOTS + tid] = mk[k];
    }
    __syncthreads();
    if (tid < NCAPS) {
        float best = -INFINITY; int bp = 0x7fffffff;
        for (int s = 0; s < SLOTS; s++) {
            float vv = sval[tid * SLOTS + s];
            int px = sl[s];
            if (vv > best || (vv == best && px < bp)) { best = vv; bp = px; }
        }
        g_idx[b * NCAPS + tid] = bp;
    }
}

// ================= K6..K12 (exact path) =====================================
__global__ void k6_smean() {
    int i = blockIdx.x * 256 + threadIdx.x;
    int c = i >> 3, k = i & 7;
    float s = 0.f;
    for (int b = 0; b < BB; b++) {
        int hw = g_idx[b * 8 + k];
        float n = fmaxf(g_norm[b * HWW + hw], 1e-12f);
        s += g_x[((size_t)(b * CC + c)) * HWW + hw] / n;
    }
    g_smean[c * 8 + k] = s * (1.f / 16.f);
}

__global__ __launch_bounds__(128) void k7_cm() {
    __shared__ float ss[CC * 8];
    for (int e = threadIdx.x; e < CC * 8; e += 128) ss[e] = g_smean[e];
    __syncthreads();
    int i = blockIdx.x * 128 + threadIdx.x;
    int b = i >> 10, hw = i & 1023;
    const float* xp = g_x + (size_t)b * CC * HWW + hw;
    float acc[8] = {};
    for (int c = 0; c < CC; c++) {
        float xv = xp[c * HWW];
#pragma unroll
        for (int k = 0; k < 8; k++) acc[k] += xv * ss[c * 8 + k];
    }
    float inv = 1.f / fmaxf(g_norm[i], 1e-12f);
#pragma unroll
    for (int k = 0; k < 8; k++) g_cm[(b * 8 + k) * HWW + hw] = acc[k] * inv;
}

__global__ void k8_minmax() {
    int bk = blockIdx.x;
    __shared__ float smn[256], smx[256];
    int tid = threadIdx.x;
    float mn = INFINITY, mx = -INFINITY;
    for (int hw = tid; hw < HWW; hw += 256) {
        float v = g_cm[bk * HWW + hw];
        mn = fminf(mn, v); mx = fmaxf(mx, v);
    }
    smn[tid] = mn; smx[tid] = mx;
    __syncthreads();
    for (int s = 128; s > 0; s >>= 1) {
        if (tid < s) {
            smn[tid] = fminf(smn[tid], smn[tid + s]);
            smx[tid] = fmaxf(smx[tid], smx[tid + s]);
        }
        __syncthreads();
    }
    if (tid == 0) { g_mm[bk * 2] = smn[0]; g_mm[bk * 2 + 1] = smx[0]; }
}

__global__ void k9_cmnorm() {
    int i = blockIdx.x * 128 + threadIdx.x;
    int b = i >> 10, hw = i & 1023;
    float s = 0.f;
#pragma unroll
    for (int k = 0; k < 8; k++) {
        int bk = b * 8 + k;
        float mn = g_mm[bk * 2], mx = g_mm[bk * 2 + 1];
        float v = (g_cm[bk * HWW + hw] - mn) / (mx - mn + 1e-12f);
        g_cm[bk * HWW + hw] = v;
        s += v;
    }
    g_cmmean[i] = s * 0.125f;
}

__global__ __launch_bounds__(256) void k10_proto() {
    int c0 = blockIdx.x * 8;
    int tid = threadIdx.x, wid = tid >> 5, lane = tid & 31;
    float acc[8][8];
#pragma unroll
    for (int cl = 0; cl < 8; cl++)
#pragma unroll
        for (int k = 0; k < 8; k++) acc[cl][k] = 0.f;
    for (int i = tid; i < BB * HWW; i += 256) {
        int b = i >> 10, hw = i & 1023;
        float cmv[8];
#pragma unroll
        for (int k = 0; k < 8; k++) cmv[k] = g_cm[(b * 8 + k) * HWW + hw];
#pragma unroll
        for (int cl = 0; cl < 8; cl++) {
            float xv = g_x[((size_t)(b * CC + c0 + cl)) * HWW + hw];
#pragma unroll
            for (int k = 0; k < 8; k++) acc[cl][k] += xv * cmv[k];
        }
    }
    __shared__ float wred[8][64];
#pragma unroll
    for (int cl = 0; cl < 8; cl++)
#pragma unroll
        for (int k = 0; k < 8; k++) {
            float v = acc[cl][k];
#pragma unroll
            for (int off = 16; off; off >>= 1)
                v += __shfl_xor_sync(0xffffffffu, v, off);
            if (lane == 0) wred[wid][cl * 8 + k] = v;
        }
    __syncthreads();
    if (tid < 64) {
        float s = 0.f;
#pragma unroll
        for (int w = 0; w < 8; w++) s += wred[w][tid];
        int cl = tid >> 3, k = tid & 7;
        g_proto[k * CC + c0 + cl] = s * (1.f / (BB * HWW));
    }
}

__global__ void k11_pm(float* __restrict__ out) {
    int c = threadIdx.x;
    float s = 0.f;
#pragma unroll
    for (int k = 0; k < 8; k++) s += g_proto[k * CC + c];
    s *= 0.125f;
    g_pm[c] = s;
    __shared__ float red[512];
    red[c] = s * s;
    __syncthreads();
    for (int st = 256; st > 0; st >>= 1) {
        if (c < st) red[c] += red[c + st];
        __syncthreads();
    }
    float nrm = fmaxf(sqrtf(red[0]), 1e-12f);
    out[c] = s / nrm;
}

__global__ __launch_bounds__(128) void k12_out(float* __restrict__ out) {
    __shared__ float spm[CC];
    for (int e = threadIdx.x; e < CC; e += 128) spm[e] = g_pm[e];
    __syncthreads();
    int i = blockIdx.x * 128 + threadIdx.x;
    int b = i >> 10, hw = i & 1023;
    float cmm = g_cmmean[i];
    const float* xp = g_x + (size_t)b * CC * HWW + hw;
    float ss2 = 0.f;
    for (int c = 0; c < CC; c++) {
        float v = xp[c * HWW] * (spm[c] + cmm);
        ss2 += v * v;
    }
    float inv = 1.f / fmaxf(sqrtf(ss2), 1e-12f);
    float* op = out + CC + (size_t)b * CC * HWW + hw;
    for (int c = 0; c < CC; c++)
        op[c * HWW] = xp[c * HWW] * (spm[c] + cmm) * inv;
}

// ================= launcher ==================================================
extern "C" void kernel_launch(void* const* d_in, const int* in_sizes, int n_in,
                              void* d_out, int out_size) {
    const float* x5     = (const float*)d_in[0];
    const float* conv_w = (const float*)d_in[1];
    const float* conv_b = (const float*)d_in[2];
    const float* caps_w = (const float*)d_in[3];
    const float* caps_b = (const float*)d_in[4];
    float* out = (float*)d_out;
    (void)in_sizes; (void)n_in; (void)out_size;

    cudaFuncSetAttribute(k1_mma,      cudaFuncAttributeMaxDynamicSharedMemorySize, K1_SMEM);
    cudaFuncSetAttribute(k2a_s8,      cudaFuncAttributeMaxDynamicSharedMemorySize, K2A_SMEM);
    cudaFuncSetAttribute(k2b_rescore, cudaFuncAttributeMaxDynamicSharedMemorySize, K2B_SMEM);
    cudaFuncSetAttribute(k2c_pick,    cudaFuncAttributeMaxDynamicSharedMemorySize, K2C_SMEM);

    kp_pre  <<<1536, 256>>>(x5, conv_w);
    kp_w    <<<2048, 256>>>(caps_w);
    kp_wq   <<<5184, 256>>>();
    k1_mma  <<<dim3(4, 4, 16), 256, K1_SMEM>>>(x5, conv_b);
    kp_x    <<<dim3(32, 16), 256>>>();
    k2a_s8  <<<dim3(4, 2, 16), 256, K2A_SMEM>>>(caps_b);
    k4_sqmax<<<128, 128>>>();
    k5_top8 <<<128, 256>>>();
    k2b_rescore<<<dim3(KSPLIT, 2, 16), 256, K2B_SMEM>>>();
    k2c_pick<<<16, 256, K2C_SMEM>>>(caps_b);
    k6_smean<<<16, 256>>>();
    k7_cm   <<<128, 128>>>();
    k8_minmax<<<128, 256>>>();
    k9_cmnorm<<<128, 128>>>();
    k10_proto<<<64, 256>>>();
    k11_pm  <<<1, 512>>>(out);
    k12_out <<<128, 128>>>(out);
}